// round 8
// baseline (speedup 1.0000x reference)
#include <cuda_runtime.h>
#include <cuda_bf16.h>
#include <cstdint>
#include <math.h>

// Problem dims
#define L_SEQ 2048
#define BSZ   4
#define DM    1024
#define DI    2048
#define DS    16
#define DR    64
#define M_ROWS 8192   // BSZ * L_SEQ

// ============================================================================
// Scratch (static device arrays)
// ============================================================================
__device__ float g_xz  [(size_t)M_ROWS * 8192];             // in_proj output (xi|z per dir)
__device__ float g_proj[2 * (size_t)M_ROWS * 96];           // x_proj output (dt_raw|B|C)
__device__ float g_dt  [2 * (size_t)M_ROWS * DI];           // dt_proj output (pre-softplus)

// bf16 hi/lo operand planes
__device__ __nv_bfloat16 g_x_hi  [(size_t)M_ROWS * DM],  g_x_lo  [(size_t)M_ROWS * DM];
__device__ __nv_bfloat16 g_inw_hi[(size_t)8192 * DM],    g_inw_lo[(size_t)8192 * DM];
__device__ __nv_bfloat16 g_xw_hi [2 * 96 * (size_t)DI],  g_xw_lo [2 * 96 * (size_t)DI];
__device__ __nv_bfloat16 g_dtw_hi[2 * (size_t)DI * DR],  g_dtw_lo[2 * (size_t)DI * DR];
__device__ __nv_bfloat16 g_ow_hi [2 * (size_t)DM * DI],  g_ow_lo [2 * (size_t)DM * DI];
__device__ __nv_bfloat16 g_xc_hi [2 * (size_t)M_ROWS * DI], g_xc_lo[2 * (size_t)M_ROWS * DI];
__device__ __nv_bfloat16 g_dtr_hi[2 * (size_t)M_ROWS * DR], g_dtr_lo[2 * (size_t)M_ROWS * DR];
__device__ __nv_bfloat16 g_y_hi  [2 * (size_t)M_ROWS * DI], g_y_lo [2 * (size_t)M_ROWS * DI];

__device__ __forceinline__ void split2(float v, __nv_bfloat16& h, __nv_bfloat16& l) {
    h = __float2bfloat16_rn(v);
    l = __float2bfloat16_rn(v - __bfloat162float(h));
}

// ============================================================================
// PTX helpers (sm_80-class only: valid on base sm_103 target)
// ============================================================================
__device__ __forceinline__ uint32_t smem_u32(const void* p) {
    uint32_t a;
    asm("{ .reg .u64 t; cvta.to.shared.u64 t, %1; cvt.u32.u64 %0, t; }" : "=r"(a) : "l"(p));
    return a;
}
__device__ __forceinline__ void cpa16(uint32_t dst, const void* src) {
    asm volatile("cp.async.cg.shared.global [%0], [%1], 16;" :: "r"(dst), "l"(src) : "memory");
}
__device__ __forceinline__ void cpa16p(uint32_t dst, const void* src, int sz) {
    asm volatile("cp.async.cg.shared.global [%0], [%1], 16, %2;" :: "r"(dst), "l"(src), "r"(sz) : "memory");
}
__device__ __forceinline__ void cp_commit() {
    asm volatile("cp.async.commit_group;" ::: "memory");
}
template <int N>
__device__ __forceinline__ void cp_wait() {
    asm volatile("cp.async.wait_group %0;" :: "n"(N) : "memory");
}
__device__ __forceinline__ void ldsm_x4(uint32_t* r, uint32_t addr) {
    asm volatile("ldmatrix.sync.aligned.m8n8.x4.shared.b16 {%0,%1,%2,%3}, [%4];"
                 : "=r"(r[0]), "=r"(r[1]), "=r"(r[2]), "=r"(r[3]) : "r"(addr));
}
__device__ __forceinline__ void mma_bf16(float* d, const uint32_t* a, const uint32_t* b) {
    asm volatile("mma.sync.aligned.m16n8k16.row.col.f32.bf16.bf16.f32 "
                 "{%0,%1,%2,%3}, {%4,%5,%6,%7}, {%8,%9}, {%0,%1,%2,%3};"
                 : "+f"(d[0]), "+f"(d[1]), "+f"(d[2]), "+f"(d[3])
                 : "r"(a[0]), "r"(a[1]), "r"(a[2]), "r"(a[3]), "r"(b[0]), "r"(b[1]));
}

// ============================================================================
// GEMM machinery: 128x128 tile, K-chunk 32, 256 threads (2x4 warps, 64x32
// warp tiles), 2-stage cp.async pipeline, rows padded to 40 halves.
// Convoy breakers: per-warp k16 phase parity + rotated i-loop start, and
// B fragments loaded as ldsm_x4 pairs (half the B-ldsm instruction count).
// bf16x3 split: acc += Ah*Bh + Ah*Bl + Al*Bh  (fp32 accumulate)
// ============================================================================
#define ROW_H 40
#define PLANE (128 * ROW_H * 2)          // 10240 B
#define OFF_AH 0
#define OFF_AL (PLANE)
#define OFF_BH (2 * PLANE)
#define OFF_BL (3 * PLANE)
#define STAGE  (4 * PLANE)               // 40960 B
#define GEMM_SMEM (2 * STAGE)            // 81920 B

struct GemmCtx {
    uint32_t sb;
    int tid, lane, warp, wm, wn, bm, bn;
    uint32_t a_lane_off, b_lane_off4;
};

__device__ __forceinline__ void gemm_init(GemmCtx& g, char* smem) {
    g.sb = smem_u32(smem);
    g.tid = threadIdx.x;
    g.lane = g.tid & 31;
    g.warp = g.tid >> 5;
    g.wm = g.warp >> 2;          // 0..1
    g.wn = g.warp & 3;           // 0..3
    g.bm = blockIdx.y * 128;
    g.bn = blockIdx.x * 128;
    g.a_lane_off = (uint32_t)((g.lane & 15) * ROW_H + 8 * (g.lane >> 4)) * 2;
    // x4 B layout: m = lane>>3: row += 8*(m>>1) [j vs j+1 block], col += 8*(m&1)
    g.b_lane_off4 = (uint32_t)(((g.lane & 7) + 8 * ((g.lane >> 4) & 1)) * ROW_H
                               + 8 * ((g.lane >> 3) & 1)) * 2;
}

__device__ __forceinline__ void gemm_load_chunk(
    const GemmCtx& g, int s, int k0, int K,
    const __nv_bfloat16* __restrict__ Ahi, const __nv_bfloat16* __restrict__ Alo,
    const __nv_bfloat16* __restrict__ Bhi, const __nv_bfloat16* __restrict__ Blo,
    int Nact)
{
    const uint32_t st = g.sb + s * STAGE;
#pragma unroll
    for (int it = 0; it < 2; ++it) {
        const int i   = g.tid + it * 256;
        const int row = i >> 2;
        const int c8  = (i & 3) * 8;
        const uint32_t so = (uint32_t)(row * ROW_H + c8) * 2;
        const size_t ga = (size_t)(g.bm + row) * K + k0 + c8;
        cpa16(st + OFF_AH + so, Ahi + ga);
        cpa16(st + OFF_AL + so, Alo + ga);
        const size_t gb = (size_t)(g.bn + row) * K + k0 + c8;
        const int sz = (g.bn + row < Nact) ? 16 : 0;
        cpa16p(st + OFF_BH + so, Bhi + gb, sz);
        cpa16p(st + OFF_BL + so, Blo + gb, sz);
    }
}

__device__ __forceinline__ void gemm_compute_chunk(const GemmCtx& g, int s, float acc[4][4][4]) {
    const uint32_t st = g.sb + s * STAGE;
    const int kpar = g.warp & 1;            // odd warps walk k16 in reverse
    const int irot = (g.warp >> 1) & 3;     // rotate i start per warp pair
#pragma unroll
    for (int kk = 0; kk < 2; ++kk) {
        const int k16 = ((kk + kpar) & 1) * 16;
        const uint32_t ak = g.a_lane_off + k16 * 2;
        const uint32_t bk = g.b_lane_off4 + k16 * 2;
        uint32_t bh[4][2], bl[4][2];
#pragma unroll
        for (int j = 0; j < 4; j += 2) {
            const uint32_t bo = (uint32_t)((g.wn * 32 + j * 8) * ROW_H) * 2 + bk;
            uint32_t t[4];
            ldsm_x4(t, st + OFF_BH + bo);
            bh[j][0] = t[0]; bh[j][1] = t[1]; bh[j + 1][0] = t[2]; bh[j + 1][1] = t[3];
            ldsm_x4(t, st + OFF_BL + bo);
            bl[j][0] = t[0]; bl[j][1] = t[1]; bl[j + 1][0] = t[2]; bl[j + 1][1] = t[3];
        }
#pragma unroll
        for (int ii = 0; ii < 4; ++ii) {
            const int i = (ii + irot) & 3;
            const uint32_t ao = (uint32_t)((g.wm * 64 + i * 16) * ROW_H) * 2 + ak;
            uint32_t ah[4], al[4];
            ldsm_x4(ah, st + OFF_AH + ao);
            ldsm_x4(al, st + OFF_AL + ao);
#pragma unroll
            for (int j = 0; j < 4; ++j) mma_bf16(acc[i][j], ah, bh[j]);
#pragma unroll
            for (int j = 0; j < 4; ++j) mma_bf16(acc[i][j], ah, bl[j]);
#pragma unroll
            for (int j = 0; j < 4; ++j) mma_bf16(acc[i][j], al, bh[j]);
        }
    }
}

// ============================================================================
// k_gemm_z: C[z][M,N] = A[z][M,K] @ B[z][N,K]^T   (z = blockIdx.z, strides)
// Optional dtr epilogue: cols<64 also split to g_dtr_hi/lo (x_proj only).
// ============================================================================
__global__ void __launch_bounds__(256, 2) k_gemm_z(
    const __nv_bfloat16* __restrict__ Ahi, const __nv_bfloat16* __restrict__ Alo, size_t aStride,
    const __nv_bfloat16* __restrict__ Bhi, const __nv_bfloat16* __restrict__ Blo, size_t bStride,
    float* __restrict__ C, size_t cStride, int K, int Nact, int ldc, int doDtr)
{
    extern __shared__ char smem[];
    GemmCtx g;
    gemm_init(g, smem);
    const int z = blockIdx.z;
    Ahi += (size_t)z * aStride; Alo += (size_t)z * aStride;
    Bhi += (size_t)z * bStride; Blo += (size_t)z * bStride;
    C   += (size_t)z * cStride;
    const int nch = K >> 5;

    float acc[4][4][4];
#pragma unroll
    for (int i = 0; i < 4; i++)
#pragma unroll
        for (int j = 0; j < 4; j++)
#pragma unroll
            for (int k = 0; k < 4; k++) acc[i][j][k] = 0.f;

    gemm_load_chunk(g, 0, 0, K, Ahi, Alo, Bhi, Blo, Nact);
    cp_commit();

    for (int c = 0; c < nch; ++c) {
        if (c + 1 < nch) {
            gemm_load_chunk(g, (c + 1) & 1, (c + 1) << 5, K, Ahi, Alo, Bhi, Blo, Nact);
            cp_commit();
            cp_wait<1>();
        } else {
            cp_wait<0>();
        }
        __syncthreads();
        gemm_compute_chunk(g, c & 1, acc);
        __syncthreads();
    }

    const int gid = g.lane >> 2;
    const int tig = g.lane & 3;
#pragma unroll
    for (int i = 0; i < 4; ++i) {
        const int row = g.bm + g.wm * 64 + i * 16 + gid;
#pragma unroll
        for (int j = 0; j < 4; ++j) {
            const int col = g.bn + g.wn * 32 + j * 8 + tig * 2;
            if (col < Nact) {
                *(float2*)&C[(size_t)row * ldc + col]       = make_float2(acc[i][j][0], acc[i][j][1]);
                *(float2*)&C[(size_t)(row + 8) * ldc + col] = make_float2(acc[i][j][2], acc[i][j][3]);
                if (doDtr && col < DR) {
                    __nv_bfloat16 h0, l0, h1, l1;
                    size_t d0 = ((size_t)z * M_ROWS + row) * DR + col;
                    split2(acc[i][j][0], h0, l0); split2(acc[i][j][1], h1, l1);
                    g_dtr_hi[d0] = h0; g_dtr_hi[d0 + 1] = h1;
                    g_dtr_lo[d0] = l0; g_dtr_lo[d0 + 1] = l1;
                    size_t d8 = d0 + 8 * DR;
                    split2(acc[i][j][2], h0, l0); split2(acc[i][j][3], h1, l1);
                    g_dtr_hi[d8] = h0; g_dtr_hi[d8 + 1] = h1;
                    g_dtr_lo[d8] = l0; g_dtr_lo[d8 + 1] = l1;
                }
            }
        }
    }
}

// ============================================================================
// k_gemm_cat: out = y0 @ ow0^T + y1 @ ow1^T  (K-concatenated, single pass)
// ============================================================================
__global__ void __launch_bounds__(256, 2) k_gemm_cat(
    const __nv_bfloat16* __restrict__ A0hi, const __nv_bfloat16* __restrict__ A0lo,
    const __nv_bfloat16* __restrict__ A1hi, const __nv_bfloat16* __restrict__ A1lo,
    const __nv_bfloat16* __restrict__ B0hi, const __nv_bfloat16* __restrict__ B0lo,
    const __nv_bfloat16* __restrict__ B1hi, const __nv_bfloat16* __restrict__ B1lo,
    float* __restrict__ C, int Kh, int Nact, int ldc)
{
    extern __shared__ char smem[];
    GemmCtx g;
    gemm_init(g, smem);
    const int nch_h = Kh >> 5;
    const int nch = nch_h * 2;

    float acc[4][4][4];
#pragma unroll
    for (int i = 0; i < 4; i++)
#pragma unroll
        for (int j = 0; j < 4; j++)
#pragma unroll
            for (int k = 0; k < 4; k++) acc[i][j][k] = 0.f;

    auto load = [&](int c, int s) {
        if (c < nch_h)
            gemm_load_chunk(g, s, c << 5, Kh, A0hi, A0lo, B0hi, B0lo, Nact);
        else
            gemm_load_chunk(g, s, (c - nch_h) << 5, Kh, A1hi, A1lo, B1hi, B1lo, Nact);
    };

    load(0, 0);
    cp_commit();
    for (int c = 0; c < nch; ++c) {
        if (c + 1 < nch) {
            load(c + 1, (c + 1) & 1);
            cp_commit();
            cp_wait<1>();
        } else {
            cp_wait<0>();
        }
        __syncthreads();
        gemm_compute_chunk(g, c & 1, acc);
        __syncthreads();
    }

    const int gid = g.lane >> 2;
    const int tig = g.lane & 3;
#pragma unroll
    for (int i = 0; i < 4; ++i) {
        const int row = g.bm + g.wm * 64 + i * 16 + gid;
#pragma unroll
        for (int j = 0; j < 4; ++j) {
            const int col = g.bn + g.wn * 32 + j * 8 + tig * 2;
            if (col < Nact) {
                *(float2*)&C[(size_t)row * ldc + col]       = make_float2(acc[i][j][0], acc[i][j][1]);
                *(float2*)&C[(size_t)(row + 8) * ldc + col] = make_float2(acc[i][j][2], acc[i][j][3]);
            }
        }
    }
}

// ============================================================================
// fp32 -> bf16 hi/lo conversions. Split into 3 launches so in_proj lands at
// launch index 3 (the slot ncu captures).
// ============================================================================
__global__ void k_cvt(const float4* __restrict__ src, __nv_bfloat16* __restrict__ hi,
                      __nv_bfloat16* __restrict__ lo, unsigned n4) {
    unsigned i = blockIdx.x * blockDim.x + threadIdx.x;
    if (i >= n4) return;
    float4 v = src[i];
    __nv_bfloat16 h0, h1, h2, h3, l0, l1, l2, l3;
    split2(v.x, h0, l0); split2(v.y, h1, l1); split2(v.z, h2, l2); split2(v.w, h3, l3);
    __nv_bfloat162* H = (__nv_bfloat162*)hi;
    __nv_bfloat162* L = (__nv_bfloat162*)lo;
    H[2 * (size_t)i]     = __nv_bfloat162(h0, h1);
    H[2 * (size_t)i + 1] = __nv_bfloat162(h2, h3);
    L[2 * (size_t)i]     = __nv_bfloat162(l0, l1);
    L[2 * (size_t)i + 1] = __nv_bfloat162(l2, l3);
}

#define N4_XW  98304u     // 2*96*2048/4
#define N4_DTW 65536u     // 2*2048*64/4
#define N4_OW  1048576u   // 2*1024*2048/4
#define N4_W3  (N4_XW + N4_DTW + N4_OW)

__global__ void k_cvt3(const float4* __restrict__ xw, const float4* __restrict__ dtw,
                       const float4* __restrict__ ow) {
    unsigned i = blockIdx.x * blockDim.x + threadIdx.x;
    if (i >= N4_W3) return;
    const float4* src;
    __nv_bfloat16 *hi, *lo;
    unsigned off = i;
    if (i < N4_XW)                      { src = xw;  hi = g_xw_hi;  lo = g_xw_lo; }
    else if ((off -= N4_XW) < N4_DTW)   { src = dtw; hi = g_dtw_hi; lo = g_dtw_lo; }
    else { off -= N4_DTW;                 src = ow;  hi = g_ow_hi;  lo = g_ow_lo; }
    float4 v = src[off];
    __nv_bfloat16 h0, h1, h2, h3, l0, l1, l2, l3;
    split2(v.x, h0, l0); split2(v.y, h1, l1); split2(v.z, h2, l2); split2(v.w, h3, l3);
    __nv_bfloat162* H = (__nv_bfloat162*)hi;
    __nv_bfloat162* L = (__nv_bfloat162*)lo;
    H[2 * (size_t)off]     = __nv_bfloat162(h0, h1);
    H[2 * (size_t)off + 1] = __nv_bfloat162(h2, h3);
    L[2 * (size_t)off]     = __nv_bfloat162(l0, l1);
    L[2 * (size_t)off + 1] = __nv_bfloat162(l2, l3);
}

// ============================================================================
// Depthwise conv (causal fwd / anti-causal bwd) + SiLU -> xc hi/lo planes
// ============================================================================
__global__ void k_conv(const float* __restrict__ cw, const float* __restrict__ cb) {
    size_t idx = (size_t)blockIdx.x * blockDim.x + threadIdx.x;
    if (idx >= (size_t)2 * M_ROWS * DI) return;
    int e = (int)(idx % DI);
    size_t r = idx / DI;
    int m = (int)(r % M_ROWS);
    int dir = (int)(r / M_ROWS);
    int l = m % L_SEQ;
    int b = m / L_SEQ;

    float acc = cb[dir * DI + e];
    const float* w4 = cw + ((size_t)dir * DI + e) * 4;
#pragma unroll
    for (int k = 0; k < 4; k++) {
        int tl = (dir == 0) ? (l - 3 + k) : (l + 3 - k);
        if (tl >= 0 && tl < L_SEQ)
            acc = fmaf(w4[k], g_xz[((size_t)(b * L_SEQ + tl)) * 8192 + dir * 4096 + e], acc);
    }
    float xc = acc / (1.f + __expf(-acc));   // silu
    __nv_bfloat16 h, lo;
    split2(xc, h, lo);
    size_t o = ((size_t)dir * M_ROWS + m) * DI + e;
    g_xc_hi[o] = h;
    g_xc_lo[o] = lo;
}

// ============================================================================
// Selective scan: 128-thread blocks, 4-deep register-ring prefetch.
// ============================================================================
__global__ void __launch_bounds__(128) k_scan(const float* __restrict__ dt_b,
                                              const float* __restrict__ A_log,
                                              const float* __restrict__ Dp) {
    const int tid  = threadIdx.x;
    const int lane = tid & 31;
    const int warp = tid >> 5;
    const int dir  = blockIdx.z;
    const int b    = blockIdx.y;
    const int e    = blockIdx.x * 128 + tid;

    __shared__ float sB[4][16], sC[4][16];

    float a[16];
#pragma unroll
    for (int s = 0; s < 16; s++)
        a[s] = -__expf(A_log[((size_t)dir * DI + e) * 16 + s]);

    const float bias  = dt_b[dir * DI + e];
    const float dcoef = Dp[dir * DI + e];

    float h[16];
#pragma unroll
    for (int s = 0; s < 16; s++) h[s] = 0.f;

    const size_t base_de   = (size_t)dir * M_ROWS * DI;
    const size_t proj_base = (size_t)dir * M_ROWS * 96;
    const size_t brow      = (size_t)b * L_SEQ;

    float rbc[4], rdt[4], rxh[4], rxl[4], rz[4];
#pragma unroll
    for (int p = 0; p < 4; p++) {
        const int tt = dir ? (L_SEQ - 1 - p) : p;
        const size_t m = brow + tt;
        rbc[p] = g_proj[proj_base + m * 96 + 64 + lane];
        rdt[p] = g_dt[base_de + m * DI + e];
        rxh[p] = __bfloat162float(g_xc_hi[base_de + m * DI + e]);
        rxl[p] = __bfloat162float(g_xc_lo[base_de + m * DI + e]);
        rz[p]  = g_xz[m * 8192 + dir * 4096 + 2048 + e];
    }

    for (int t0 = 0; t0 < L_SEQ; t0 += 4) {
#pragma unroll
        for (int u = 0; u < 4; u++) {
            const int t  = t0 + u;
            const int tt = dir ? (L_SEQ - 1 - t) : t;
            const size_t m = brow + tt;

            const float bc = rbc[u], dtv = rdt[u], xh = rxh[u], xl = rxl[u], zz = rz[u];

            const int tp = t + 4;
            if (tp < L_SEQ) {
                const int tq = dir ? (L_SEQ - 1 - tp) : tp;
                const size_t mp = brow + tq;
                rbc[u] = g_proj[proj_base + mp * 96 + 64 + lane];
                rdt[u] = g_dt[base_de + mp * DI + e];
                rxh[u] = __bfloat162float(g_xc_hi[base_de + mp * DI + e]);
                rxl[u] = __bfloat162float(g_xc_lo[base_de + mp * DI + e]);
                rz[u]  = g_xz[mp * 8192 + dir * 4096 + 2048 + e];
            }

            if (lane < 16) sB[warp][lane] = bc; else sC[warp][lane - 16] = bc;
            __syncwarp();

            const float v   = dtv + bias;
            const float dt  = (v > 15.f) ? v : log1pf(__expf(v));
            const float x   = xh + xl;
            const float dtx = dt * x;

            float y = 0.f;
#pragma unroll
            for (int s = 0; s < 16; s++) {
                float dA = __expf(dt * a[s]);
                h[s] = fmaf(h[s], dA, dtx * sB[warp][s]);
                y    = fmaf(h[s], sC[warp][s], y);
            }
            const float yv  = fmaf(x, dcoef, y);
            const float sz  = zz / (1.f + __expf(-zz));
            const float out = yv * sz;
            __nv_bfloat16 hh, ll;
            split2(out, hh, ll);
            const size_t o = base_de + m * DI + e;
            g_y_hi[o] = hh;
            g_y_lo[o] = ll;
            __syncwarp();
        }
    }
}

// ============================================================================
extern "C" void kernel_launch(void* const* d_in, const int* in_sizes, int n_in,
                              void* d_out, int out_size) {
    const float* x      = (const float*)d_in[0];
    const float* in_w   = (const float*)d_in[1];
    const float* conv_w = (const float*)d_in[2];
    const float* conv_b = (const float*)d_in[3];
    const float* x_w    = (const float*)d_in[4];
    const float* dt_w   = (const float*)d_in[5];
    const float* dt_bv  = (const float*)d_in[6];
    const float* A_log  = (const float*)d_in[7];
    const float* Dp     = (const float*)d_in[8];
    const float* out_w  = (const float*)d_in[9];
    float* out = (float*)d_out;

    cudaFuncSetAttribute(k_gemm_z,   cudaFuncAttributeMaxDynamicSharedMemorySize, GEMM_SMEM);
    cudaFuncSetAttribute(k_gemm_cat, cudaFuncAttributeMaxDynamicSharedMemorySize, GEMM_SMEM);

    float *xz, *proj, *dtv;
    __nv_bfloat16 *xhi, *xlo, *inwhi, *inwlo, *xwhi, *xwlo, *dtwhi, *dtwlo, *owhi, *owlo;
    __nv_bfloat16 *xchi, *xclo, *dtrhi, *dtrlo, *yhi, *ylo;
    cudaGetSymbolAddress((void**)&xz, g_xz);
    cudaGetSymbolAddress((void**)&proj, g_proj);
    cudaGetSymbolAddress((void**)&dtv, g_dt);
    cudaGetSymbolAddress((void**)&xhi, g_x_hi);     cudaGetSymbolAddress((void**)&xlo, g_x_lo);
    cudaGetSymbolAddress((void**)&inwhi, g_inw_hi); cudaGetSymbolAddress((void**)&inwlo, g_inw_lo);
    cudaGetSymbolAddress((void**)&xwhi, g_xw_hi);   cudaGetSymbolAddress((void**)&xwlo, g_xw_lo);
    cudaGetSymbolAddress((void**)&dtwhi, g_dtw_hi); cudaGetSymbolAddress((void**)&dtwlo, g_dtw_lo);
    cudaGetSymbolAddress((void**)&owhi, g_ow_hi);   cudaGetSymbolAddress((void**)&owlo, g_ow_lo);
    cudaGetSymbolAddress((void**)&xchi, g_xc_hi);   cudaGetSymbolAddress((void**)&xclo, g_xc_lo);
    cudaGetSymbolAddress((void**)&dtrhi, g_dtr_hi); cudaGetSymbolAddress((void**)&dtrlo, g_dtr_lo);
    cudaGetSymbolAddress((void**)&yhi, g_y_hi);     cudaGetSymbolAddress((void**)&ylo, g_y_lo);

    // 0-2) conversions (3 launches -> in_proj sits at profiled slot 3)
    k_cvt<<<(2097152u + 255) / 256, 256>>>((const float4*)x, xhi, xlo, 2097152u);
    k_cvt<<<(2097152u + 255) / 256, 256>>>((const float4*)in_w, inwhi, inwlo, 2097152u);
    k_cvt3<<<(N4_W3 + 255) / 256, 256>>>((const float4*)x_w, (const float4*)dt_w,
                                         (const float4*)out_w);

    // 3) in_proj: xz = x @ in_w^T  (M=8192, N=8192, K=1024)  [PROFILED SLOT]
    k_gemm_z<<<dim3(64, 64, 1), 256, GEMM_SMEM>>>(xhi, xlo, 0, inwhi, inwlo, 0,
                                                  xz, 0, DM, 8192, 8192, 0);

    // 4) depthwise conv + silu -> xc hi/lo
    k_conv<<<(unsigned)(((size_t)2 * M_ROWS * DI) / 256), 256>>>(conv_w, conv_b);

    // 5) x_proj (both dirs): proj = xc @ x_proj_w^T (N=96, K=2048); dtr fused
    k_gemm_z<<<dim3(1, 64, 2), 256, GEMM_SMEM>>>(
        xchi, xclo, (size_t)M_ROWS * DI, xwhi, xwlo, (size_t)96 * DI,
        proj, (size_t)M_ROWS * 96, DI, 96, 96, 1);

    // 6) dt_proj (both dirs): dt = dt_raw @ dt_proj_w^T (N=2048, K=64)
    k_gemm_z<<<dim3(16, 64, 2), 256, GEMM_SMEM>>>(
        dtrhi, dtrlo, (size_t)M_ROWS * DR, dtwhi, dtwlo, (size_t)DI * DR,
        dtv, (size_t)M_ROWS * DI, DR, DI, DI, 0);

    // 7) selective scan + gating -> y hi/lo
    k_scan<<<dim3(DI / 128, BSZ, 2), 128>>>(dt_bv, A_log, Dp);

    // 8) out_proj (both dirs, K-concatenated single pass)
    k_gemm_cat<<<dim3(8, 64, 1), 256, GEMM_SMEM>>>(
        yhi, ylo, yhi + (size_t)M_ROWS * DI, ylo + (size_t)M_ROWS * DI,
        owhi, owlo, owhi + (size_t)DM * DI, owlo + (size_t)DM * DI,
        out, DI, DM, DM);
}

// round 9
// speedup vs baseline: 1.7485x; 1.7485x over previous
#include <cuda_runtime.h>
#include <cuda_bf16.h>
#include <cstdint>
#include <math.h>

// Problem dims
#define L_SEQ 2048
#define BSZ   4
#define DM    1024
#define DI    2048
#define DS    16
#define DR    64
#define M_ROWS 8192   // BSZ * L_SEQ

// ============================================================================
// Scratch (static device arrays)
// ============================================================================
__device__ float g_xz  [(size_t)M_ROWS * 8192];             // in_proj output (xi|z per dir)
__device__ float g_proj[2 * (size_t)M_ROWS * 96];           // x_proj output (dt_raw|B|C)
__device__ float g_dt  [2 * (size_t)M_ROWS * DI];           // dt_proj output (pre-softplus)

// bf16 hi/lo operand planes
__device__ __nv_bfloat16 g_x_hi  [(size_t)M_ROWS * DM],  g_x_lo  [(size_t)M_ROWS * DM];
__device__ __nv_bfloat16 g_inw_hi[(size_t)8192 * DM],    g_inw_lo[(size_t)8192 * DM];
__device__ __nv_bfloat16 g_xw_hi [2 * 96 * (size_t)DI],  g_xw_lo [2 * 96 * (size_t)DI];
__device__ __nv_bfloat16 g_dtw_hi[2 * (size_t)DI * DR],  g_dtw_lo[2 * (size_t)DI * DR];
__device__ __nv_bfloat16 g_ow_hi [2 * (size_t)DM * DI],  g_ow_lo [2 * (size_t)DM * DI];
__device__ __nv_bfloat16 g_xc_hi [2 * (size_t)M_ROWS * DI], g_xc_lo[2 * (size_t)M_ROWS * DI];
__device__ __nv_bfloat16 g_dtr_hi[2 * (size_t)M_ROWS * DR], g_dtr_lo[2 * (size_t)M_ROWS * DR];
__device__ __nv_bfloat16 g_y_hi  [2 * (size_t)M_ROWS * DI], g_y_lo [2 * (size_t)M_ROWS * DI];

__device__ __forceinline__ void split2(float v, __nv_bfloat16& h, __nv_bfloat16& l) {
    h = __float2bfloat16_rn(v);
    l = __float2bfloat16_rn(v - __bfloat162float(h));
}

// ============================================================================
// PTX helpers (sm_80-class only: valid on base sm_103 target)
// ============================================================================
__device__ __forceinline__ uint32_t smem_u32(const void* p) {
    uint32_t a;
    asm("{ .reg .u64 t; cvta.to.shared.u64 t, %1; cvt.u32.u64 %0, t; }" : "=r"(a) : "l"(p));
    return a;
}
__device__ __forceinline__ void cpa16(uint32_t dst, const void* src) {
    asm volatile("cp.async.cg.shared.global [%0], [%1], 16;" :: "r"(dst), "l"(src) : "memory");
}
__device__ __forceinline__ void cpa16p(uint32_t dst, const void* src, int sz) {
    asm volatile("cp.async.cg.shared.global [%0], [%1], 16, %2;" :: "r"(dst), "l"(src), "r"(sz) : "memory");
}
__device__ __forceinline__ void cp_commit() {
    asm volatile("cp.async.commit_group;" ::: "memory");
}
template <int N>
__device__ __forceinline__ void cp_wait() {
    asm volatile("cp.async.wait_group %0;" :: "n"(N) : "memory");
}
__device__ __forceinline__ void ldsm_x4(uint32_t* r, uint32_t addr) {
    asm volatile("ldmatrix.sync.aligned.m8n8.x4.shared.b16 {%0,%1,%2,%3}, [%4];"
                 : "=r"(r[0]), "=r"(r[1]), "=r"(r[2]), "=r"(r[3]) : "r"(addr));
}
__device__ __forceinline__ void ldsm_x2(uint32_t* r, uint32_t addr) {
    asm volatile("ldmatrix.sync.aligned.m8n8.x2.shared.b16 {%0,%1}, [%2];"
                 : "=r"(r[0]), "=r"(r[1]) : "r"(addr));
}
__device__ __forceinline__ void mma_bf16(float* d, const uint32_t* a, const uint32_t* b) {
    asm volatile("mma.sync.aligned.m16n8k16.row.col.f32.bf16.bf16.f32 "
                 "{%0,%1,%2,%3}, {%4,%5,%6,%7}, {%8,%9}, {%0,%1,%2,%3};"
                 : "+f"(d[0]), "+f"(d[1]), "+f"(d[2]), "+f"(d[3])
                 : "r"(a[0]), "r"(a[1]), "r"(a[2]), "r"(a[3]), "r"(b[0]), "r"(b[1]));
}

// ============================================================================
// GEMM machinery (EXACT round-5 best config): 128x128 tile, K-chunk 32,
// 256 threads (2x4 warps, 64x32 warp tiles), 2-stage cp.async pipeline,
// rows padded to 40 halves. Static accumulator indexing ONLY.
// bf16x3 split: acc += Ah*Bh + Ah*Bl + Al*Bh  (fp32 accumulate)
// ============================================================================
#define ROW_H 40
#define PLANE (128 * ROW_H * 2)          // 10240 B
#define OFF_AH 0
#define OFF_AL (PLANE)
#define OFF_BH (2 * PLANE)
#define OFF_BL (3 * PLANE)
#define STAGE  (4 * PLANE)               // 40960 B
#define GEMM_SMEM (2 * STAGE)            // 81920 B

struct GemmCtx {
    uint32_t sb;
    int tid, lane, warp, wm, wn, bm, bn;
    uint32_t a_lane_off, b_lane_off;
};

__device__ __forceinline__ void gemm_init(GemmCtx& g, char* smem) {
    g.sb = smem_u32(smem);
    g.tid = threadIdx.x;
    g.lane = g.tid & 31;
    g.warp = g.tid >> 5;
    g.wm = g.warp >> 2;
    g.wn = g.warp & 3;
    g.bm = blockIdx.y * 128;
    g.bn = blockIdx.x * 128;
    g.a_lane_off = (uint32_t)((g.lane & 15) * ROW_H + 8 * (g.lane >> 4)) * 2;
    g.b_lane_off = (uint32_t)((g.lane & 7) * ROW_H + 8 * ((g.lane >> 3) & 1)) * 2;
}

__device__ __forceinline__ void gemm_load_chunk(
    const GemmCtx& g, int s, int k0, int K,
    const __nv_bfloat16* __restrict__ Ahi, const __nv_bfloat16* __restrict__ Alo,
    const __nv_bfloat16* __restrict__ Bhi, const __nv_bfloat16* __restrict__ Blo,
    int Nact)
{
    const uint32_t st = g.sb + s * STAGE;
#pragma unroll
    for (int it = 0; it < 2; ++it) {
        const int i   = g.tid + it * 256;
        const int row = i >> 2;
        const int c8  = (i & 3) * 8;
        const uint32_t so = (uint32_t)(row * ROW_H + c8) * 2;
        const size_t ga = (size_t)(g.bm + row) * K + k0 + c8;
        cpa16(st + OFF_AH + so, Ahi + ga);
        cpa16(st + OFF_AL + so, Alo + ga);
        const size_t gb = (size_t)(g.bn + row) * K + k0 + c8;
        const int sz = (g.bn + row < Nact) ? 16 : 0;
        cpa16p(st + OFF_BH + so, Bhi + gb, sz);
        cpa16p(st + OFF_BL + so, Blo + gb, sz);
    }
}

// Pass-major MMA schedule, static indices only (dynamic acc idx => spills!)
__device__ __forceinline__ void gemm_compute_chunk(const GemmCtx& g, int s, float acc[4][4][4]) {
    const uint32_t st = g.sb + s * STAGE;
#pragma unroll
    for (int k16 = 0; k16 < 32; k16 += 16) {
        const uint32_t ak = g.a_lane_off + k16 * 2;
        const uint32_t bk = g.b_lane_off + k16 * 2;
        uint32_t bh[4][2], bl[4][2];
#pragma unroll
        for (int j = 0; j < 4; ++j) {
            const uint32_t bo = (uint32_t)((g.wn * 32 + j * 8) * ROW_H) * 2 + bk;
            ldsm_x2(bh[j], st + OFF_BH + bo);
            ldsm_x2(bl[j], st + OFF_BL + bo);
        }
#pragma unroll
        for (int i = 0; i < 4; ++i) {
            const uint32_t ao = (uint32_t)((g.wm * 64 + i * 16) * ROW_H) * 2 + ak;
            uint32_t ah[4], al[4];
            ldsm_x4(ah, st + OFF_AH + ao);
            ldsm_x4(al, st + OFF_AL + ao);
#pragma unroll
            for (int j = 0; j < 4; ++j) mma_bf16(acc[i][j], ah, bh[j]);
#pragma unroll
            for (int j = 0; j < 4; ++j) mma_bf16(acc[i][j], ah, bl[j]);
#pragma unroll
            for (int j = 0; j < 4; ++j) mma_bf16(acc[i][j], al, bh[j]);
        }
    }
}

// ============================================================================
// k_gemm_z: C[z][M,N] = A[z][M,K] @ B[z][N,K]^T   (z = blockIdx.z, strides)
// Optional dtr epilogue: cols<64 also split to g_dtr_hi/lo (x_proj only).
// ============================================================================
__global__ void __launch_bounds__(256, 2) k_gemm_z(
    const __nv_bfloat16* __restrict__ Ahi, const __nv_bfloat16* __restrict__ Alo, size_t aStride,
    const __nv_bfloat16* __restrict__ Bhi, const __nv_bfloat16* __restrict__ Blo, size_t bStride,
    float* __restrict__ C, size_t cStride, int K, int Nact, int ldc, int doDtr)
{
    extern __shared__ char smem[];
    GemmCtx g;
    gemm_init(g, smem);
    const int z = blockIdx.z;
    Ahi += (size_t)z * aStride; Alo += (size_t)z * aStride;
    Bhi += (size_t)z * bStride; Blo += (size_t)z * bStride;
    C   += (size_t)z * cStride;
    const int nch = K >> 5;

    float acc[4][4][4];
#pragma unroll
    for (int i = 0; i < 4; i++)
#pragma unroll
        for (int j = 0; j < 4; j++)
#pragma unroll
            for (int k = 0; k < 4; k++) acc[i][j][k] = 0.f;

    gemm_load_chunk(g, 0, 0, K, Ahi, Alo, Bhi, Blo, Nact);
    cp_commit();

    for (int c = 0; c < nch; ++c) {
        if (c + 1 < nch) {
            gemm_load_chunk(g, (c + 1) & 1, (c + 1) << 5, K, Ahi, Alo, Bhi, Blo, Nact);
            cp_commit();
            cp_wait<1>();
        } else {
            cp_wait<0>();
        }
        __syncthreads();
        gemm_compute_chunk(g, c & 1, acc);
        __syncthreads();
    }

    const int gid = g.lane >> 2;
    const int tig = g.lane & 3;
#pragma unroll
    for (int i = 0; i < 4; ++i) {
        const int row = g.bm + g.wm * 64 + i * 16 + gid;
#pragma unroll
        for (int j = 0; j < 4; ++j) {
            const int col = g.bn + g.wn * 32 + j * 8 + tig * 2;
            if (col < Nact) {
                *(float2*)&C[(size_t)row * ldc + col]       = make_float2(acc[i][j][0], acc[i][j][1]);
                *(float2*)&C[(size_t)(row + 8) * ldc + col] = make_float2(acc[i][j][2], acc[i][j][3]);
                if (doDtr && col < DR) {
                    __nv_bfloat16 h0, l0, h1, l1;
                    size_t d0 = ((size_t)z * M_ROWS + row) * DR + col;
                    split2(acc[i][j][0], h0, l0); split2(acc[i][j][1], h1, l1);
                    g_dtr_hi[d0] = h0; g_dtr_hi[d0 + 1] = h1;
                    g_dtr_lo[d0] = l0; g_dtr_lo[d0 + 1] = l1;
                    size_t d8 = d0 + 8 * DR;
                    split2(acc[i][j][2], h0, l0); split2(acc[i][j][3], h1, l1);
                    g_dtr_hi[d8] = h0; g_dtr_hi[d8 + 1] = h1;
                    g_dtr_lo[d8] = l0; g_dtr_lo[d8 + 1] = l1;
                }
            }
        }
    }
}

// ============================================================================
// k_gemm_cat: out = y0 @ ow0^T + y1 @ ow1^T  (K-concatenated, single pass)
// ============================================================================
__global__ void __launch_bounds__(256, 2) k_gemm_cat(
    const __nv_bfloat16* __restrict__ A0hi, const __nv_bfloat16* __restrict__ A0lo,
    const __nv_bfloat16* __restrict__ A1hi, const __nv_bfloat16* __restrict__ A1lo,
    const __nv_bfloat16* __restrict__ B0hi, const __nv_bfloat16* __restrict__ B0lo,
    const __nv_bfloat16* __restrict__ B1hi, const __nv_bfloat16* __restrict__ B1lo,
    float* __restrict__ C, int Kh, int Nact, int ldc)
{
    extern __shared__ char smem[];
    GemmCtx g;
    gemm_init(g, smem);
    const int nch_h = Kh >> 5;
    const int nch = nch_h * 2;

    float acc[4][4][4];
#pragma unroll
    for (int i = 0; i < 4; i++)
#pragma unroll
        for (int j = 0; j < 4; j++)
#pragma unroll
            for (int k = 0; k < 4; k++) acc[i][j][k] = 0.f;

    auto load = [&](int c, int s) {
        if (c < nch_h)
            gemm_load_chunk(g, s, c << 5, Kh, A0hi, A0lo, B0hi, B0lo, Nact);
        else
            gemm_load_chunk(g, s, (c - nch_h) << 5, Kh, A1hi, A1lo, B1hi, B1lo, Nact);
    };

    load(0, 0);
    cp_commit();
    for (int c = 0; c < nch; ++c) {
        if (c + 1 < nch) {
            load(c + 1, (c + 1) & 1);
            cp_commit();
            cp_wait<1>();
        } else {
            cp_wait<0>();
        }
        __syncthreads();
        gemm_compute_chunk(g, c & 1, acc);
        __syncthreads();
    }

    const int gid = g.lane >> 2;
    const int tig = g.lane & 3;
#pragma unroll
    for (int i = 0; i < 4; ++i) {
        const int row = g.bm + g.wm * 64 + i * 16 + gid;
#pragma unroll
        for (int j = 0; j < 4; ++j) {
            const int col = g.bn + g.wn * 32 + j * 8 + tig * 2;
            if (col < Nact) {
                *(float2*)&C[(size_t)row * ldc + col]       = make_float2(acc[i][j][0], acc[i][j][1]);
                *(float2*)&C[(size_t)(row + 8) * ldc + col] = make_float2(acc[i][j][2], acc[i][j][3]);
            }
        }
    }
}

// ============================================================================
// fp32 -> bf16 hi/lo conversions. Split into 3 launches so in_proj lands at
// launch index 3 (the slot ncu captures).
// ============================================================================
__global__ void k_cvt(const float4* __restrict__ src, __nv_bfloat16* __restrict__ hi,
                      __nv_bfloat16* __restrict__ lo, unsigned n4) {
    unsigned i = blockIdx.x * blockDim.x + threadIdx.x;
    if (i >= n4) return;
    float4 v = src[i];
    __nv_bfloat16 h0, h1, h2, h3, l0, l1, l2, l3;
    split2(v.x, h0, l0); split2(v.y, h1, l1); split2(v.z, h2, l2); split2(v.w, h3, l3);
    __nv_bfloat162* H = (__nv_bfloat162*)hi;
    __nv_bfloat162* L = (__nv_bfloat162*)lo;
    H[2 * (size_t)i]     = __nv_bfloat162(h0, h1);
    H[2 * (size_t)i + 1] = __nv_bfloat162(h2, h3);
    L[2 * (size_t)i]     = __nv_bfloat162(l0, l1);
    L[2 * (size_t)i + 1] = __nv_bfloat162(l2, l3);
}

#define N4_XW  98304u     // 2*96*2048/4
#define N4_DTW 65536u     // 2*2048*64/4
#define N4_OW  1048576u   // 2*1024*2048/4
#define N4_W3  (N4_XW + N4_DTW + N4_OW)

__global__ void k_cvt3(const float4* __restrict__ xw, const float4* __restrict__ dtw,
                       const float4* __restrict__ ow) {
    unsigned i = blockIdx.x * blockDim.x + threadIdx.x;
    if (i >= N4_W3) return;
    const float4* src;
    __nv_bfloat16 *hi, *lo;
    unsigned off = i;
    if (i < N4_XW)                      { src = xw;  hi = g_xw_hi;  lo = g_xw_lo; }
    else if ((off -= N4_XW) < N4_DTW)   { src = dtw; hi = g_dtw_hi; lo = g_dtw_lo; }
    else { off -= N4_DTW;                 src = ow;  hi = g_ow_hi;  lo = g_ow_lo; }
    float4 v = src[off];
    __nv_bfloat16 h0, h1, h2, h3, l0, l1, l2, l3;
    split2(v.x, h0, l0); split2(v.y, h1, l1); split2(v.z, h2, l2); split2(v.w, h3, l3);
    __nv_bfloat162* H = (__nv_bfloat162*)hi;
    __nv_bfloat162* L = (__nv_bfloat162*)lo;
    H[2 * (size_t)off]     = __nv_bfloat162(h0, h1);
    H[2 * (size_t)off + 1] = __nv_bfloat162(h2, h3);
    L[2 * (size_t)off]     = __nv_bfloat162(l0, l1);
    L[2 * (size_t)off + 1] = __nv_bfloat162(l2, l3);
}

// ============================================================================
// Depthwise conv (causal fwd / anti-causal bwd) + SiLU -> xc hi/lo planes
// ============================================================================
__global__ void k_conv(const float* __restrict__ cw, const float* __restrict__ cb) {
    size_t idx = (size_t)blockIdx.x * blockDim.x + threadIdx.x;
    if (idx >= (size_t)2 * M_ROWS * DI) return;
    int e = (int)(idx % DI);
    size_t r = idx / DI;
    int m = (int)(r % M_ROWS);
    int dir = (int)(r / M_ROWS);
    int l = m % L_SEQ;
    int b = m / L_SEQ;

    float acc = cb[dir * DI + e];
    const float* w4 = cw + ((size_t)dir * DI + e) * 4;
#pragma unroll
    for (int k = 0; k < 4; k++) {
        int tl = (dir == 0) ? (l - 3 + k) : (l + 3 - k);
        if (tl >= 0 && tl < L_SEQ)
            acc = fmaf(w4[k], g_xz[((size_t)(b * L_SEQ + tl)) * 8192 + dir * 4096 + e], acc);
    }
    float xc = acc / (1.f + __expf(-acc));   // silu
    __nv_bfloat16 h, lo;
    split2(xc, h, lo);
    size_t o = ((size_t)dir * M_ROWS + m) * DI + e;
    g_xc_hi[o] = h;
    g_xc_lo[o] = lo;
}

// ============================================================================
// Selective scan v2: 2 lanes per channel (8 states each, shfl-combined y).
// 256-thread blocks, 1024 warps chip-wide (was 512 -> sub-1 warp/SMSP).
// 4-deep register-ring prefetch. Fuses softplus, recurrence, D-skip, gating.
// ============================================================================
__global__ void __launch_bounds__(256) k_scan(const float* __restrict__ dt_b,
                                              const float* __restrict__ A_log,
                                              const float* __restrict__ Dp) {
    const int tid  = threadIdx.x;
    const int lane = tid & 31;
    const int warp = tid >> 5;          // 0..7
    const int half = lane & 1;          // state half: 0 -> s0..7, 1 -> s8..15
    const int dir  = blockIdx.z;
    const int b    = blockIdx.y;
    const int e    = blockIdx.x * 128 + warp * 16 + (lane >> 1);

    __shared__ float sB[8][16], sC[8][16];

    float a[8];
#pragma unroll
    for (int s = 0; s < 8; s++)
        a[s] = -__expf(A_log[((size_t)dir * DI + e) * 16 + half * 8 + s]);

    const float bias  = dt_b[dir * DI + e];
    const float dcoef = Dp[dir * DI + e];

    float h[8];
#pragma unroll
    for (int s = 0; s < 8; s++) h[s] = 0.f;

    const size_t base_de   = (size_t)dir * M_ROWS * DI;
    const size_t proj_base = (size_t)dir * M_ROWS * 96;
    const size_t brow      = (size_t)b * L_SEQ;

    // 4-deep prefetch ring
    float rbc[4], rdt[4], rxh[4], rxl[4], rz[4];
#pragma unroll
    for (int p = 0; p < 4; p++) {
        const int tt = dir ? (L_SEQ - 1 - p) : p;
        const size_t m = brow + tt;
        rbc[p] = g_proj[proj_base + m * 96 + 64 + lane];
        rdt[p] = g_dt[base_de + m * DI + e];
        rxh[p] = __bfloat162float(g_xc_hi[base_de + m * DI + e]);
        rxl[p] = __bfloat162float(g_xc_lo[base_de + m * DI + e]);
        rz[p]  = g_xz[m * 8192 + dir * 4096 + 2048 + e];
    }

    for (int t0 = 0; t0 < L_SEQ; t0 += 4) {
#pragma unroll
        for (int u = 0; u < 4; u++) {
            const int t  = t0 + u;
            const int tt = dir ? (L_SEQ - 1 - t) : t;
            const size_t m = brow + tt;

            const float bc = rbc[u], dtv = rdt[u], xh = rxh[u], xl = rxl[u], zz = rz[u];

            const int tp = t + 4;
            if (tp < L_SEQ) {
                const int tq = dir ? (L_SEQ - 1 - tp) : tp;
                const size_t mp = brow + tq;
                rbc[u] = g_proj[proj_base + mp * 96 + 64 + lane];
                rdt[u] = g_dt[base_de + mp * DI + e];
                rxh[u] = __bfloat162float(g_xc_hi[base_de + mp * DI + e]);
                rxl[u] = __bfloat162float(g_xc_lo[base_de + mp * DI + e]);
                rz[u]  = g_xz[mp * 8192 + dir * 4096 + 2048 + e];
            }

            if (lane < 16) sB[warp][lane] = bc; else sC[warp][lane - 16] = bc;
            __syncwarp();

            const float v   = dtv + bias;
            const float dt  = (v > 15.f) ? v : log1pf(__expf(v));
            const float x   = xh + xl;
            const float dtx = dt * x;

            float y = 0.f;
#pragma unroll
            for (int s = 0; s < 8; s++) {
                float dA = __expf(dt * a[s]);
                h[s] = fmaf(h[s], dA, dtx * sB[warp][half * 8 + s]);
                y    = fmaf(h[s], sC[warp][half * 8 + s], y);
            }
            // combine the two state-halves of this channel
            y += __shfl_xor_sync(0xffffffffu, y, 1);

            const float yv  = fmaf(x, dcoef, y);
            const float sz  = zz / (1.f + __expf(-zz));
            const float out = yv * sz;
            __nv_bfloat16 hh, ll;
            split2(out, hh, ll);
            const size_t o = base_de + m * DI + e;
            if (half == 0) g_y_hi[o] = hh;
            else           g_y_lo[o] = ll;
            __syncwarp();
        }
    }
}

// ============================================================================
extern "C" void kernel_launch(void* const* d_in, const int* in_sizes, int n_in,
                              void* d_out, int out_size) {
    const float* x      = (const float*)d_in[0];
    const float* in_w   = (const float*)d_in[1];
    const float* conv_w = (const float*)d_in[2];
    const float* conv_b = (const float*)d_in[3];
    const float* x_w    = (const float*)d_in[4];
    const float* dt_w   = (const float*)d_in[5];
    const float* dt_bv  = (const float*)d_in[6];
    const float* A_log  = (const float*)d_in[7];
    const float* Dp     = (const float*)d_in[8];
    const float* out_w  = (const float*)d_in[9];
    float* out = (float*)d_out;

    cudaFuncSetAttribute(k_gemm_z,   cudaFuncAttributeMaxDynamicSharedMemorySize, GEMM_SMEM);
    cudaFuncSetAttribute(k_gemm_cat, cudaFuncAttributeMaxDynamicSharedMemorySize, GEMM_SMEM);

    float *xz, *proj, *dtv;
    __nv_bfloat16 *xhi, *xlo, *inwhi, *inwlo, *xwhi, *xwlo, *dtwhi, *dtwlo, *owhi, *owlo;
    __nv_bfloat16 *xchi, *xclo, *dtrhi, *dtrlo, *yhi, *ylo;
    cudaGetSymbolAddress((void**)&xz, g_xz);
    cudaGetSymbolAddress((void**)&proj, g_proj);
    cudaGetSymbolAddress((void**)&dtv, g_dt);
    cudaGetSymbolAddress((void**)&xhi, g_x_hi);     cudaGetSymbolAddress((void**)&xlo, g_x_lo);
    cudaGetSymbolAddress((void**)&inwhi, g_inw_hi); cudaGetSymbolAddress((void**)&inwlo, g_inw_lo);
    cudaGetSymbolAddress((void**)&xwhi, g_xw_hi);   cudaGetSymbolAddress((void**)&xwlo, g_xw_lo);
    cudaGetSymbolAddress((void**)&dtwhi, g_dtw_hi); cudaGetSymbolAddress((void**)&dtwlo, g_dtw_lo);
    cudaGetSymbolAddress((void**)&owhi, g_ow_hi);   cudaGetSymbolAddress((void**)&owlo, g_ow_lo);
    cudaGetSymbolAddress((void**)&xchi, g_xc_hi);   cudaGetSymbolAddress((void**)&xclo, g_xc_lo);
    cudaGetSymbolAddress((void**)&dtrhi, g_dtr_hi); cudaGetSymbolAddress((void**)&dtrlo, g_dtr_lo);
    cudaGetSymbolAddress((void**)&yhi, g_y_hi);     cudaGetSymbolAddress((void**)&ylo, g_y_lo);

    // 0-2) conversions (3 launches -> in_proj sits at profiled slot 3)
    k_cvt<<<(2097152u + 255) / 256, 256>>>((const float4*)x, xhi, xlo, 2097152u);
    k_cvt<<<(2097152u + 255) / 256, 256>>>((const float4*)in_w, inwhi, inwlo, 2097152u);
    k_cvt3<<<(N4_W3 + 255) / 256, 256>>>((const float4*)x_w, (const float4*)dt_w,
                                         (const float4*)out_w);

    // 3) in_proj: xz = x @ in_w^T  (M=8192, N=8192, K=1024)  [PROFILED SLOT]
    k_gemm_z<<<dim3(64, 64, 1), 256, GEMM_SMEM>>>(xhi, xlo, 0, inwhi, inwlo, 0,
                                                  xz, 0, DM, 8192, 8192, 0);

    // 4) depthwise conv + silu -> xc hi/lo
    k_conv<<<(unsigned)(((size_t)2 * M_ROWS * DI) / 256), 256>>>(conv_w, conv_b);

    // 5) x_proj (both dirs): proj = xc @ x_proj_w^T (N=96, K=2048); dtr fused
    k_gemm_z<<<dim3(1, 64, 2), 256, GEMM_SMEM>>>(
        xchi, xclo, (size_t)M_ROWS * DI, xwhi, xwlo, (size_t)96 * DI,
        proj, (size_t)M_ROWS * 96, DI, 96, 96, 1);

    // 6) dt_proj (both dirs): dt = dt_raw @ dt_proj_w^T (N=2048, K=64)
    k_gemm_z<<<dim3(16, 64, 2), 256, GEMM_SMEM>>>(
        dtrhi, dtrlo, (size_t)M_ROWS * DR, dtwhi, dtwlo, (size_t)DI * DR,
        dtv, (size_t)M_ROWS * DI, DR, DI, DI, 0);

    // 7) selective scan + gating -> y hi/lo  (2 lanes/channel, 1024 warps)
    k_scan<<<dim3(DI / 128, BSZ, 2), 256>>>(dt_bv, A_log, Dp);

    // 8) out_proj (both dirs, K-concatenated single pass)
    k_gemm_cat<<<dim3(8, 64, 1), 256, GEMM_SMEM>>>(
        yhi, ylo, yhi + (size_t)M_ROWS * DI, ylo + (size_t)M_ROWS * DI,
        owhi, owlo, owhi + (size_t)DM * DI, owlo + (size_t)DM * DI,
        out, DI, DM, DM);
}

// round 10
// speedup vs baseline: 1.8124x; 1.0365x over previous
#include <cuda_runtime.h>
#include <cuda_bf16.h>
#include <cstdint>
#include <math.h>

// Problem dims
#define L_SEQ 2048
#define BSZ   4
#define DM    1024
#define DI    2048
#define DS    16
#define DR    64
#define M_ROWS 8192   // BSZ * L_SEQ

// ============================================================================
// Scratch (static device arrays)
// ============================================================================
__device__ float g_xz  [(size_t)M_ROWS * 8192];             // in_proj output (xi|z per dir)
__device__ float g_proj[2 * (size_t)M_ROWS * 96];           // x_proj output (dt_raw|B|C)
__device__ float g_proj_part[8 * (size_t)M_ROWS * 96];      // x_proj split-K partials
__device__ float g_dt  [2 * (size_t)M_ROWS * DI];           // dt_proj output (pre-softplus)

// bf16 hi/lo operand planes
__device__ __nv_bfloat16 g_x_hi  [(size_t)M_ROWS * DM],  g_x_lo  [(size_t)M_ROWS * DM];
__device__ __nv_bfloat16 g_inw_hi[(size_t)8192 * DM],    g_inw_lo[(size_t)8192 * DM];
__device__ __nv_bfloat16 g_xw_hi [2 * 96 * (size_t)DI],  g_xw_lo [2 * 96 * (size_t)DI];
__device__ __nv_bfloat16 g_dtw_hi[2 * (size_t)DI * DR],  g_dtw_lo[2 * (size_t)DI * DR];
__device__ __nv_bfloat16 g_ow_hi [2 * (size_t)DM * DI],  g_ow_lo [2 * (size_t)DM * DI];
__device__ __nv_bfloat16 g_xc_hi [2 * (size_t)M_ROWS * DI], g_xc_lo[2 * (size_t)M_ROWS * DI];
__device__ __nv_bfloat16 g_dtr_hi[2 * (size_t)M_ROWS * DR], g_dtr_lo[2 * (size_t)M_ROWS * DR];
__device__ __nv_bfloat16 g_y_hi  [2 * (size_t)M_ROWS * DI], g_y_lo [2 * (size_t)M_ROWS * DI];

__device__ __forceinline__ void split2(float v, __nv_bfloat16& h, __nv_bfloat16& l) {
    h = __float2bfloat16_rn(v);
    l = __float2bfloat16_rn(v - __bfloat162float(h));
}

// ============================================================================
// PTX helpers (sm_80-class only: valid on base sm_103 target)
// ============================================================================
__device__ __forceinline__ uint32_t smem_u32(const void* p) {
    uint32_t a;
    asm("{ .reg .u64 t; cvta.to.shared.u64 t, %1; cvt.u32.u64 %0, t; }" : "=r"(a) : "l"(p));
    return a;
}
__device__ __forceinline__ void cpa16(uint32_t dst, const void* src) {
    asm volatile("cp.async.cg.shared.global [%0], [%1], 16;" :: "r"(dst), "l"(src) : "memory");
}
__device__ __forceinline__ void cpa16p(uint32_t dst, const void* src, int sz) {
    asm volatile("cp.async.cg.shared.global [%0], [%1], 16, %2;" :: "r"(dst), "l"(src), "r"(sz) : "memory");
}
__device__ __forceinline__ void cp_commit() {
    asm volatile("cp.async.commit_group;" ::: "memory");
}
template <int N>
__device__ __forceinline__ void cp_wait() {
    asm volatile("cp.async.wait_group %0;" :: "n"(N) : "memory");
}
__device__ __forceinline__ void ldsm_x4(uint32_t* r, uint32_t addr) {
    asm volatile("ldmatrix.sync.aligned.m8n8.x4.shared.b16 {%0,%1,%2,%3}, [%4];"
                 : "=r"(r[0]), "=r"(r[1]), "=r"(r[2]), "=r"(r[3]) : "r"(addr));
}
__device__ __forceinline__ void ldsm_x2(uint32_t* r, uint32_t addr) {
    asm volatile("ldmatrix.sync.aligned.m8n8.x2.shared.b16 {%0,%1}, [%2];"
                 : "=r"(r[0]), "=r"(r[1]) : "r"(addr));
}
__device__ __forceinline__ void mma_bf16(float* d, const uint32_t* a, const uint32_t* b) {
    asm volatile("mma.sync.aligned.m16n8k16.row.col.f32.bf16.bf16.f32 "
                 "{%0,%1,%2,%3}, {%4,%5,%6,%7}, {%8,%9}, {%0,%1,%2,%3};"
                 : "+f"(d[0]), "+f"(d[1]), "+f"(d[2]), "+f"(d[3])
                 : "r"(a[0]), "r"(a[1]), "r"(a[2]), "r"(a[3]), "r"(b[0]), "r"(b[1]));
}

// ============================================================================
// GEMM machinery (EXACT round-5 best config): 128x128 tile, K-chunk 32,
// 256 threads (2x4 warps, 64x32 warp tiles), 2-stage cp.async pipeline,
// rows padded to 40 halves. Static accumulator indexing ONLY.
// bf16x3 split: acc += Ah*Bh + Ah*Bl + Al*Bh  (fp32 accumulate)
// ============================================================================
#define ROW_H 40
#define PLANE (128 * ROW_H * 2)          // 10240 B
#define OFF_AH 0
#define OFF_AL (PLANE)
#define OFF_BH (2 * PLANE)
#define OFF_BL (3 * PLANE)
#define STAGE  (4 * PLANE)               // 40960 B
#define GEMM_SMEM (2 * STAGE)            // 81920 B

struct GemmCtx {
    uint32_t sb;
    int tid, lane, warp, wm, wn, bm, bn;
    uint32_t a_lane_off, b_lane_off;
};

__device__ __forceinline__ void gemm_init(GemmCtx& g, char* smem) {
    g.sb = smem_u32(smem);
    g.tid = threadIdx.x;
    g.lane = g.tid & 31;
    g.warp = g.tid >> 5;
    g.wm = g.warp >> 2;
    g.wn = g.warp & 3;
    g.bm = blockIdx.y * 128;
    g.bn = blockIdx.x * 128;
    g.a_lane_off = (uint32_t)((g.lane & 15) * ROW_H + 8 * (g.lane >> 4)) * 2;
    g.b_lane_off = (uint32_t)((g.lane & 7) * ROW_H + 8 * ((g.lane >> 3) & 1)) * 2;
}

__device__ __forceinline__ void gemm_load_chunk(
    const GemmCtx& g, int s, int k0, int K,
    const __nv_bfloat16* __restrict__ Ahi, const __nv_bfloat16* __restrict__ Alo,
    const __nv_bfloat16* __restrict__ Bhi, const __nv_bfloat16* __restrict__ Blo,
    int Nact)
{
    const uint32_t st = g.sb + s * STAGE;
#pragma unroll
    for (int it = 0; it < 2; ++it) {
        const int i   = g.tid + it * 256;
        const int row = i >> 2;
        const int c8  = (i & 3) * 8;
        const uint32_t so = (uint32_t)(row * ROW_H + c8) * 2;
        const size_t ga = (size_t)(g.bm + row) * K + k0 + c8;
        cpa16(st + OFF_AH + so, Ahi + ga);
        cpa16(st + OFF_AL + so, Alo + ga);
        const size_t gb = (size_t)(g.bn + row) * K + k0 + c8;
        const int sz = (g.bn + row < Nact) ? 16 : 0;
        cpa16p(st + OFF_BH + so, Bhi + gb, sz);
        cpa16p(st + OFF_BL + so, Blo + gb, sz);
    }
}

// Pass-major MMA schedule, static indices only (dynamic acc idx => spills!)
__device__ __forceinline__ void gemm_compute_chunk(const GemmCtx& g, int s, float acc[4][4][4]) {
    const uint32_t st = g.sb + s * STAGE;
#pragma unroll
    for (int k16 = 0; k16 < 32; k16 += 16) {
        const uint32_t ak = g.a_lane_off + k16 * 2;
        const uint32_t bk = g.b_lane_off + k16 * 2;
        uint32_t bh[4][2], bl[4][2];
#pragma unroll
        for (int j = 0; j < 4; ++j) {
            const uint32_t bo = (uint32_t)((g.wn * 32 + j * 8) * ROW_H) * 2 + bk;
            ldsm_x2(bh[j], st + OFF_BH + bo);
            ldsm_x2(bl[j], st + OFF_BL + bo);
        }
#pragma unroll
        for (int i = 0; i < 4; ++i) {
            const uint32_t ao = (uint32_t)((g.wm * 64 + i * 16) * ROW_H) * 2 + ak;
            uint32_t ah[4], al[4];
            ldsm_x4(ah, st + OFF_AH + ao);
            ldsm_x4(al, st + OFF_AL + ao);
#pragma unroll
            for (int j = 0; j < 4; ++j) mma_bf16(acc[i][j], ah, bh[j]);
#pragma unroll
            for (int j = 0; j < 4; ++j) mma_bf16(acc[i][j], ah, bl[j]);
#pragma unroll
            for (int j = 0; j < 4; ++j) mma_bf16(acc[i][j], al, bh[j]);
        }
    }
}

// ============================================================================
// k_gemm_z: C = A[dir][M, kStart:kStart+kLen] @ B[dir][..]^T (split-K capable)
// blockIdx.z = dir * nsplit + ks;  C += dir*cStride + ks*partStride.
// ============================================================================
__global__ void __launch_bounds__(256, 2) k_gemm_z(
    const __nv_bfloat16* __restrict__ Ahi, const __nv_bfloat16* __restrict__ Alo, size_t aStride,
    const __nv_bfloat16* __restrict__ Bhi, const __nv_bfloat16* __restrict__ Blo, size_t bStride,
    float* __restrict__ C, size_t cStride, size_t partStride,
    int K_ld, int kLen, int nsplit, int Nact, int ldc)
{
    extern __shared__ char smem[];
    GemmCtx g;
    gemm_init(g, smem);
    const int dir = blockIdx.z / nsplit;
    const int ks  = blockIdx.z % nsplit;
    const int kStart = ks * kLen;
    Ahi += (size_t)dir * aStride; Alo += (size_t)dir * aStride;
    Bhi += (size_t)dir * bStride; Blo += (size_t)dir * bStride;
    C   += (size_t)dir * cStride + (size_t)ks * partStride;
    const int nch = kLen >> 5;

    float acc[4][4][4];
#pragma unroll
    for (int i = 0; i < 4; i++)
#pragma unroll
        for (int j = 0; j < 4; j++)
#pragma unroll
            for (int k = 0; k < 4; k++) acc[i][j][k] = 0.f;

    gemm_load_chunk(g, 0, kStart, K_ld, Ahi, Alo, Bhi, Blo, Nact);
    cp_commit();

    for (int c = 0; c < nch; ++c) {
        if (c + 1 < nch) {
            gemm_load_chunk(g, (c + 1) & 1, kStart + ((c + 1) << 5), K_ld, Ahi, Alo, Bhi, Blo, Nact);
            cp_commit();
            cp_wait<1>();
        } else {
            cp_wait<0>();
        }
        __syncthreads();
        gemm_compute_chunk(g, c & 1, acc);
        __syncthreads();
    }

    const int gid = g.lane >> 2;
    const int tig = g.lane & 3;
#pragma unroll
    for (int i = 0; i < 4; ++i) {
        const int row = g.bm + g.wm * 64 + i * 16 + gid;
#pragma unroll
        for (int j = 0; j < 4; ++j) {
            const int col = g.bn + g.wn * 32 + j * 8 + tig * 2;
            if (col < Nact) {
                *(float2*)&C[(size_t)row * ldc + col]       = make_float2(acc[i][j][0], acc[i][j][1]);
                *(float2*)&C[(size_t)(row + 8) * ldc + col] = make_float2(acc[i][j][2], acc[i][j][3]);
            }
        }
    }
}

// ============================================================================
// k_gemm_cat: out = y0 @ ow0^T + y1 @ ow1^T  (K-concatenated, single pass)
// ============================================================================
__global__ void __launch_bounds__(256, 2) k_gemm_cat(
    const __nv_bfloat16* __restrict__ A0hi, const __nv_bfloat16* __restrict__ A0lo,
    const __nv_bfloat16* __restrict__ A1hi, const __nv_bfloat16* __restrict__ A1lo,
    const __nv_bfloat16* __restrict__ B0hi, const __nv_bfloat16* __restrict__ B0lo,
    const __nv_bfloat16* __restrict__ B1hi, const __nv_bfloat16* __restrict__ B1lo,
    float* __restrict__ C, int Kh, int Nact, int ldc)
{
    extern __shared__ char smem[];
    GemmCtx g;
    gemm_init(g, smem);
    const int nch_h = Kh >> 5;
    const int nch = nch_h * 2;

    float acc[4][4][4];
#pragma unroll
    for (int i = 0; i < 4; i++)
#pragma unroll
        for (int j = 0; j < 4; j++)
#pragma unroll
            for (int k = 0; k < 4; k++) acc[i][j][k] = 0.f;

    auto load = [&](int c, int s) {
        if (c < nch_h)
            gemm_load_chunk(g, s, c << 5, Kh, A0hi, A0lo, B0hi, B0lo, Nact);
        else
            gemm_load_chunk(g, s, (c - nch_h) << 5, Kh, A1hi, A1lo, B1hi, B1lo, Nact);
    };

    load(0, 0);
    cp_commit();
    for (int c = 0; c < nch; ++c) {
        if (c + 1 < nch) {
            load(c + 1, (c + 1) & 1);
            cp_commit();
            cp_wait<1>();
        } else {
            cp_wait<0>();
        }
        __syncthreads();
        gemm_compute_chunk(g, c & 1, acc);
        __syncthreads();
    }

    const int gid = g.lane >> 2;
    const int tig = g.lane & 3;
#pragma unroll
    for (int i = 0; i < 4; ++i) {
        const int row = g.bm + g.wm * 64 + i * 16 + gid;
#pragma unroll
        for (int j = 0; j < 4; ++j) {
            const int col = g.bn + g.wn * 32 + j * 8 + tig * 2;
            if (col < Nact) {
                *(float2*)&C[(size_t)row * ldc + col]       = make_float2(acc[i][j][0], acc[i][j][1]);
                *(float2*)&C[(size_t)(row + 8) * ldc + col] = make_float2(acc[i][j][2], acc[i][j][3]);
            }
        }
    }
}

// ============================================================================
// k_reduce_proj: g_proj = sum of 4 split-K partials; cols<64 also split to dtr
// ============================================================================
__global__ void k_reduce_proj() {
    size_t idx = (size_t)blockIdx.x * blockDim.x + threadIdx.x;
    const size_t total = (size_t)2 * M_ROWS * 96;
    if (idx >= total) return;
    const int dir = (int)(idx / ((size_t)M_ROWS * 96));
    const size_t off = idx % ((size_t)M_ROWS * 96);
    const float* base = g_proj_part + (size_t)dir * 4 * M_ROWS * 96;
    float v = base[off] + base[off + (size_t)M_ROWS * 96]
            + base[off + (size_t)2 * M_ROWS * 96] + base[off + (size_t)3 * M_ROWS * 96];
    g_proj[idx] = v;
    const int col = (int)(off % 96);
    if (col < DR) {
        const size_t row = off / 96;
        __nv_bfloat16 h, l;
        split2(v, h, l);
        const size_t d = ((size_t)dir * M_ROWS + row) * DR + col;
        g_dtr_hi[d] = h;
        g_dtr_lo[d] = l;
    }
}

// ============================================================================
// Fused fp32 -> bf16 hi/lo conversion for all 5 input tensors (one launch)
// ============================================================================
#define N4_X   2097152u   // 8192*1024/4
#define N4_INW 2097152u   // 8192*1024/4
#define N4_XW  98304u     // 2*96*2048/4
#define N4_DTW 65536u     // 2*2048*64/4
#define N4_OW  1048576u   // 2*1024*2048/4
#define N4_TOT (N4_X + N4_INW + N4_XW + N4_DTW + N4_OW)

__global__ void k_cvt_all(const float4* __restrict__ x, const float4* __restrict__ inw,
                          const float4* __restrict__ xw, const float4* __restrict__ dtw,
                          const float4* __restrict__ ow) {
    uint32_t i = blockIdx.x * blockDim.x + threadIdx.x;
    if (i >= N4_TOT) return;
    const float4* src;
    __nv_bfloat16 *hi, *lo;
    uint32_t off = i;
    if (i < N4_X)                         { src = x;   hi = g_x_hi;   lo = g_x_lo; }
    else if ((off -= N4_X)   < N4_INW)    { src = inw; hi = g_inw_hi; lo = g_inw_lo; }
    else if ((off -= N4_INW) < N4_XW)     { src = xw;  hi = g_xw_hi;  lo = g_xw_lo; }
    else if ((off -= N4_XW)  < N4_DTW)    { src = dtw; hi = g_dtw_hi; lo = g_dtw_lo; }
    else { off -= N4_DTW;                   src = ow;  hi = g_ow_hi;  lo = g_ow_lo; }

    float4 v = src[off];
    __nv_bfloat16 h0, h1, h2, h3, l0, l1, l2, l3;
    split2(v.x, h0, l0); split2(v.y, h1, l1); split2(v.z, h2, l2); split2(v.w, h3, l3);
    __nv_bfloat162* H = (__nv_bfloat162*)hi;
    __nv_bfloat162* L = (__nv_bfloat162*)lo;
    H[2 * (size_t)off]     = __nv_bfloat162(h0, h1);
    H[2 * (size_t)off + 1] = __nv_bfloat162(h2, h3);
    L[2 * (size_t)off]     = __nv_bfloat162(l0, l1);
    L[2 * (size_t)off + 1] = __nv_bfloat162(l2, l3);
}

// ============================================================================
// Depthwise conv + SiLU, sliding-window sequential over L (reads each xi once).
// Thread = (dir, b, chunk, e); L split into 4 chunks of 512.
// dir0 (causal):      xc[l] = cb + sum_k cw[k] * xi[l-3+k]
// dir1 (anti-causal): xc[l] = cb + sum_k cw[k] * xi[l+3-k]
// ============================================================================
#define CONV_CH 4
#define CONV_LC (L_SEQ / CONV_CH)   // 512

__global__ void __launch_bounds__(256) k_conv(const float* __restrict__ cw,
                                              const float* __restrict__ cb) {
    const int gtid = blockIdx.x * 256 + threadIdx.x;     // 0 .. 65535
    const int e = gtid & (DI - 1);
    const int r = gtid >> 11;      // 0..31
    const int chunk = r & 3;
    const int b = (r >> 2) & 3;
    const int dir = r >> 4;
    const int t0 = chunk * CONV_LC;

    const float* w4 = cw + ((size_t)dir * DI + e) * 4;
    float w0, w1, w2, w3;
    if (dir == 0) { w0 = w4[0]; w1 = w4[1]; w2 = w4[2]; w3 = w4[3]; }
    else          { w0 = w4[3]; w1 = w4[2]; w2 = w4[1]; w3 = w4[0]; }
    const float bias = cb[dir * DI + e];

    const size_t xibase = (size_t)dir * 4096 + e;
    const size_t mrow   = (size_t)b * L_SEQ;
    auto XI = [&](int t) -> float {
        return (t >= 0 && t < L_SEQ) ? g_xz[(mrow + t) * 8192 + xibase] : 0.f;
    };

    float h0 = 0.f, h1, h2, h3;
    if (dir == 0) { h1 = XI(t0 - 3); h2 = XI(t0 - 2); h3 = XI(t0 - 1); }
    else          { h1 = XI(t0);     h2 = XI(t0 + 1); h3 = XI(t0 + 2); }

    const size_t obase = ((size_t)dir * M_ROWS + mrow) * DI + e;
#pragma unroll 4
    for (int l = t0; l < t0 + CONV_LC; ++l) {
        const float nv = (dir == 0) ? XI(l) : XI(l + 3);
        h0 = h1; h1 = h2; h2 = h3; h3 = nv;
        const float acc = bias + w0 * h0 + w1 * h1 + w2 * h2 + w3 * h3;
        const float xc = acc / (1.f + __expf(-acc));
        __nv_bfloat16 hh, ll;
        split2(xc, hh, ll);
        g_xc_hi[obase + (size_t)l * DI] = hh;
        g_xc_lo[obase + (size_t)l * DI] = ll;
    }
}

// ============================================================================
// Selective scan (R5 v1): 128-thread blocks, 4-deep register-ring prefetch.
// Fuses softplus, recurrence, D-skip, silu(z) gating. Writes y hi/lo planes.
// ============================================================================
__global__ void __launch_bounds__(128) k_scan(const float* __restrict__ dt_b,
                                              const float* __restrict__ A_log,
                                              const float* __restrict__ Dp) {
    const int tid  = threadIdx.x;
    const int lane = tid & 31;
    const int warp = tid >> 5;
    const int dir  = blockIdx.z;
    const int b    = blockIdx.y;
    const int e    = blockIdx.x * 128 + tid;

    __shared__ float sB[4][16], sC[4][16];

    float a[16];
#pragma unroll
    for (int s = 0; s < 16; s++)
        a[s] = -__expf(A_log[((size_t)dir * DI + e) * 16 + s]);

    const float bias  = dt_b[dir * DI + e];
    const float dcoef = Dp[dir * DI + e];

    float h[16];
#pragma unroll
    for (int s = 0; s < 16; s++) h[s] = 0.f;

    const size_t base_de   = (size_t)dir * M_ROWS * DI;
    const size_t proj_base = (size_t)dir * M_ROWS * 96;
    const size_t brow      = (size_t)b * L_SEQ;

    float rbc[4], rdt[4], rxh[4], rxl[4], rz[4];
#pragma unroll
    for (int p = 0; p < 4; p++) {
        const int tt = dir ? (L_SEQ - 1 - p) : p;
        const size_t m = brow + tt;
        rbc[p] = g_proj[proj_base + m * 96 + 64 + lane];
        rdt[p] = g_dt[base_de + m * DI + e];
        rxh[p] = __bfloat162float(g_xc_hi[base_de + m * DI + e]);
        rxl[p] = __bfloat162float(g_xc_lo[base_de + m * DI + e]);
        rz[p]  = g_xz[m * 8192 + dir * 4096 + 2048 + e];
    }

    for (int t0 = 0; t0 < L_SEQ; t0 += 4) {
#pragma unroll
        for (int u = 0; u < 4; u++) {
            const int t  = t0 + u;
            const int tt = dir ? (L_SEQ - 1 - t) : t;
            const size_t m = brow + tt;

            const float bc = rbc[u], dtv = rdt[u], xh = rxh[u], xl = rxl[u], zz = rz[u];

            const int tp = t + 4;
            if (tp < L_SEQ) {
                const int tq = dir ? (L_SEQ - 1 - tp) : tp;
                const size_t mp = brow + tq;
                rbc[u] = g_proj[proj_base + mp * 96 + 64 + lane];
                rdt[u] = g_dt[base_de + mp * DI + e];
                rxh[u] = __bfloat162float(g_xc_hi[base_de + mp * DI + e]);
                rxl[u] = __bfloat162float(g_xc_lo[base_de + mp * DI + e]);
                rz[u]  = g_xz[mp * 8192 + dir * 4096 + 2048 + e];
            }

            if (lane < 16) sB[warp][lane] = bc; else sC[warp][lane - 16] = bc;
            __syncwarp();

            const float v   = dtv + bias;
            const float dt  = (v > 15.f) ? v : log1pf(__expf(v));
            const float x   = xh + xl;
            const float dtx = dt * x;

            float y = 0.f;
#pragma unroll
            for (int s = 0; s < 16; s++) {
                float dA = __expf(dt * a[s]);
                h[s] = fmaf(h[s], dA, dtx * sB[warp][s]);
                y    = fmaf(h[s], sC[warp][s], y);
            }
            const float yv  = fmaf(x, dcoef, y);
            const float sz  = zz / (1.f + __expf(-zz));
            const float out = yv * sz;
            __nv_bfloat16 hh, ll;
            split2(out, hh, ll);
            const size_t o = base_de + m * DI + e;
            g_y_hi[o] = hh;
            g_y_lo[o] = ll;
            __syncwarp();
        }
    }
}

// ============================================================================
extern "C" void kernel_launch(void* const* d_in, const int* in_sizes, int n_in,
                              void* d_out, int out_size) {
    const float* x      = (const float*)d_in[0];
    const float* in_w   = (const float*)d_in[1];
    const float* conv_w = (const float*)d_in[2];
    const float* conv_b = (const float*)d_in[3];
    const float* x_w    = (const float*)d_in[4];
    const float* dt_w   = (const float*)d_in[5];
    const float* dt_bv  = (const float*)d_in[6];
    const float* A_log  = (const float*)d_in[7];
    const float* Dp     = (const float*)d_in[8];
    const float* out_w  = (const float*)d_in[9];
    float* out = (float*)d_out;

    cudaFuncSetAttribute(k_gemm_z,   cudaFuncAttributeMaxDynamicSharedMemorySize, GEMM_SMEM);
    cudaFuncSetAttribute(k_gemm_cat, cudaFuncAttributeMaxDynamicSharedMemorySize, GEMM_SMEM);

    float *xz, *projpart, *dtv;
    __nv_bfloat16 *xhi, *xlo, *inwhi, *inwlo, *xwhi, *xwlo, *dtwhi, *dtwlo, *owhi, *owlo;
    __nv_bfloat16 *xchi, *xclo, *dtrhi, *dtrlo, *yhi, *ylo;
    cudaGetSymbolAddress((void**)&xz, g_xz);
    cudaGetSymbolAddress((void**)&projpart, g_proj_part);
    cudaGetSymbolAddress((void**)&dtv, g_dt);
    cudaGetSymbolAddress((void**)&xhi, g_x_hi);     cudaGetSymbolAddress((void**)&xlo, g_x_lo);
    cudaGetSymbolAddress((void**)&inwhi, g_inw_hi); cudaGetSymbolAddress((void**)&inwlo, g_inw_lo);
    cudaGetSymbolAddress((void**)&xwhi, g_xw_hi);   cudaGetSymbolAddress((void**)&xwlo, g_xw_lo);
    cudaGetSymbolAddress((void**)&dtwhi, g_dtw_hi); cudaGetSymbolAddress((void**)&dtwlo, g_dtw_lo);
    cudaGetSymbolAddress((void**)&owhi, g_ow_hi);   cudaGetSymbolAddress((void**)&owlo, g_ow_lo);
    cudaGetSymbolAddress((void**)&xchi, g_xc_hi);   cudaGetSymbolAddress((void**)&xclo, g_xc_lo);
    cudaGetSymbolAddress((void**)&dtrhi, g_dtr_hi); cudaGetSymbolAddress((void**)&dtrlo, g_dtr_lo);
    cudaGetSymbolAddress((void**)&yhi, g_y_hi);     cudaGetSymbolAddress((void**)&ylo, g_y_lo);

    // 0) all fp32 -> bf16 hi/lo conversions, one launch
    k_cvt_all<<<(N4_TOT + 255) / 256, 256>>>((const float4*)x, (const float4*)in_w,
                                             (const float4*)x_w, (const float4*)dt_w,
                                             (const float4*)out_w);

    // 1) in_proj: xz = x @ in_w^T  (M=8192, N=8192, K=1024), dirs fused in N
    k_gemm_z<<<dim3(64, 64, 1), 256, GEMM_SMEM>>>(
        xhi, xlo, 0, inwhi, inwlo, 0,
        xz, 0, 0, DM, DM, 1, 8192, 8192);

    // 2) depthwise conv + silu -> xc hi/lo  (sliding window, reads xi once)
    k_conv<<<256, 256>>>(conv_w, conv_b);

    // 3) x_proj (both dirs, split-K x4): partials = xc @ x_proj_w^T
    k_gemm_z<<<dim3(1, 64, 8), 256, GEMM_SMEM>>>(
        xchi, xclo, (size_t)M_ROWS * DI, xwhi, xwlo, (size_t)96 * DI,
        projpart, (size_t)4 * M_ROWS * 96, (size_t)M_ROWS * 96,
        DI, DI / 4, 4, 96, 96);

    // 4) reduce partials -> g_proj, and bf16-split dt_raw -> g_dtr
    k_reduce_proj<<<(unsigned)(((size_t)2 * M_ROWS * 96 + 255) / 256), 256>>>();

    // 5) dt_proj (both dirs): dt = dt_raw @ dt_proj_w^T (N=2048, K=64)
    k_gemm_z<<<dim3(16, 64, 2), 256, GEMM_SMEM>>>(
        dtrhi, dtrlo, (size_t)M_ROWS * DR, dtwhi, dtwlo, (size_t)DI * DR,
        dtv, (size_t)M_ROWS * DI, 0, DR, DR, 1, DI, DI);

    // 6) selective scan + gating -> y hi/lo
    k_scan<<<dim3(DI / 128, BSZ, 2), 128>>>(dt_bv, A_log, Dp);

    // 7) out_proj (both dirs, K-concatenated single pass)
    k_gemm_cat<<<dim3(8, 64, 1), 256, GEMM_SMEM>>>(
        yhi, ylo, yhi + (size_t)M_ROWS * DI, ylo + (size_t)M_ROWS * DI,
        owhi, owlo, owhi + (size_t)DM * DI, owlo + (size_t)DM * DI,
        out, DI, DM, DM);
}

// round 11
// speedup vs baseline: 1.9792x; 1.0921x over previous
#include <cuda_runtime.h>
#include <cuda_bf16.h>
#include <cstdint>
#include <math.h>

// Problem dims
#define L_SEQ 2048
#define BSZ   4
#define DM    1024
#define DI    2048
#define DS    16
#define DR    64
#define M_ROWS 8192   // BSZ * L_SEQ

// ============================================================================
// Scratch (static device arrays)
// ============================================================================
__device__ float g_xz  [(size_t)M_ROWS * 8192];             // in_proj output (xi|z per dir)
__device__ float g_proj[2 * (size_t)M_ROWS * 96];           // x_proj output (dt_raw|B|C)
__device__ float g_dt  [2 * (size_t)M_ROWS * DI];           // dt_proj output (pre-softplus)

// bf16 hi/lo operand planes
__device__ __nv_bfloat16 g_x_hi  [(size_t)M_ROWS * DM],  g_x_lo  [(size_t)M_ROWS * DM];
__device__ __nv_bfloat16 g_inw_hi[(size_t)8192 * DM],    g_inw_lo[(size_t)8192 * DM];
__device__ __nv_bfloat16 g_xw_hi [2 * 96 * (size_t)DI],  g_xw_lo [2 * 96 * (size_t)DI];
__device__ __nv_bfloat16 g_dtw_hi[2 * (size_t)DI * DR],  g_dtw_lo[2 * (size_t)DI * DR];
__device__ __nv_bfloat16 g_ow_hi [2 * (size_t)DM * DI],  g_ow_lo [2 * (size_t)DM * DI];
__device__ __nv_bfloat16 g_xc_hi [2 * (size_t)M_ROWS * DI], g_xc_lo[2 * (size_t)M_ROWS * DI];
__device__ __nv_bfloat16 g_dtr_hi[2 * (size_t)M_ROWS * DR], g_dtr_lo[2 * (size_t)M_ROWS * DR];
__device__ __nv_bfloat16 g_y_hi  [2 * (size_t)M_ROWS * DI], g_y_lo [2 * (size_t)M_ROWS * DI];

__device__ __forceinline__ void split2(float v, __nv_bfloat16& h, __nv_bfloat16& l) {
    h = __float2bfloat16_rn(v);
    l = __float2bfloat16_rn(v - __bfloat162float(h));
}

// ============================================================================
// PTX helpers (sm_80-class only: valid on base sm_103 target)
// ============================================================================
__device__ __forceinline__ uint32_t smem_u32(const void* p) {
    uint32_t a;
    asm("{ .reg .u64 t; cvta.to.shared.u64 t, %1; cvt.u32.u64 %0, t; }" : "=r"(a) : "l"(p));
    return a;
}
__device__ __forceinline__ void cpa16(uint32_t dst, const void* src) {
    asm volatile("cp.async.cg.shared.global [%0], [%1], 16;" :: "r"(dst), "l"(src) : "memory");
}
__device__ __forceinline__ void cpa16p(uint32_t dst, const void* src, int sz) {
    asm volatile("cp.async.cg.shared.global [%0], [%1], 16, %2;" :: "r"(dst), "l"(src), "r"(sz) : "memory");
}
__device__ __forceinline__ void cp_commit() {
    asm volatile("cp.async.commit_group;" ::: "memory");
}
template <int N>
__device__ __forceinline__ void cp_wait() {
    asm volatile("cp.async.wait_group %0;" :: "n"(N) : "memory");
}
__device__ __forceinline__ void ldsm_x4(uint32_t* r, uint32_t addr) {
    asm volatile("ldmatrix.sync.aligned.m8n8.x4.shared.b16 {%0,%1,%2,%3}, [%4];"
                 : "=r"(r[0]), "=r"(r[1]), "=r"(r[2]), "=r"(r[3]) : "r"(addr));
}
__device__ __forceinline__ void ldsm_x2(uint32_t* r, uint32_t addr) {
    asm volatile("ldmatrix.sync.aligned.m8n8.x2.shared.b16 {%0,%1}, [%2];"
                 : "=r"(r[0]), "=r"(r[1]) : "r"(addr));
}
__device__ __forceinline__ void mma_bf16(float* d, const uint32_t* a, const uint32_t* b) {
    asm volatile("mma.sync.aligned.m16n8k16.row.col.f32.bf16.bf16.f32 "
                 "{%0,%1,%2,%3}, {%4,%5,%6,%7}, {%8,%9}, {%0,%1,%2,%3};"
                 : "+f"(d[0]), "+f"(d[1]), "+f"(d[2]), "+f"(d[3])
                 : "r"(a[0]), "r"(a[1]), "r"(a[2]), "r"(a[3]), "r"(b[0]), "r"(b[1]));
}

// ============================================================================
// GEMM machinery: 128x128 tile, K-chunk 32 (64B rows), 256 threads (2x4 warps,
// 64x32 warp tiles). NEW vs R5: XOR-swizzled smem (no padding), 3-stage
// cp.async pipeline, ONE __syncthreads per chunk (trailing barrier provably
// redundant at depth 3). Static accumulator indexing ONLY (dynamic => spills).
// bf16x3 split: acc += Ah*Bh + Ah*Bl + Al*Bh  (fp32 accumulate)
// ============================================================================
#define PLANE 8192                       // 128 rows x 64 B, no padding
#define OFF_AH 0
#define OFF_AL (PLANE)
#define OFF_BH (2 * PLANE)
#define OFF_BL (3 * PLANE)
#define STAGE  (4 * PLANE)               // 32768 B
#define NSTAGE 3
#define GEMM_SMEM (NSTAGE * STAGE)       // 98304 B (2 CTAs/SM: 196608 < 227KB)
// 64B-row swizzle: chunk bits[5:4] ^= row bits[2:1]; conflict-free for
// ldsm 8x8 phases (rows r,r' collide only if r==r') and for cp.async stores.
#define SW64(o) ((o) ^ (((o) >> 3) & 0x30))

struct GemmCtx {
    uint32_t sb;
    int tid, lane, warp, wm, wn, bm, bn;
    uint32_t a_lane_off, b_lane_off;
};

__device__ __forceinline__ void gemm_init(GemmCtx& g, char* smem) {
    g.sb = smem_u32(smem);
    g.tid = threadIdx.x;
    g.lane = g.tid & 31;
    g.warp = g.tid >> 5;
    g.wm = g.warp >> 2;
    g.wn = g.warp & 3;
    g.bm = blockIdx.y * 128;
    g.bn = blockIdx.x * 128;
    g.a_lane_off = (uint32_t)((g.lane & 15) * 64 + (g.lane >> 4) * 16);        // bytes
    g.b_lane_off = (uint32_t)((g.lane & 7) * 64 + ((g.lane >> 3) & 1) * 16);   // bytes
}

__device__ __forceinline__ void gemm_load_chunk(
    const GemmCtx& g, int s, int k0, int K,
    const __nv_bfloat16* __restrict__ Ahi, const __nv_bfloat16* __restrict__ Alo,
    const __nv_bfloat16* __restrict__ Bhi, const __nv_bfloat16* __restrict__ Blo,
    int Nact)
{
    const uint32_t st = g.sb + s * STAGE;
#pragma unroll
    for (int it = 0; it < 2; ++it) {
        const int i   = g.tid + it * 256;
        const int row = i >> 2;
        const int c8  = (i & 3) * 8;                       // halves
        const uint32_t so = SW64((uint32_t)(row * 64 + c8 * 2));
        const size_t ga = (size_t)(g.bm + row) * K + k0 + c8;
        cpa16(st + OFF_AH + so, Ahi + ga);
        cpa16(st + OFF_AL + so, Alo + ga);
        const size_t gb = (size_t)(g.bn + row) * K + k0 + c8;
        const int sz = (g.bn + row < Nact) ? 16 : 0;
        cpa16p(st + OFF_BH + so, Bhi + gb, sz);
        cpa16p(st + OFF_BL + so, Blo + gb, sz);
    }
}

// Pass-major MMA schedule, static indices only.
__device__ __forceinline__ void gemm_compute_chunk(const GemmCtx& g, int s, float acc[4][4][4]) {
    const uint32_t st = g.sb + s * STAGE;
#pragma unroll
    for (int k16 = 0; k16 < 32; k16 += 16) {
        const uint32_t ak = g.a_lane_off + k16 * 2;
        const uint32_t bk = g.b_lane_off + k16 * 2;
        uint32_t bh[4][2], bl[4][2];
#pragma unroll
        for (int j = 0; j < 4; ++j) {
            const uint32_t bo = (uint32_t)((g.wn * 32 + j * 8) * 64) + bk;
            const uint32_t bos = SW64(bo);
            ldsm_x2(bh[j], st + OFF_BH + bos);
            ldsm_x2(bl[j], st + OFF_BL + bos);
        }
#pragma unroll
        for (int i = 0; i < 4; ++i) {
            const uint32_t ao = (uint32_t)((g.wm * 64 + i * 16) * 64) + ak;
            const uint32_t aos = SW64(ao);
            uint32_t ah[4], al[4];
            ldsm_x4(ah, st + OFF_AH + aos);
            ldsm_x4(al, st + OFF_AL + aos);
#pragma unroll
            for (int j = 0; j < 4; ++j) mma_bf16(acc[i][j], ah, bh[j]);
#pragma unroll
            for (int j = 0; j < 4; ++j) mma_bf16(acc[i][j], ah, bl[j]);
#pragma unroll
            for (int j = 0; j < 4; ++j) mma_bf16(acc[i][j], al, bh[j]);
        }
    }
}

// ============================================================================
// k_gemm_z: C[z][M,N] = A[z][M,K] @ B[z][N,K]^T   (z = blockIdx.z, strides)
// Optional dtr epilogue: cols<64 also split to g_dtr_hi/lo (x_proj only).
// ============================================================================
__global__ void __launch_bounds__(256, 2) k_gemm_z(
    const __nv_bfloat16* __restrict__ Ahi, const __nv_bfloat16* __restrict__ Alo, size_t aStride,
    const __nv_bfloat16* __restrict__ Bhi, const __nv_bfloat16* __restrict__ Blo, size_t bStride,
    float* __restrict__ C, size_t cStride, int K, int Nact, int ldc, int doDtr)
{
    extern __shared__ __align__(1024) char smem[];
    GemmCtx g;
    gemm_init(g, smem);
    const int z = blockIdx.z;
    Ahi += (size_t)z * aStride; Alo += (size_t)z * aStride;
    Bhi += (size_t)z * bStride; Blo += (size_t)z * bStride;
    C   += (size_t)z * cStride;
    const int nch = K >> 5;

    float acc[4][4][4];
#pragma unroll
    for (int i = 0; i < 4; i++)
#pragma unroll
        for (int j = 0; j < 4; j++)
#pragma unroll
            for (int k = 0; k < 4; k++) acc[i][j][k] = 0.f;

    // 3-stage prologue (always 2 committed groups)
    gemm_load_chunk(g, 0, 0, K, Ahi, Alo, Bhi, Blo, Nact);
    cp_commit();
    if (1 < nch) gemm_load_chunk(g, 1, 32, K, Ahi, Alo, Bhi, Blo, Nact);
    cp_commit();

    for (int c = 0; c < nch; ++c) {
        cp_wait<1>();              // chunk c complete (<=1 newer group pending)
        __syncthreads();           // single barrier per chunk
        if (c + 2 < nch)
            gemm_load_chunk(g, (c + 2) % NSTAGE, (c + 2) << 5, K, Ahi, Alo, Bhi, Blo, Nact);
        cp_commit();
        gemm_compute_chunk(g, c % NSTAGE, acc);
        // no trailing barrier: buffer (c%3) is next written for chunk c+3,
        // issued only after iteration c+1's barrier.
    }

    const int gid = g.lane >> 2;
    const int tig = g.lane & 3;
#pragma unroll
    for (int i = 0; i < 4; ++i) {
        const int row = g.bm + g.wm * 64 + i * 16 + gid;
#pragma unroll
        for (int j = 0; j < 4; ++j) {
            const int col = g.bn + g.wn * 32 + j * 8 + tig * 2;
            if (col < Nact) {
                *(float2*)&C[(size_t)row * ldc + col]       = make_float2(acc[i][j][0], acc[i][j][1]);
                *(float2*)&C[(size_t)(row + 8) * ldc + col] = make_float2(acc[i][j][2], acc[i][j][3]);
                if (doDtr && col < DR) {
                    __nv_bfloat16 h0, l0, h1, l1;
                    size_t d0 = ((size_t)z * M_ROWS + row) * DR + col;
                    split2(acc[i][j][0], h0, l0); split2(acc[i][j][1], h1, l1);
                    g_dtr_hi[d0] = h0; g_dtr_hi[d0 + 1] = h1;
                    g_dtr_lo[d0] = l0; g_dtr_lo[d0 + 1] = l1;
                    size_t d8 = d0 + 8 * DR;
                    split2(acc[i][j][2], h0, l0); split2(acc[i][j][3], h1, l1);
                    g_dtr_hi[d8] = h0; g_dtr_hi[d8 + 1] = h1;
                    g_dtr_lo[d8] = l0; g_dtr_lo[d8 + 1] = l1;
                }
            }
        }
    }
}

// ============================================================================
// k_gemm_cat: out = y0 @ ow0^T + y1 @ ow1^T  (K-concatenated, single pass)
// ============================================================================
__global__ void __launch_bounds__(256, 2) k_gemm_cat(
    const __nv_bfloat16* __restrict__ A0hi, const __nv_bfloat16* __restrict__ A0lo,
    const __nv_bfloat16* __restrict__ A1hi, const __nv_bfloat16* __restrict__ A1lo,
    const __nv_bfloat16* __restrict__ B0hi, const __nv_bfloat16* __restrict__ B0lo,
    const __nv_bfloat16* __restrict__ B1hi, const __nv_bfloat16* __restrict__ B1lo,
    float* __restrict__ C, int Kh, int Nact, int ldc)
{
    extern __shared__ __align__(1024) char smem[];
    GemmCtx g;
    gemm_init(g, smem);
    const int nch_h = Kh >> 5;
    const int nch = nch_h * 2;

    float acc[4][4][4];
#pragma unroll
    for (int i = 0; i < 4; i++)
#pragma unroll
        for (int j = 0; j < 4; j++)
#pragma unroll
            for (int k = 0; k < 4; k++) acc[i][j][k] = 0.f;

    auto load = [&](int c, int s) {
        if (c < nch_h)
            gemm_load_chunk(g, s, c << 5, Kh, A0hi, A0lo, B0hi, B0lo, Nact);
        else
            gemm_load_chunk(g, s, (c - nch_h) << 5, Kh, A1hi, A1lo, B1hi, B1lo, Nact);
    };

    load(0, 0);
    cp_commit();
    if (1 < nch) load(1, 1);
    cp_commit();

    for (int c = 0; c < nch; ++c) {
        cp_wait<1>();
        __syncthreads();
        if (c + 2 < nch) load(c + 2, (c + 2) % NSTAGE);
        cp_commit();
        gemm_compute_chunk(g, c % NSTAGE, acc);
    }

    const int gid = g.lane >> 2;
    const int tig = g.lane & 3;
#pragma unroll
    for (int i = 0; i < 4; ++i) {
        const int row = g.bm + g.wm * 64 + i * 16 + gid;
#pragma unroll
        for (int j = 0; j < 4; ++j) {
            const int col = g.bn + g.wn * 32 + j * 8 + tig * 2;
            if (col < Nact) {
                *(float2*)&C[(size_t)row * ldc + col]       = make_float2(acc[i][j][0], acc[i][j][1]);
                *(float2*)&C[(size_t)(row + 8) * ldc + col] = make_float2(acc[i][j][2], acc[i][j][3]);
            }
        }
    }
}

// ============================================================================
// Fused fp32 -> bf16 hi/lo conversion for all 5 input tensors (one launch)
// ============================================================================
#define N4_X   2097152u   // 8192*1024/4
#define N4_INW 2097152u   // 8192*1024/4
#define N4_XW  98304u     // 2*96*2048/4
#define N4_DTW 65536u     // 2*2048*64/4
#define N4_OW  1048576u   // 2*1024*2048/4
#define N4_TOT (N4_X + N4_INW + N4_XW + N4_DTW + N4_OW)

__global__ void k_cvt_all(const float4* __restrict__ x, const float4* __restrict__ inw,
                          const float4* __restrict__ xw, const float4* __restrict__ dtw,
                          const float4* __restrict__ ow) {
    uint32_t i = blockIdx.x * blockDim.x + threadIdx.x;
    if (i >= N4_TOT) return;
    const float4* src;
    __nv_bfloat16 *hi, *lo;
    uint32_t off = i;
    if (i < N4_X)                         { src = x;   hi = g_x_hi;   lo = g_x_lo; }
    else if ((off -= N4_X)   < N4_INW)    { src = inw; hi = g_inw_hi; lo = g_inw_lo; }
    else if ((off -= N4_INW) < N4_XW)     { src = xw;  hi = g_xw_hi;  lo = g_xw_lo; }
    else if ((off -= N4_XW)  < N4_DTW)    { src = dtw; hi = g_dtw_hi; lo = g_dtw_lo; }
    else { off -= N4_DTW;                   src = ow;  hi = g_ow_hi;  lo = g_ow_lo; }

    float4 v = src[off];
    __nv_bfloat16 h0, h1, h2, h3, l0, l1, l2, l3;
    split2(v.x, h0, l0); split2(v.y, h1, l1); split2(v.z, h2, l2); split2(v.w, h3, l3);
    __nv_bfloat162* H = (__nv_bfloat162*)hi;
    __nv_bfloat162* L = (__nv_bfloat162*)lo;
    H[2 * (size_t)off]     = __nv_bfloat162(h0, h1);
    H[2 * (size_t)off + 1] = __nv_bfloat162(h2, h3);
    L[2 * (size_t)off]     = __nv_bfloat162(l0, l1);
    L[2 * (size_t)off + 1] = __nv_bfloat162(l2, l3);
}

// ============================================================================
// Depthwise conv (causal fwd / anti-causal bwd) + SiLU -> xc hi/lo planes
// (R5 elementwise version: 4 taps/thread, L2-served reuse)
// ============================================================================
__global__ void k_conv(const float* __restrict__ cw, const float* __restrict__ cb) {
    size_t idx = (size_t)blockIdx.x * blockDim.x + threadIdx.x;
    if (idx >= (size_t)2 * M_ROWS * DI) return;
    int e = (int)(idx % DI);
    size_t r = idx / DI;
    int m = (int)(r % M_ROWS);
    int dir = (int)(r / M_ROWS);
    int l = m % L_SEQ;
    int b = m / L_SEQ;

    float acc = cb[dir * DI + e];
    const float* w4 = cw + ((size_t)dir * DI + e) * 4;
#pragma unroll
    for (int k = 0; k < 4; k++) {
        int tl = (dir == 0) ? (l - 3 + k) : (l + 3 - k);
        if (tl >= 0 && tl < L_SEQ)
            acc = fmaf(w4[k], g_xz[((size_t)(b * L_SEQ + tl)) * 8192 + dir * 4096 + e], acc);
    }
    float xc = acc / (1.f + __expf(-acc));   // silu
    __nv_bfloat16 h, lo;
    split2(xc, h, lo);
    size_t o = ((size_t)dir * M_ROWS + m) * DI + e;
    g_xc_hi[o] = h;
    g_xc_lo[o] = lo;
}

// ============================================================================
// Selective scan (R5 v1): 128-thread blocks, 4-deep register-ring prefetch.
// Fuses softplus, recurrence, D-skip, silu(z) gating. Writes y hi/lo planes.
// ============================================================================
__global__ void __launch_bounds__(128) k_scan(const float* __restrict__ dt_b,
                                              const float* __restrict__ A_log,
                                              const float* __restrict__ Dp) {
    const int tid  = threadIdx.x;
    const int lane = tid & 31;
    const int warp = tid >> 5;
    const int dir  = blockIdx.z;
    const int b    = blockIdx.y;
    const int e    = blockIdx.x * 128 + tid;

    __shared__ float sB[4][16], sC[4][16];

    float a[16];
#pragma unroll
    for (int s = 0; s < 16; s++)
        a[s] = -__expf(A_log[((size_t)dir * DI + e) * 16 + s]);

    const float bias  = dt_b[dir * DI + e];
    const float dcoef = Dp[dir * DI + e];

    float h[16];
#pragma unroll
    for (int s = 0; s < 16; s++) h[s] = 0.f;

    const size_t base_de   = (size_t)dir * M_ROWS * DI;
    const size_t proj_base = (size_t)dir * M_ROWS * 96;
    const size_t brow      = (size_t)b * L_SEQ;

    float rbc[4], rdt[4], rxh[4], rxl[4], rz[4];
#pragma unroll
    for (int p = 0; p < 4; p++) {
        const int tt = dir ? (L_SEQ - 1 - p) : p;
        const size_t m = brow + tt;
        rbc[p] = g_proj[proj_base + m * 96 + 64 + lane];
        rdt[p] = g_dt[base_de + m * DI + e];
        rxh[p] = __bfloat162float(g_xc_hi[base_de + m * DI + e]);
        rxl[p] = __bfloat162float(g_xc_lo[base_de + m * DI + e]);
        rz[p]  = g_xz[m * 8192 + dir * 4096 + 2048 + e];
    }

    for (int t0 = 0; t0 < L_SEQ; t0 += 4) {
#pragma unroll
        for (int u = 0; u < 4; u++) {
            const int t  = t0 + u;
            const int tt = dir ? (L_SEQ - 1 - t) : t;
            const size_t m = brow + tt;

            const float bc = rbc[u], dtv = rdt[u], xh = rxh[u], xl = rxl[u], zz = rz[u];

            const int tp = t + 4;
            if (tp < L_SEQ) {
                const int tq = dir ? (L_SEQ - 1 - tp) : tp;
                const size_t mp = brow + tq;
                rbc[u] = g_proj[proj_base + mp * 96 + 64 + lane];
                rdt[u] = g_dt[base_de + mp * DI + e];
                rxh[u] = __bfloat162float(g_xc_hi[base_de + mp * DI + e]);
                rxl[u] = __bfloat162float(g_xc_lo[base_de + mp * DI + e]);
                rz[u]  = g_xz[mp * 8192 + dir * 4096 + 2048 + e];
            }

            if (lane < 16) sB[warp][lane] = bc; else sC[warp][lane - 16] = bc;
            __syncwarp();

            const float v   = dtv + bias;
            const float dt  = (v > 15.f) ? v : log1pf(__expf(v));
            const float x   = xh + xl;
            const float dtx = dt * x;

            float y = 0.f;
#pragma unroll
            for (int s = 0; s < 16; s++) {
                float dA = __expf(dt * a[s]);
                h[s] = fmaf(h[s], dA, dtx * sB[warp][s]);
                y    = fmaf(h[s], sC[warp][s], y);
            }
            const float yv  = fmaf(x, dcoef, y);
            const float sz  = zz / (1.f + __expf(-zz));
            const float out = yv * sz;
            __nv_bfloat16 hh, ll;
            split2(out, hh, ll);
            const size_t o = base_de + m * DI + e;
            g_y_hi[o] = hh;
            g_y_lo[o] = ll;
            __syncwarp();
        }
    }
}

// ============================================================================
extern "C" void kernel_launch(void* const* d_in, const int* in_sizes, int n_in,
                              void* d_out, int out_size) {
    const float* x      = (const float*)d_in[0];
    const float* in_w   = (const float*)d_in[1];
    const float* conv_w = (const float*)d_in[2];
    const float* conv_b = (const float*)d_in[3];
    const float* x_w    = (const float*)d_in[4];
    const float* dt_w   = (const float*)d_in[5];
    const float* dt_bv  = (const float*)d_in[6];
    const float* A_log  = (const float*)d_in[7];
    const float* Dp     = (const float*)d_in[8];
    const float* out_w  = (const float*)d_in[9];
    float* out = (float*)d_out;

    cudaFuncSetAttribute(k_gemm_z,   cudaFuncAttributeMaxDynamicSharedMemorySize, GEMM_SMEM);
    cudaFuncSetAttribute(k_gemm_cat, cudaFuncAttributeMaxDynamicSharedMemorySize, GEMM_SMEM);

    float *xz, *proj, *dtv;
    __nv_bfloat16 *xhi, *xlo, *inwhi, *inwlo, *xwhi, *xwlo, *dtwhi, *dtwlo, *owhi, *owlo;
    __nv_bfloat16 *xchi, *xclo, *dtrhi, *dtrlo, *yhi, *ylo;
    cudaGetSymbolAddress((void**)&xz, g_xz);
    cudaGetSymbolAddress((void**)&proj, g_proj);
    cudaGetSymbolAddress((void**)&dtv, g_dt);
    cudaGetSymbolAddress((void**)&xhi, g_x_hi);     cudaGetSymbolAddress((void**)&xlo, g_x_lo);
    cudaGetSymbolAddress((void**)&inwhi, g_inw_hi); cudaGetSymbolAddress((void**)&inwlo, g_inw_lo);
    cudaGetSymbolAddress((void**)&xwhi, g_xw_hi);   cudaGetSymbolAddress((void**)&xwlo, g_xw_lo);
    cudaGetSymbolAddress((void**)&dtwhi, g_dtw_hi); cudaGetSymbolAddress((void**)&dtwlo, g_dtw_lo);
    cudaGetSymbolAddress((void**)&owhi, g_ow_hi);   cudaGetSymbolAddress((void**)&owlo, g_ow_lo);
    cudaGetSymbolAddress((void**)&xchi, g_xc_hi);   cudaGetSymbolAddress((void**)&xclo, g_xc_lo);
    cudaGetSymbolAddress((void**)&dtrhi, g_dtr_hi); cudaGetSymbolAddress((void**)&dtrlo, g_dtr_lo);
    cudaGetSymbolAddress((void**)&yhi, g_y_hi);     cudaGetSymbolAddress((void**)&ylo, g_y_lo);

    // 0) all fp32 -> bf16 hi/lo conversions, one launch
    k_cvt_all<<<(N4_TOT + 255) / 256, 256>>>((const float4*)x, (const float4*)in_w,
                                             (const float4*)x_w, (const float4*)dt_w,
                                             (const float4*)out_w);

    // 1) in_proj: xz = x @ in_w^T  (M=8192, N=8192, K=1024)
    k_gemm_z<<<dim3(64, 64, 1), 256, GEMM_SMEM>>>(xhi, xlo, 0, inwhi, inwlo, 0,
                                                  xz, 0, DM, 8192, 8192, 0);

    // 2) depthwise conv + silu -> xc hi/lo
    k_conv<<<(unsigned)(((size_t)2 * M_ROWS * DI) / 256), 256>>>(conv_w, conv_b);

    // 3) x_proj (both dirs): proj = xc @ x_proj_w^T (N=96, K=2048); dtr fused
    k_gemm_z<<<dim3(1, 64, 2), 256, GEMM_SMEM>>>(
        xchi, xclo, (size_t)M_ROWS * DI, xwhi, xwlo, (size_t)96 * DI,
        proj, (size_t)M_ROWS * 96, DI, 96, 96, 1);

    // 4) dt_proj (both dirs): dt = dt_raw @ dt_proj_w^T (N=2048, K=64)
    k_gemm_z<<<dim3(16, 64, 2), 256, GEMM_SMEM>>>(
        dtrhi, dtrlo, (size_t)M_ROWS * DR, dtwhi, dtwlo, (size_t)DI * DR,
        dtv, (size_t)M_ROWS * DI, DR, DI, DI, 0);

    // 5) selective scan + gating -> y hi/lo
    k_scan<<<dim3(DI / 128, BSZ, 2), 128>>>(dt_bv, A_log, Dp);

    // 6) out_proj (both dirs, K-concatenated single pass)
    k_gemm_cat<<<dim3(8, 64, 1), 256, GEMM_SMEM>>>(
        yhi, ylo, yhi + (size_t)M_ROWS * DI, ylo + (size_t)M_ROWS * DI,
        owhi, owlo, owhi + (size_t)DM * DI, owlo + (size_t)DM * DI,
        out, DI, DM, DM);
}

// round 12
// speedup vs baseline: 1.9864x; 1.0037x over previous
#include <cuda_runtime.h>
#include <cuda_bf16.h>
#include <cstdint>
#include <math.h>

// Problem dims
#define L_SEQ 2048
#define BSZ   4
#define DM    1024
#define DI    2048
#define DS    16
#define DR    64
#define M_ROWS 8192   // BSZ * L_SEQ

// ============================================================================
// Scratch (static device arrays)
// ============================================================================
__device__ float g_xz  [(size_t)M_ROWS * 8192];             // in_proj output (xi|z per dir)
__device__ float g_proj[2 * (size_t)M_ROWS * 96];           // x_proj output (dt_raw|B|C)
__device__ float g_proj_part[4 * (size_t)M_ROWS * 96];      // x_proj split-K partials [dir][ks]
__device__ float g_dt  [2 * (size_t)M_ROWS * DI];           // dt_proj output (pre-softplus)

// bf16 hi/lo operand planes
__device__ __nv_bfloat16 g_x_hi  [(size_t)M_ROWS * DM],  g_x_lo  [(size_t)M_ROWS * DM];
__device__ __nv_bfloat16 g_inw_hi[(size_t)8192 * DM],    g_inw_lo[(size_t)8192 * DM];
__device__ __nv_bfloat16 g_xw_hi [2 * 96 * (size_t)DI],  g_xw_lo [2 * 96 * (size_t)DI];
__device__ __nv_bfloat16 g_dtw_hi[2 * (size_t)DI * DR],  g_dtw_lo[2 * (size_t)DI * DR];
__device__ __nv_bfloat16 g_ow_hi [2 * (size_t)DM * DI],  g_ow_lo [2 * (size_t)DM * DI];
__device__ __nv_bfloat16 g_xc_hi [2 * (size_t)M_ROWS * DI], g_xc_lo[2 * (size_t)M_ROWS * DI];
__device__ __nv_bfloat16 g_dtr_hi[2 * (size_t)M_ROWS * DR], g_dtr_lo[2 * (size_t)M_ROWS * DR];
__device__ __nv_bfloat16 g_y_hi  [2 * (size_t)M_ROWS * DI], g_y_lo [2 * (size_t)M_ROWS * DI];

__device__ __forceinline__ void split2(float v, __nv_bfloat16& h, __nv_bfloat16& l) {
    h = __float2bfloat16_rn(v);
    l = __float2bfloat16_rn(v - __bfloat162float(h));
}

// ============================================================================
// PTX helpers (sm_80-class only: valid on base sm_103 target)
// ============================================================================
__device__ __forceinline__ uint32_t smem_u32(const void* p) {
    uint32_t a;
    asm("{ .reg .u64 t; cvta.to.shared.u64 t, %1; cvt.u32.u64 %0, t; }" : "=r"(a) : "l"(p));
    return a;
}
__device__ __forceinline__ void cpa16(uint32_t dst, const void* src) {
    asm volatile("cp.async.cg.shared.global [%0], [%1], 16;" :: "r"(dst), "l"(src) : "memory");
}
__device__ __forceinline__ void cpa16p(uint32_t dst, const void* src, int sz) {
    asm volatile("cp.async.cg.shared.global [%0], [%1], 16, %2;" :: "r"(dst), "l"(src), "r"(sz) : "memory");
}
__device__ __forceinline__ void cp_commit() {
    asm volatile("cp.async.commit_group;" ::: "memory");
}
template <int N>
__device__ __forceinline__ void cp_wait() {
    asm volatile("cp.async.wait_group %0;" :: "n"(N) : "memory");
}
__device__ __forceinline__ void ldsm_x4(uint32_t* r, uint32_t addr) {
    asm volatile("ldmatrix.sync.aligned.m8n8.x4.shared.b16 {%0,%1,%2,%3}, [%4];"
                 : "=r"(r[0]), "=r"(r[1]), "=r"(r[2]), "=r"(r[3]) : "r"(addr));
}
__device__ __forceinline__ void ldsm_x2(uint32_t* r, uint32_t addr) {
    asm volatile("ldmatrix.sync.aligned.m8n8.x2.shared.b16 {%0,%1}, [%2];"
                 : "=r"(r[0]), "=r"(r[1]) : "r"(addr));
}
__device__ __forceinline__ void mma_bf16(float* d, const uint32_t* a, const uint32_t* b) {
    asm volatile("mma.sync.aligned.m16n8k16.row.col.f32.bf16.bf16.f32 "
                 "{%0,%1,%2,%3}, {%4,%5,%6,%7}, {%8,%9}, {%0,%1,%2,%3};"
                 : "+f"(d[0]), "+f"(d[1]), "+f"(d[2]), "+f"(d[3])
                 : "r"(a[0]), "r"(a[1]), "r"(a[2]), "r"(a[3]), "r"(b[0]), "r"(b[1]));
}

// ============================================================================
// GEMM machinery (R11 WINNER config): 128x128 tile, K-chunk 32 (64B rows),
// 256 threads (2x4 warps, 64x32 warp tiles), XOR-swizzled smem (no padding),
// 3-stage cp.async pipeline, ONE __syncthreads per chunk.
// Static accumulator indexing ONLY (dynamic => spills).
// bf16x3 split: acc += Ah*Bh + Ah*Bl + Al*Bh  (fp32 accumulate)
// ============================================================================
#define PLANE 8192                       // 128 rows x 64 B, no padding
#define OFF_AH 0
#define OFF_AL (PLANE)
#define OFF_BH (2 * PLANE)
#define OFF_BL (3 * PLANE)
#define STAGE  (4 * PLANE)               // 32768 B
#define NSTAGE 3
#define GEMM_SMEM (NSTAGE * STAGE)       // 98304 B (2 CTAs/SM)
#define SW64(o) ((o) ^ (((o) >> 3) & 0x30))

struct GemmCtx {
    uint32_t sb;
    int tid, lane, warp, wm, wn, bm, bn;
    uint32_t a_lane_off, b_lane_off;
};

__device__ __forceinline__ void gemm_init(GemmCtx& g, char* smem) {
    g.sb = smem_u32(smem);
    g.tid = threadIdx.x;
    g.lane = g.tid & 31;
    g.warp = g.tid >> 5;
    g.wm = g.warp >> 2;
    g.wn = g.warp & 3;
    g.bm = blockIdx.y * 128;
    g.bn = blockIdx.x * 128;
    g.a_lane_off = (uint32_t)((g.lane & 15) * 64 + (g.lane >> 4) * 16);        // bytes
    g.b_lane_off = (uint32_t)((g.lane & 7) * 64 + ((g.lane >> 3) & 1) * 16);   // bytes
}

__device__ __forceinline__ void gemm_load_chunk(
    const GemmCtx& g, int s, int k0, int K,
    const __nv_bfloat16* __restrict__ Ahi, const __nv_bfloat16* __restrict__ Alo,
    const __nv_bfloat16* __restrict__ Bhi, const __nv_bfloat16* __restrict__ Blo,
    int Nact)
{
    const uint32_t st = g.sb + s * STAGE;
#pragma unroll
    for (int it = 0; it < 2; ++it) {
        const int i   = g.tid + it * 256;
        const int row = i >> 2;
        const int c8  = (i & 3) * 8;
        const uint32_t so = SW64((uint32_t)(row * 64 + c8 * 2));
        const size_t ga = (size_t)(g.bm + row) * K + k0 + c8;
        cpa16(st + OFF_AH + so, Ahi + ga);
        cpa16(st + OFF_AL + so, Alo + ga);
        const size_t gb = (size_t)(g.bn + row) * K + k0 + c8;
        const int sz = (g.bn + row < Nact) ? 16 : 0;
        cpa16p(st + OFF_BH + so, Bhi + gb, sz);
        cpa16p(st + OFF_BL + so, Blo + gb, sz);
    }
}

__device__ __forceinline__ void gemm_compute_chunk(const GemmCtx& g, int s, float acc[4][4][4]) {
    const uint32_t st = g.sb + s * STAGE;
#pragma unroll
    for (int k16 = 0; k16 < 32; k16 += 16) {
        const uint32_t ak = g.a_lane_off + k16 * 2;
        const uint32_t bk = g.b_lane_off + k16 * 2;
        uint32_t bh[4][2], bl[4][2];
#pragma unroll
        for (int j = 0; j < 4; ++j) {
            const uint32_t bo = (uint32_t)((g.wn * 32 + j * 8) * 64) + bk;
            const uint32_t bos = SW64(bo);
            ldsm_x2(bh[j], st + OFF_BH + bos);
            ldsm_x2(bl[j], st + OFF_BL + bos);
        }
#pragma unroll
        for (int i = 0; i < 4; ++i) {
            const uint32_t ao = (uint32_t)((g.wm * 64 + i * 16) * 64) + ak;
            const uint32_t aos = SW64(ao);
            uint32_t ah[4], al[4];
            ldsm_x4(ah, st + OFF_AH + aos);
            ldsm_x4(al, st + OFF_AL + aos);
#pragma unroll
            for (int j = 0; j < 4; ++j) mma_bf16(acc[i][j], ah, bh[j]);
#pragma unroll
            for (int j = 0; j < 4; ++j) mma_bf16(acc[i][j], ah, bl[j]);
#pragma unroll
            for (int j = 0; j < 4; ++j) mma_bf16(acc[i][j], al, bh[j]);
        }
    }
}

// ============================================================================
// k_gemm_z: split-K capable. blockIdx.z = dir * nsplit + ks; kStart = ks*kLen.
// C target = C + dir*cStride + ks*partStride.
// ============================================================================
__global__ void __launch_bounds__(256, 2) k_gemm_z(
    const __nv_bfloat16* __restrict__ Ahi, const __nv_bfloat16* __restrict__ Alo, size_t aStride,
    const __nv_bfloat16* __restrict__ Bhi, const __nv_bfloat16* __restrict__ Blo, size_t bStride,
    float* __restrict__ C, size_t cStride, size_t partStride,
    int K_ld, int kLen, int nsplit, int Nact, int ldc)
{
    extern __shared__ __align__(1024) char smem[];
    GemmCtx g;
    gemm_init(g, smem);
    const int dir = blockIdx.z / nsplit;
    const int ks  = blockIdx.z % nsplit;
    const int kStart = ks * kLen;
    Ahi += (size_t)dir * aStride; Alo += (size_t)dir * aStride;
    Bhi += (size_t)dir * bStride; Blo += (size_t)dir * bStride;
    C   += (size_t)dir * cStride + (size_t)ks * partStride;
    const int nch = kLen >> 5;

    float acc[4][4][4];
#pragma unroll
    for (int i = 0; i < 4; i++)
#pragma unroll
        for (int j = 0; j < 4; j++)
#pragma unroll
            for (int k = 0; k < 4; k++) acc[i][j][k] = 0.f;

    // 3-stage prologue (always 2 committed groups)
    gemm_load_chunk(g, 0, kStart, K_ld, Ahi, Alo, Bhi, Blo, Nact);
    cp_commit();
    if (1 < nch) gemm_load_chunk(g, 1, kStart + 32, K_ld, Ahi, Alo, Bhi, Blo, Nact);
    cp_commit();

    for (int c = 0; c < nch; ++c) {
        cp_wait<1>();
        __syncthreads();
        if (c + 2 < nch)
            gemm_load_chunk(g, (c + 2) % NSTAGE, kStart + ((c + 2) << 5), K_ld, Ahi, Alo, Bhi, Blo, Nact);
        cp_commit();
        gemm_compute_chunk(g, c % NSTAGE, acc);
        // no trailing barrier (buffer next written at c+3, after c+1's barrier)
    }

    const int gid = g.lane >> 2;
    const int tig = g.lane & 3;
#pragma unroll
    for (int i = 0; i < 4; ++i) {
        const int row = g.bm + g.wm * 64 + i * 16 + gid;
#pragma unroll
        for (int j = 0; j < 4; ++j) {
            const int col = g.bn + g.wn * 32 + j * 8 + tig * 2;
            if (col < Nact) {
                *(float2*)&C[(size_t)row * ldc + col]       = make_float2(acc[i][j][0], acc[i][j][1]);
                *(float2*)&C[(size_t)(row + 8) * ldc + col] = make_float2(acc[i][j][2], acc[i][j][3]);
            }
        }
    }
}

// ============================================================================
// k_gemm_cat: out = y0 @ ow0^T + y1 @ ow1^T  (K-concatenated, single pass)
// ============================================================================
__global__ void __launch_bounds__(256, 2) k_gemm_cat(
    const __nv_bfloat16* __restrict__ A0hi, const __nv_bfloat16* __restrict__ A0lo,
    const __nv_bfloat16* __restrict__ A1hi, const __nv_bfloat16* __restrict__ A1lo,
    const __nv_bfloat16* __restrict__ B0hi, const __nv_bfloat16* __restrict__ B0lo,
    const __nv_bfloat16* __restrict__ B1hi, const __nv_bfloat16* __restrict__ B1lo,
    float* __restrict__ C, int Kh, int Nact, int ldc)
{
    extern __shared__ __align__(1024) char smem[];
    GemmCtx g;
    gemm_init(g, smem);
    const int nch_h = Kh >> 5;
    const int nch = nch_h * 2;

    float acc[4][4][4];
#pragma unroll
    for (int i = 0; i < 4; i++)
#pragma unroll
        for (int j = 0; j < 4; j++)
#pragma unroll
            for (int k = 0; k < 4; k++) acc[i][j][k] = 0.f;

    auto load = [&](int c, int s) {
        if (c < nch_h)
            gemm_load_chunk(g, s, c << 5, Kh, A0hi, A0lo, B0hi, B0lo, Nact);
        else
            gemm_load_chunk(g, s, (c - nch_h) << 5, Kh, A1hi, A1lo, B1hi, B1lo, Nact);
    };

    load(0, 0);
    cp_commit();
    if (1 < nch) load(1, 1);
    cp_commit();

    for (int c = 0; c < nch; ++c) {
        cp_wait<1>();
        __syncthreads();
        if (c + 2 < nch) load(c + 2, (c + 2) % NSTAGE);
        cp_commit();
        gemm_compute_chunk(g, c % NSTAGE, acc);
    }

    const int gid = g.lane >> 2;
    const int tig = g.lane & 3;
#pragma unroll
    for (int i = 0; i < 4; ++i) {
        const int row = g.bm + g.wm * 64 + i * 16 + gid;
#pragma unroll
        for (int j = 0; j < 4; ++j) {
            const int col = g.bn + g.wn * 32 + j * 8 + tig * 2;
            if (col < Nact) {
                *(float2*)&C[(size_t)row * ldc + col]       = make_float2(acc[i][j][0], acc[i][j][1]);
                *(float2*)&C[(size_t)(row + 8) * ldc + col] = make_float2(acc[i][j][2], acc[i][j][3]);
            }
        }
    }
}

// ============================================================================
// k_reduce_proj2: g_proj = sum of 2 split-K partials; cols<64 also -> dtr hi/lo
// ============================================================================
__global__ void k_reduce_proj2() {
    size_t idx = (size_t)blockIdx.x * blockDim.x + threadIdx.x;
    const size_t total = (size_t)2 * M_ROWS * 96;
    if (idx >= total) return;
    const int dir = (int)(idx / ((size_t)M_ROWS * 96));
    const size_t off = idx % ((size_t)M_ROWS * 96);
    const float* base = g_proj_part + (size_t)dir * 2 * M_ROWS * 96;
    float v = base[off] + base[off + (size_t)M_ROWS * 96];
    g_proj[idx] = v;
    const int col = (int)(off % 96);
    if (col < DR) {
        const size_t row = off / 96;
        __nv_bfloat16 h, l;
        split2(v, h, l);
        const size_t d = ((size_t)dir * M_ROWS + row) * DR + col;
        g_dtr_hi[d] = h;
        g_dtr_lo[d] = l;
    }
}

// ============================================================================
// fp32 -> bf16 hi/lo conversions, TWO launches (so conv lands at slot 3).
// ============================================================================
#define N4_X   2097152u   // 8192*1024/4
#define N4_INW 2097152u   // 8192*1024/4
#define N4_A   (N4_X + N4_INW)
#define N4_XW  98304u     // 2*96*2048/4
#define N4_DTW 65536u     // 2*2048*64/4
#define N4_OW  1048576u   // 2*1024*2048/4
#define N4_B   (N4_XW + N4_DTW + N4_OW)

__global__ void k_cvt_a(const float4* __restrict__ x, const float4* __restrict__ inw) {
    uint32_t i = blockIdx.x * blockDim.x + threadIdx.x;
    if (i >= N4_A) return;
    const float4* src;
    __nv_bfloat16 *hi, *lo;
    uint32_t off = i;
    if (i < N4_X) { src = x;   hi = g_x_hi;   lo = g_x_lo; }
    else { off -= N4_X; src = inw; hi = g_inw_hi; lo = g_inw_lo; }
    float4 v = src[off];
    __nv_bfloat16 h0, h1, h2, h3, l0, l1, l2, l3;
    split2(v.x, h0, l0); split2(v.y, h1, l1); split2(v.z, h2, l2); split2(v.w, h3, l3);
    __nv_bfloat162* H = (__nv_bfloat162*)hi;
    __nv_bfloat162* L = (__nv_bfloat162*)lo;
    H[2 * (size_t)off]     = __nv_bfloat162(h0, h1);
    H[2 * (size_t)off + 1] = __nv_bfloat162(h2, h3);
    L[2 * (size_t)off]     = __nv_bfloat162(l0, l1);
    L[2 * (size_t)off + 1] = __nv_bfloat162(l2, l3);
}

__global__ void k_cvt_b(const float4* __restrict__ xw, const float4* __restrict__ dtw,
                        const float4* __restrict__ ow) {
    uint32_t i = blockIdx.x * blockDim.x + threadIdx.x;
    if (i >= N4_B) return;
    const float4* src;
    __nv_bfloat16 *hi, *lo;
    uint32_t off = i;
    if (i < N4_XW)                      { src = xw;  hi = g_xw_hi;  lo = g_xw_lo; }
    else if ((off -= N4_XW) < N4_DTW)   { src = dtw; hi = g_dtw_hi; lo = g_dtw_lo; }
    else { off -= N4_DTW;                 src = ow;  hi = g_ow_hi;  lo = g_ow_lo; }
    float4 v = src[off];
    __nv_bfloat16 h0, h1, h2, h3, l0, l1, l2, l3;
    split2(v.x, h0, l0); split2(v.y, h1, l1); split2(v.z, h2, l2); split2(v.w, h3, l3);
    __nv_bfloat162* H = (__nv_bfloat162*)hi;
    __nv_bfloat162* L = (__nv_bfloat162*)lo;
    H[2 * (size_t)off]     = __nv_bfloat162(h0, h1);
    H[2 * (size_t)off + 1] = __nv_bfloat162(h2, h3);
    L[2 * (size_t)off]     = __nv_bfloat162(l0, l1);
    L[2 * (size_t)off + 1] = __nv_bfloat162(l2, l3);
}

// ============================================================================
// Depthwise conv (causal fwd / anti-causal bwd) + SiLU -> xc hi/lo planes
// (R5/R11 elementwise version: 4 taps/thread, L2-served reuse)  [PROFILED SLOT]
// ============================================================================
__global__ void k_conv(const float* __restrict__ cw, const float* __restrict__ cb) {
    size_t idx = (size_t)blockIdx.x * blockDim.x + threadIdx.x;
    if (idx >= (size_t)2 * M_ROWS * DI) return;
    int e = (int)(idx % DI);
    size_t r = idx / DI;
    int m = (int)(r % M_ROWS);
    int dir = (int)(r / M_ROWS);
    int l = m % L_SEQ;
    int b = m / L_SEQ;

    float acc = cb[dir * DI + e];
    const float* w4 = cw + ((size_t)dir * DI + e) * 4;
#pragma unroll
    for (int k = 0; k < 4; k++) {
        int tl = (dir == 0) ? (l - 3 + k) : (l + 3 - k);
        if (tl >= 0 && tl < L_SEQ)
            acc = fmaf(w4[k], g_xz[((size_t)(b * L_SEQ + tl)) * 8192 + dir * 4096 + e], acc);
    }
    float xc = acc / (1.f + __expf(-acc));   // silu
    __nv_bfloat16 h, lo;
    split2(xc, h, lo);
    size_t o = ((size_t)dir * M_ROWS + m) * DI + e;
    g_xc_hi[o] = h;
    g_xc_lo[o] = lo;
}

// ============================================================================
// Selective scan (R5 v1): 128-thread blocks, 4-deep register-ring prefetch.
// Fuses softplus, recurrence, D-skip, silu(z) gating. Writes y hi/lo planes.
// ============================================================================
__global__ void __launch_bounds__(128) k_scan(const float* __restrict__ dt_b,
                                              const float* __restrict__ A_log,
                                              const float* __restrict__ Dp) {
    const int tid  = threadIdx.x;
    const int lane = tid & 31;
    const int warp = tid >> 5;
    const int dir  = blockIdx.z;
    const int b    = blockIdx.y;
    const int e    = blockIdx.x * 128 + tid;

    __shared__ float sB[4][16], sC[4][16];

    float a[16];
#pragma unroll
    for (int s = 0; s < 16; s++)
        a[s] = -__expf(A_log[((size_t)dir * DI + e) * 16 + s]);

    const float bias  = dt_b[dir * DI + e];
    const float dcoef = Dp[dir * DI + e];

    float h[16];
#pragma unroll
    for (int s = 0; s < 16; s++) h[s] = 0.f;

    const size_t base_de   = (size_t)dir * M_ROWS * DI;
    const size_t proj_base = (size_t)dir * M_ROWS * 96;
    const size_t brow      = (size_t)b * L_SEQ;

    float rbc[4], rdt[4], rxh[4], rxl[4], rz[4];
#pragma unroll
    for (int p = 0; p < 4; p++) {
        const int tt = dir ? (L_SEQ - 1 - p) : p;
        const size_t m = brow + tt;
        rbc[p] = g_proj[proj_base + m * 96 + 64 + lane];
        rdt[p] = g_dt[base_de + m * DI + e];
        rxh[p] = __bfloat162float(g_xc_hi[base_de + m * DI + e]);
        rxl[p] = __bfloat162float(g_xc_lo[base_de + m * DI + e]);
        rz[p]  = g_xz[m * 8192 + dir * 4096 + 2048 + e];
    }

    for (int t0 = 0; t0 < L_SEQ; t0 += 4) {
#pragma unroll
        for (int u = 0; u < 4; u++) {
            const int t  = t0 + u;
            const int tt = dir ? (L_SEQ - 1 - t) : t;
            const size_t m = brow + tt;

            const float bc = rbc[u], dtv = rdt[u], xh = rxh[u], xl = rxl[u], zz = rz[u];

            const int tp = t + 4;
            if (tp < L_SEQ) {
                const int tq = dir ? (L_SEQ - 1 - tp) : tp;
                const size_t mp = brow + tq;
                rbc[u] = g_proj[proj_base + mp * 96 + 64 + lane];
                rdt[u] = g_dt[base_de + mp * DI + e];
                rxh[u] = __bfloat162float(g_xc_hi[base_de + mp * DI + e]);
                rxl[u] = __bfloat162float(g_xc_lo[base_de + mp * DI + e]);
                rz[u]  = g_xz[mp * 8192 + dir * 4096 + 2048 + e];
            }

            if (lane < 16) sB[warp][lane] = bc; else sC[warp][lane - 16] = bc;
            __syncwarp();

            const float v   = dtv + bias;
            const float dt  = (v > 15.f) ? v : log1pf(__expf(v));
            const float x   = xh + xl;
            const float dtx = dt * x;

            float y = 0.f;
#pragma unroll
            for (int s = 0; s < 16; s++) {
                float dA = __expf(dt * a[s]);
                h[s] = fmaf(h[s], dA, dtx * sB[warp][s]);
                y    = fmaf(h[s], sC[warp][s], y);
            }
            const float yv  = fmaf(x, dcoef, y);
            const float sz  = zz / (1.f + __expf(-zz));
            const float out = yv * sz;
            __nv_bfloat16 hh, ll;
            split2(out, hh, ll);
            const size_t o = base_de + m * DI + e;
            g_y_hi[o] = hh;
            g_y_lo[o] = ll;
            __syncwarp();
        }
    }
}

// ============================================================================
extern "C" void kernel_launch(void* const* d_in, const int* in_sizes, int n_in,
                              void* d_out, int out_size) {
    const float* x      = (const float*)d_in[0];
    const float* in_w   = (const float*)d_in[1];
    const float* conv_w = (const float*)d_in[2];
    const float* conv_b = (const float*)d_in[3];
    const float* x_w    = (const float*)d_in[4];
    const float* dt_w   = (const float*)d_in[5];
    const float* dt_bv  = (const float*)d_in[6];
    const float* A_log  = (const float*)d_in[7];
    const float* Dp     = (const float*)d_in[8];
    const float* out_w  = (const float*)d_in[9];
    float* out = (float*)d_out;

    cudaFuncSetAttribute(k_gemm_z,   cudaFuncAttributeMaxDynamicSharedMemorySize, GEMM_SMEM);
    cudaFuncSetAttribute(k_gemm_cat, cudaFuncAttributeMaxDynamicSharedMemorySize, GEMM_SMEM);

    float *xz, *projpart, *dtv;
    __nv_bfloat16 *xhi, *xlo, *inwhi, *inwlo, *xwhi, *xwlo, *dtwhi, *dtwlo, *owhi, *owlo;
    __nv_bfloat16 *xchi, *xclo, *dtrhi, *dtrlo, *yhi, *ylo;
    cudaGetSymbolAddress((void**)&xz, g_xz);
    cudaGetSymbolAddress((void**)&projpart, g_proj_part);
    cudaGetSymbolAddress((void**)&dtv, g_dt);
    cudaGetSymbolAddress((void**)&xhi, g_x_hi);     cudaGetSymbolAddress((void**)&xlo, g_x_lo);
    cudaGetSymbolAddress((void**)&inwhi, g_inw_hi); cudaGetSymbolAddress((void**)&inwlo, g_inw_lo);
    cudaGetSymbolAddress((void**)&xwhi, g_xw_hi);   cudaGetSymbolAddress((void**)&xwlo, g_xw_lo);
    cudaGetSymbolAddress((void**)&dtwhi, g_dtw_hi); cudaGetSymbolAddress((void**)&dtwlo, g_dtw_lo);
    cudaGetSymbolAddress((void**)&owhi, g_ow_hi);   cudaGetSymbolAddress((void**)&owlo, g_ow_lo);
    cudaGetSymbolAddress((void**)&xchi, g_xc_hi);   cudaGetSymbolAddress((void**)&xclo, g_xc_lo);
    cudaGetSymbolAddress((void**)&dtrhi, g_dtr_hi); cudaGetSymbolAddress((void**)&dtrlo, g_dtr_lo);
    cudaGetSymbolAddress((void**)&yhi, g_y_hi);     cudaGetSymbolAddress((void**)&ylo, g_y_lo);

    // 0-1) conversions (2 launches -> conv sits at profiled slot 3)
    k_cvt_a<<<(N4_A + 255) / 256, 256>>>((const float4*)x, (const float4*)in_w);
    k_cvt_b<<<(N4_B + 255) / 256, 256>>>((const float4*)x_w, (const float4*)dt_w,
                                         (const float4*)out_w);

    // 2) in_proj: xz = x @ in_w^T  (M=8192, N=8192, K=1024)
    k_gemm_z<<<dim3(64, 64, 1), 256, GEMM_SMEM>>>(
        xhi, xlo, 0, inwhi, inwlo, 0,
        xz, 0, 0, DM, DM, 1, 8192, 8192);

    // 3) depthwise conv + silu -> xc hi/lo  [PROFILED SLOT]
    k_conv<<<(unsigned)(((size_t)2 * M_ROWS * DI) / 256), 256>>>(conv_w, conv_b);

    // 4) x_proj (both dirs, split-K x2): partials = xc @ x_proj_w^T
    k_gemm_z<<<dim3(1, 64, 4), 256, GEMM_SMEM>>>(
        xchi, xclo, (size_t)M_ROWS * DI, xwhi, xwlo, (size_t)96 * DI,
        projpart, (size_t)2 * M_ROWS * 96, (size_t)M_ROWS * 96,
        DI, DI / 2, 2, 96, 96);

    // 5) reduce 2 partials -> g_proj, and bf16-split dt_raw -> g_dtr
    k_reduce_proj2<<<(unsigned)(((size_t)2 * M_ROWS * 96 + 255) / 256), 256>>>();

    // 6) dt_proj (both dirs): dt = dt_raw @ dt_proj_w^T (N=2048, K=64)
    k_gemm_z<<<dim3(16, 64, 2), 256, GEMM_SMEM>>>(
        dtrhi, dtrlo, (size_t)M_ROWS * DR, dtwhi, dtwlo, (size_t)DI * DR,
        dtv, (size_t)M_ROWS * DI, 0, DR, DR, 1, DI, DI);

    // 7) selective scan + gating -> y hi/lo
    k_scan<<<dim3(DI / 128, BSZ, 2), 128>>>(dt_bv, A_log, Dp);

    // 8) out_proj (both dirs, K-concatenated single pass)
    k_gemm_cat<<<dim3(8, 64, 1), 256, GEMM_SMEM>>>(
        yhi, ylo, yhi + (size_t)M_ROWS * DI, ylo + (size_t)M_ROWS * DI,
        owhi, owlo, owhi + (size_t)DM * DI, owlo + (size_t)DM * DI,
        out, DI, DM, DM);
}

// round 13
// speedup vs baseline: 2.0010x; 1.0073x over previous
#include <cuda_runtime.h>
#include <cuda_bf16.h>
#include <cstdint>
#include <math.h>

// Problem dims
#define L_SEQ 2048
#define BSZ   4
#define DM    1024
#define DI    2048
#define DS    16
#define DR    64
#define M_ROWS 8192   // BSZ * L_SEQ

// ============================================================================
// Scratch (static device arrays)
// ============================================================================
__device__ float g_xz  [(size_t)M_ROWS * 8192];             // in_proj output (xi|z per dir)
__device__ float g_proj[2 * (size_t)M_ROWS * 96];           // x_proj output (dt_raw|B|C)
__device__ float g_proj_part[4 * (size_t)M_ROWS * 96];      // x_proj split-K partials [dir][ks]
__device__ float g_dt  [2 * (size_t)M_ROWS * DI];           // dt_proj output (pre-softplus)

// bf16 hi/lo operand planes
__device__ __nv_bfloat16 g_x_hi  [(size_t)M_ROWS * DM],  g_x_lo  [(size_t)M_ROWS * DM];
__device__ __nv_bfloat16 g_inw_hi[(size_t)8192 * DM],    g_inw_lo[(size_t)8192 * DM];
__device__ __nv_bfloat16 g_xw_hi [2 * 96 * (size_t)DI],  g_xw_lo [2 * 96 * (size_t)DI];
__device__ __nv_bfloat16 g_dtw_hi[2 * (size_t)DI * DR],  g_dtw_lo[2 * (size_t)DI * DR];
__device__ __nv_bfloat16 g_ow_hi [2 * (size_t)DM * DI],  g_ow_lo [2 * (size_t)DM * DI];
__device__ __nv_bfloat16 g_xc_hi [2 * (size_t)M_ROWS * DI], g_xc_lo[2 * (size_t)M_ROWS * DI];
__device__ __nv_bfloat16 g_dtr_hi[2 * (size_t)M_ROWS * DR], g_dtr_lo[2 * (size_t)M_ROWS * DR];
__device__ __nv_bfloat16 g_y_hi  [2 * (size_t)M_ROWS * DI], g_y_lo [2 * (size_t)M_ROWS * DI];

__device__ __forceinline__ void split2(float v, __nv_bfloat16& h, __nv_bfloat16& l) {
    h = __float2bfloat16_rn(v);
    l = __float2bfloat16_rn(v - __bfloat162float(h));
}

// ============================================================================
// PTX helpers (sm_80-class only: valid on base sm_103 target)
// ============================================================================
__device__ __forceinline__ uint32_t smem_u32(const void* p) {
    uint32_t a;
    asm("{ .reg .u64 t; cvta.to.shared.u64 t, %1; cvt.u32.u64 %0, t; }" : "=r"(a) : "l"(p));
    return a;
}
__device__ __forceinline__ void cpa16(uint32_t dst, const void* src) {
    asm volatile("cp.async.cg.shared.global [%0], [%1], 16;" :: "r"(dst), "l"(src) : "memory");
}
__device__ __forceinline__ void cpa16p(uint32_t dst, const void* src, int sz) {
    asm volatile("cp.async.cg.shared.global [%0], [%1], 16, %2;" :: "r"(dst), "l"(src), "r"(sz) : "memory");
}
__device__ __forceinline__ void cp_commit() {
    asm volatile("cp.async.commit_group;" ::: "memory");
}
template <int N>
__device__ __forceinline__ void cp_wait() {
    asm volatile("cp.async.wait_group %0;" :: "n"(N) : "memory");
}
__device__ __forceinline__ void ldsm_x4(uint32_t* r, uint32_t addr) {
    asm volatile("ldmatrix.sync.aligned.m8n8.x4.shared.b16 {%0,%1,%2,%3}, [%4];"
                 : "=r"(r[0]), "=r"(r[1]), "=r"(r[2]), "=r"(r[3]) : "r"(addr));
}
__device__ __forceinline__ void ldsm_x2(uint32_t* r, uint32_t addr) {
    asm volatile("ldmatrix.sync.aligned.m8n8.x2.shared.b16 {%0,%1}, [%2];"
                 : "=r"(r[0]), "=r"(r[1]) : "r"(addr));
}
__device__ __forceinline__ void mma_bf16(float* d, const uint32_t* a, const uint32_t* b) {
    asm volatile("mma.sync.aligned.m16n8k16.row.col.f32.bf16.bf16.f32 "
                 "{%0,%1,%2,%3}, {%4,%5,%6,%7}, {%8,%9}, {%0,%1,%2,%3};"
                 : "+f"(d[0]), "+f"(d[1]), "+f"(d[2]), "+f"(d[3])
                 : "r"(a[0]), "r"(a[1]), "r"(a[2]), "r"(a[3]), "r"(b[0]), "r"(b[1]));
}

// ============================================================================
// GEMM machinery (R11 WINNER config): 128x128 tile, K-chunk 32 (64B rows),
// 256 threads (2x4 warps, 64x32 warp tiles), XOR-swizzled smem (no padding),
// 3-stage cp.async pipeline, ONE __syncthreads per chunk.
// Static accumulator indexing ONLY (dynamic => spills).
// bf16x3 split: acc += Ah*Bh + Ah*Bl + Al*Bh  (fp32 accumulate)
// ============================================================================
#define PLANE 8192                       // 128 rows x 64 B, no padding
#define OFF_AH 0
#define OFF_AL (PLANE)
#define OFF_BH (2 * PLANE)
#define OFF_BL (3 * PLANE)
#define STAGE  (4 * PLANE)               // 32768 B
#define NSTAGE 3
#define GEMM_SMEM (NSTAGE * STAGE)       // 98304 B (2 CTAs/SM)
#define SW64(o) ((o) ^ (((o) >> 3) & 0x30))

struct GemmCtx {
    uint32_t sb;
    int tid, lane, warp, wm, wn, bm, bn;
    uint32_t a_lane_off, b_lane_off;
};

__device__ __forceinline__ void gemm_init(GemmCtx& g, char* smem) {
    g.sb = smem_u32(smem);
    g.tid = threadIdx.x;
    g.lane = g.tid & 31;
    g.warp = g.tid >> 5;
    g.wm = g.warp >> 2;
    g.wn = g.warp & 3;
    g.bm = blockIdx.y * 128;
    g.bn = blockIdx.x * 128;
    g.a_lane_off = (uint32_t)((g.lane & 15) * 64 + (g.lane >> 4) * 16);        // bytes
    g.b_lane_off = (uint32_t)((g.lane & 7) * 64 + ((g.lane >> 3) & 1) * 16);   // bytes
}

__device__ __forceinline__ void gemm_load_chunk(
    const GemmCtx& g, int s, int k0, int K,
    const __nv_bfloat16* __restrict__ Ahi, const __nv_bfloat16* __restrict__ Alo,
    const __nv_bfloat16* __restrict__ Bhi, const __nv_bfloat16* __restrict__ Blo,
    int Nact)
{
    const uint32_t st = g.sb + s * STAGE;
#pragma unroll
    for (int it = 0; it < 2; ++it) {
        const int i   = g.tid + it * 256;
        const int row = i >> 2;
        const int c8  = (i & 3) * 8;
        const uint32_t so = SW64((uint32_t)(row * 64 + c8 * 2));
        const size_t ga = (size_t)(g.bm + row) * K + k0 + c8;
        cpa16(st + OFF_AH + so, Ahi + ga);
        cpa16(st + OFF_AL + so, Alo + ga);
        const size_t gb = (size_t)(g.bn + row) * K + k0 + c8;
        const int sz = (g.bn + row < Nact) ? 16 : 0;
        cpa16p(st + OFF_BH + so, Bhi + gb, sz);
        cpa16p(st + OFF_BL + so, Blo + gb, sz);
    }
}

__device__ __forceinline__ void gemm_compute_chunk(const GemmCtx& g, int s, float acc[4][4][4]) {
    const uint32_t st = g.sb + s * STAGE;
#pragma unroll
    for (int k16 = 0; k16 < 32; k16 += 16) {
        const uint32_t ak = g.a_lane_off + k16 * 2;
        const uint32_t bk = g.b_lane_off + k16 * 2;
        uint32_t bh[4][2], bl[4][2];
#pragma unroll
        for (int j = 0; j < 4; ++j) {
            const uint32_t bo = (uint32_t)((g.wn * 32 + j * 8) * 64) + bk;
            const uint32_t bos = SW64(bo);
            ldsm_x2(bh[j], st + OFF_BH + bos);
            ldsm_x2(bl[j], st + OFF_BL + bos);
        }
#pragma unroll
        for (int i = 0; i < 4; ++i) {
            const uint32_t ao = (uint32_t)((g.wm * 64 + i * 16) * 64) + ak;
            const uint32_t aos = SW64(ao);
            uint32_t ah[4], al[4];
            ldsm_x4(ah, st + OFF_AH + aos);
            ldsm_x4(al, st + OFF_AL + aos);
#pragma unroll
            for (int j = 0; j < 4; ++j) mma_bf16(acc[i][j], ah, bh[j]);
#pragma unroll
            for (int j = 0; j < 4; ++j) mma_bf16(acc[i][j], ah, bl[j]);
#pragma unroll
            for (int j = 0; j < 4; ++j) mma_bf16(acc[i][j], al, bh[j]);
        }
    }
}

// ============================================================================
// k_gemm_z: split-K capable. blockIdx.z = dir * nsplit + ks; kStart = ks*kLen.
// C target = C + dir*cStride + ks*partStride.
// ============================================================================
__global__ void __launch_bounds__(256, 2) k_gemm_z(
    const __nv_bfloat16* __restrict__ Ahi, const __nv_bfloat16* __restrict__ Alo, size_t aStride,
    const __nv_bfloat16* __restrict__ Bhi, const __nv_bfloat16* __restrict__ Blo, size_t bStride,
    float* __restrict__ C, size_t cStride, size_t partStride,
    int K_ld, int kLen, int nsplit, int Nact, int ldc)
{
    extern __shared__ __align__(1024) char smem[];
    GemmCtx g;
    gemm_init(g, smem);
    const int dir = blockIdx.z / nsplit;
    const int ks  = blockIdx.z % nsplit;
    const int kStart = ks * kLen;
    Ahi += (size_t)dir * aStride; Alo += (size_t)dir * aStride;
    Bhi += (size_t)dir * bStride; Blo += (size_t)dir * bStride;
    C   += (size_t)dir * cStride + (size_t)ks * partStride;
    const int nch = kLen >> 5;

    float acc[4][4][4];
#pragma unroll
    for (int i = 0; i < 4; i++)
#pragma unroll
        for (int j = 0; j < 4; j++)
#pragma unroll
            for (int k = 0; k < 4; k++) acc[i][j][k] = 0.f;

    gemm_load_chunk(g, 0, kStart, K_ld, Ahi, Alo, Bhi, Blo, Nact);
    cp_commit();
    if (1 < nch) gemm_load_chunk(g, 1, kStart + 32, K_ld, Ahi, Alo, Bhi, Blo, Nact);
    cp_commit();

    for (int c = 0; c < nch; ++c) {
        cp_wait<1>();
        __syncthreads();
        if (c + 2 < nch)
            gemm_load_chunk(g, (c + 2) % NSTAGE, kStart + ((c + 2) << 5), K_ld, Ahi, Alo, Bhi, Blo, Nact);
        cp_commit();
        gemm_compute_chunk(g, c % NSTAGE, acc);
    }

    const int gid = g.lane >> 2;
    const int tig = g.lane & 3;
#pragma unroll
    for (int i = 0; i < 4; ++i) {
        const int row = g.bm + g.wm * 64 + i * 16 + gid;
#pragma unroll
        for (int j = 0; j < 4; ++j) {
            const int col = g.bn + g.wn * 32 + j * 8 + tig * 2;
            if (col < Nact) {
                *(float2*)&C[(size_t)row * ldc + col]       = make_float2(acc[i][j][0], acc[i][j][1]);
                *(float2*)&C[(size_t)(row + 8) * ldc + col] = make_float2(acc[i][j][2], acc[i][j][3]);
            }
        }
    }
}

// ============================================================================
// k_gemm_cat: out = y0 @ ow0^T + y1 @ ow1^T  (K-concatenated, single pass)
// ============================================================================
__global__ void __launch_bounds__(256, 2) k_gemm_cat(
    const __nv_bfloat16* __restrict__ A0hi, const __nv_bfloat16* __restrict__ A0lo,
    const __nv_bfloat16* __restrict__ A1hi, const __nv_bfloat16* __restrict__ A1lo,
    const __nv_bfloat16* __restrict__ B0hi, const __nv_bfloat16* __restrict__ B0lo,
    const __nv_bfloat16* __restrict__ B1hi, const __nv_bfloat16* __restrict__ B1lo,
    float* __restrict__ C, int Kh, int Nact, int ldc)
{
    extern __shared__ __align__(1024) char smem[];
    GemmCtx g;
    gemm_init(g, smem);
    const int nch_h = Kh >> 5;
    const int nch = nch_h * 2;

    float acc[4][4][4];
#pragma unroll
    for (int i = 0; i < 4; i++)
#pragma unroll
        for (int j = 0; j < 4; j++)
#pragma unroll
            for (int k = 0; k < 4; k++) acc[i][j][k] = 0.f;

    auto load = [&](int c, int s) {
        if (c < nch_h)
            gemm_load_chunk(g, s, c << 5, Kh, A0hi, A0lo, B0hi, B0lo, Nact);
        else
            gemm_load_chunk(g, s, (c - nch_h) << 5, Kh, A1hi, A1lo, B1hi, B1lo, Nact);
    };

    load(0, 0);
    cp_commit();
    if (1 < nch) load(1, 1);
    cp_commit();

    for (int c = 0; c < nch; ++c) {
        cp_wait<1>();
        __syncthreads();
        if (c + 2 < nch) load(c + 2, (c + 2) % NSTAGE);
        cp_commit();
        gemm_compute_chunk(g, c % NSTAGE, acc);
    }

    const int gid = g.lane >> 2;
    const int tig = g.lane & 3;
#pragma unroll
    for (int i = 0; i < 4; ++i) {
        const int row = g.bm + g.wm * 64 + i * 16 + gid;
#pragma unroll
        for (int j = 0; j < 4; ++j) {
            const int col = g.bn + g.wn * 32 + j * 8 + tig * 2;
            if (col < Nact) {
                *(float2*)&C[(size_t)row * ldc + col]       = make_float2(acc[i][j][0], acc[i][j][1]);
                *(float2*)&C[(size_t)(row + 8) * ldc + col] = make_float2(acc[i][j][2], acc[i][j][3]);
            }
        }
    }
}

// ============================================================================
// k_reduce_proj2: g_proj = sum of 2 split-K partials; cols<64 also -> dtr hi/lo
// ============================================================================
__global__ void k_reduce_proj2() {
    size_t idx = (size_t)blockIdx.x * blockDim.x + threadIdx.x;
    const size_t total = (size_t)2 * M_ROWS * 96;
    if (idx >= total) return;
    const int dir = (int)(idx / ((size_t)M_ROWS * 96));
    const size_t off = idx % ((size_t)M_ROWS * 96);
    const float* base = g_proj_part + (size_t)dir * 2 * M_ROWS * 96;
    float v = base[off] + base[off + (size_t)M_ROWS * 96];
    g_proj[idx] = v;
    const int col = (int)(off % 96);
    if (col < DR) {
        const size_t row = off / 96;
        __nv_bfloat16 h, l;
        split2(v, h, l);
        const size_t d = ((size_t)dir * M_ROWS + row) * DR + col;
        g_dtr_hi[d] = h;
        g_dtr_lo[d] = l;
    }
}

// ============================================================================
// fp32 -> bf16 hi/lo conversions, TWO launches (so conv lands at slot 3).
// ============================================================================
#define N4_X   2097152u   // 8192*1024/4
#define N4_INW 2097152u   // 8192*1024/4
#define N4_A   (N4_X + N4_INW)
#define N4_XW  98304u     // 2*96*2048/4
#define N4_DTW 65536u     // 2*2048*64/4
#define N4_OW  1048576u   // 2*1024*2048/4
#define N4_B   (N4_XW + N4_DTW + N4_OW)

__global__ void k_cvt_a(const float4* __restrict__ x, const float4* __restrict__ inw) {
    uint32_t i = blockIdx.x * blockDim.x + threadIdx.x;
    if (i >= N4_A) return;
    const float4* src;
    __nv_bfloat16 *hi, *lo;
    uint32_t off = i;
    if (i < N4_X) { src = x;   hi = g_x_hi;   lo = g_x_lo; }
    else { off -= N4_X; src = inw; hi = g_inw_hi; lo = g_inw_lo; }
    float4 v = src[off];
    __nv_bfloat16 h0, h1, h2, h3, l0, l1, l2, l3;
    split2(v.x, h0, l0); split2(v.y, h1, l1); split2(v.z, h2, l2); split2(v.w, h3, l3);
    __nv_bfloat162* H = (__nv_bfloat162*)hi;
    __nv_bfloat162* L = (__nv_bfloat162*)lo;
    H[2 * (size_t)off]     = __nv_bfloat162(h0, h1);
    H[2 * (size_t)off + 1] = __nv_bfloat162(h2, h3);
    L[2 * (size_t)off]     = __nv_bfloat162(l0, l1);
    L[2 * (size_t)off + 1] = __nv_bfloat162(l2, l3);
}

__global__ void k_cvt_b(const float4* __restrict__ xw, const float4* __restrict__ dtw,
                        const float4* __restrict__ ow) {
    uint32_t i = blockIdx.x * blockDim.x + threadIdx.x;
    if (i >= N4_B) return;
    const float4* src;
    __nv_bfloat16 *hi, *lo;
    uint32_t off = i;
    if (i < N4_XW)                      { src = xw;  hi = g_xw_hi;  lo = g_xw_lo; }
    else if ((off -= N4_XW) < N4_DTW)   { src = dtw; hi = g_dtw_hi; lo = g_dtw_lo; }
    else { off -= N4_DTW;                 src = ow;  hi = g_ow_hi;  lo = g_ow_lo; }
    float4 v = src[off];
    __nv_bfloat16 h0, h1, h2, h3, l0, l1, l2, l3;
    split2(v.x, h0, l0); split2(v.y, h1, l1); split2(v.z, h2, l2); split2(v.w, h3, l3);
    __nv_bfloat162* H = (__nv_bfloat162*)hi;
    __nv_bfloat162* L = (__nv_bfloat162*)lo;
    H[2 * (size_t)off]     = __nv_bfloat162(h0, h1);
    H[2 * (size_t)off + 1] = __nv_bfloat162(h2, h3);
    L[2 * (size_t)off]     = __nv_bfloat162(l0, l1);
    L[2 * (size_t)off + 1] = __nv_bfloat162(l2, l3);
}

// ============================================================================
// Depthwise conv + SiLU, x4 channel-vectorized (one thread = 4 consecutive e).
// Index math amortized 4x; taps are float4 loads; outputs packed 8B stores.
// dir0 causal: taps xi[l-3+k]; dir1 anti-causal: taps xi[l+3-k].  [PROFILED]
// ============================================================================
__global__ void __launch_bounds__(256) k_conv(const float* __restrict__ cw,
                                              const float* __restrict__ cb) {
    const size_t idx = (size_t)blockIdx.x * 256 + threadIdx.x;  // 8.4M threads
    if (idx >= (size_t)2 * M_ROWS * (DI / 4)) return;
    const int e   = (int)(idx % (DI / 4)) * 4;
    const size_t r = idx / (DI / 4);
    const int m   = (int)(r % M_ROWS);
    const int dir = (int)(r / M_ROWS);
    const int l   = m & (L_SEQ - 1);
    const int b   = m >> 11;

    // per-channel weights: cw[dir][e+c][k], 4 contiguous floats per channel
    const float4* wv = (const float4*)(cw + ((size_t)dir * DI + e) * 4);
    const float4 w0 = wv[0], w1 = wv[1], w2 = wv[2], w3 = wv[3];
    const float4 bias = *(const float4*)(cb + dir * DI + e);

    const size_t xibase = (size_t)(b * L_SEQ) * 8192 + (size_t)dir * 4096 + e;
    float4 acc = bias;
#pragma unroll
    for (int k = 0; k < 4; k++) {
        const int tl = (dir == 0) ? (l - 3 + k) : (l + 3 - k);
        if (tl >= 0 && tl < L_SEQ) {
            const float4 xi = *(const float4*)(g_xz + xibase + (size_t)tl * 8192);
            const float wk0 = (k == 0) ? w0.x : (k == 1) ? w0.y : (k == 2) ? w0.z : w0.w;
            const float wk1 = (k == 0) ? w1.x : (k == 1) ? w1.y : (k == 2) ? w1.z : w1.w;
            const float wk2 = (k == 0) ? w2.x : (k == 1) ? w2.y : (k == 2) ? w2.z : w2.w;
            const float wk3 = (k == 0) ? w3.x : (k == 1) ? w3.y : (k == 2) ? w3.z : w3.w;
            acc.x = fmaf(wk0, xi.x, acc.x);
            acc.y = fmaf(wk1, xi.y, acc.y);
            acc.z = fmaf(wk2, xi.z, acc.z);
            acc.w = fmaf(wk3, xi.w, acc.w);
        }
    }

    const float xc0 = acc.x / (1.f + __expf(-acc.x));
    const float xc1 = acc.y / (1.f + __expf(-acc.y));
    const float xc2 = acc.z / (1.f + __expf(-acc.z));
    const float xc3 = acc.w / (1.f + __expf(-acc.w));

    __nv_bfloat16 h0, h1, h2, h3, l0, l1, l2, l3;
    split2(xc0, h0, l0); split2(xc1, h1, l1); split2(xc2, h2, l2); split2(xc3, h3, l3);

    const size_t o = ((size_t)dir * M_ROWS + m) * DI + e;
    __nv_bfloat162 hp0(h0, h1), hp1(h2, h3), lp0(l0, l1), lp1(l2, l3);
    *(uint2*)(g_xc_hi + o) = make_uint2(*(uint32_t*)&hp0, *(uint32_t*)&hp1);
    *(uint2*)(g_xc_lo + o) = make_uint2(*(uint32_t*)&lp0, *(uint32_t*)&lp1);
}

// ============================================================================
// Selective scan (R5 v1): 128-thread blocks, 4-deep register-ring prefetch.
// Fuses softplus, recurrence, D-skip, silu(z) gating. Writes y hi/lo planes.
// ============================================================================
__global__ void __launch_bounds__(128) k_scan(const float* __restrict__ dt_b,
                                              const float* __restrict__ A_log,
                                              const float* __restrict__ Dp) {
    const int tid  = threadIdx.x;
    const int lane = tid & 31;
    const int warp = tid >> 5;
    const int dir  = blockIdx.z;
    const int b    = blockIdx.y;
    const int e    = blockIdx.x * 128 + tid;

    __shared__ float sB[4][16], sC[4][16];

    float a[16];
#pragma unroll
    for (int s = 0; s < 16; s++)
        a[s] = -__expf(A_log[((size_t)dir * DI + e) * 16 + s]);

    const float bias  = dt_b[dir * DI + e];
    const float dcoef = Dp[dir * DI + e];

    float h[16];
#pragma unroll
    for (int s = 0; s < 16; s++) h[s] = 0.f;

    const size_t base_de   = (size_t)dir * M_ROWS * DI;
    const size_t proj_base = (size_t)dir * M_ROWS * 96;
    const size_t brow      = (size_t)b * L_SEQ;

    float rbc[4], rdt[4], rxh[4], rxl[4], rz[4];
#pragma unroll
    for (int p = 0; p < 4; p++) {
        const int tt = dir ? (L_SEQ - 1 - p) : p;
        const size_t m = brow + tt;
        rbc[p] = g_proj[proj_base + m * 96 + 64 + lane];
        rdt[p] = g_dt[base_de + m * DI + e];
        rxh[p] = __bfloat162float(g_xc_hi[base_de + m * DI + e]);
        rxl[p] = __bfloat162float(g_xc_lo[base_de + m * DI + e]);
        rz[p]  = g_xz[m * 8192 + dir * 4096 + 2048 + e];
    }

    for (int t0 = 0; t0 < L_SEQ; t0 += 4) {
#pragma unroll
        for (int u = 0; u < 4; u++) {
            const int t  = t0 + u;
            const int tt = dir ? (L_SEQ - 1 - t) : t;
            const size_t m = brow + tt;

            const float bc = rbc[u], dtv = rdt[u], xh = rxh[u], xl = rxl[u], zz = rz[u];

            const int tp = t + 4;
            if (tp < L_SEQ) {
                const int tq = dir ? (L_SEQ - 1 - tp) : tp;
                const size_t mp = brow + tq;
                rbc[u] = g_proj[proj_base + mp * 96 + 64 + lane];
                rdt[u] = g_dt[base_de + mp * DI + e];
                rxh[u] = __bfloat162float(g_xc_hi[base_de + mp * DI + e]);
                rxl[u] = __bfloat162float(g_xc_lo[base_de + mp * DI + e]);
                rz[u]  = g_xz[mp * 8192 + dir * 4096 + 2048 + e];
            }

            if (lane < 16) sB[warp][lane] = bc; else sC[warp][lane - 16] = bc;
            __syncwarp();

            const float v   = dtv + bias;
            const float dt  = (v > 15.f) ? v : log1pf(__expf(v));
            const float x   = xh + xl;
            const float dtx = dt * x;

            float y = 0.f;
#pragma unroll
            for (int s = 0; s < 16; s++) {
                float dA = __expf(dt * a[s]);
                h[s] = fmaf(h[s], dA, dtx * sB[warp][s]);
                y    = fmaf(h[s], sC[warp][s], y);
            }
            const float yv  = fmaf(x, dcoef, y);
            const float sz  = zz / (1.f + __expf(-zz));
            const float out = yv * sz;
            __nv_bfloat16 hh, ll;
            split2(out, hh, ll);
            const size_t o = base_de + m * DI + e;
            g_y_hi[o] = hh;
            g_y_lo[o] = ll;
            __syncwarp();
        }
    }
}

// ============================================================================
extern "C" void kernel_launch(void* const* d_in, const int* in_sizes, int n_in,
                              void* d_out, int out_size) {
    const float* x      = (const float*)d_in[0];
    const float* in_w   = (const float*)d_in[1];
    const float* conv_w = (const float*)d_in[2];
    const float* conv_b = (const float*)d_in[3];
    const float* x_w    = (const float*)d_in[4];
    const float* dt_w   = (const float*)d_in[5];
    const float* dt_bv  = (const float*)d_in[6];
    const float* A_log  = (const float*)d_in[7];
    const float* Dp     = (const float*)d_in[8];
    const float* out_w  = (const float*)d_in[9];
    float* out = (float*)d_out;

    cudaFuncSetAttribute(k_gemm_z,   cudaFuncAttributeMaxDynamicSharedMemorySize, GEMM_SMEM);
    cudaFuncSetAttribute(k_gemm_cat, cudaFuncAttributeMaxDynamicSharedMemorySize, GEMM_SMEM);

    float *xz, *projpart, *dtv;
    __nv_bfloat16 *xhi, *xlo, *inwhi, *inwlo, *xwhi, *xwlo, *dtwhi, *dtwlo, *owhi, *owlo;
    __nv_bfloat16 *xchi, *xclo, *dtrhi, *dtrlo, *yhi, *ylo;
    cudaGetSymbolAddress((void**)&xz, g_xz);
    cudaGetSymbolAddress((void**)&projpart, g_proj_part);
    cudaGetSymbolAddress((void**)&dtv, g_dt);
    cudaGetSymbolAddress((void**)&xhi, g_x_hi);     cudaGetSymbolAddress((void**)&xlo, g_x_lo);
    cudaGetSymbolAddress((void**)&inwhi, g_inw_hi); cudaGetSymbolAddress((void**)&inwlo, g_inw_lo);
    cudaGetSymbolAddress((void**)&xwhi, g_xw_hi);   cudaGetSymbolAddress((void**)&xwlo, g_xw_lo);
    cudaGetSymbolAddress((void**)&dtwhi, g_dtw_hi); cudaGetSymbolAddress((void**)&dtwlo, g_dtw_lo);
    cudaGetSymbolAddress((void**)&owhi, g_ow_hi);   cudaGetSymbolAddress((void**)&owlo, g_ow_lo);
    cudaGetSymbolAddress((void**)&xchi, g_xc_hi);   cudaGetSymbolAddress((void**)&xclo, g_xc_lo);
    cudaGetSymbolAddress((void**)&dtrhi, g_dtr_hi); cudaGetSymbolAddress((void**)&dtrlo, g_dtr_lo);
    cudaGetSymbolAddress((void**)&yhi, g_y_hi);     cudaGetSymbolAddress((void**)&ylo, g_y_lo);

    // 0-1) conversions (2 launches -> conv sits at profiled slot 3)
    k_cvt_a<<<(N4_A + 255) / 256, 256>>>((const float4*)x, (const float4*)in_w);
    k_cvt_b<<<(N4_B + 255) / 256, 256>>>((const float4*)x_w, (const float4*)dt_w,
                                         (const float4*)out_w);

    // 2) in_proj: xz = x @ in_w^T  (M=8192, N=8192, K=1024)
    k_gemm_z<<<dim3(64, 64, 1), 256, GEMM_SMEM>>>(
        xhi, xlo, 0, inwhi, inwlo, 0,
        xz, 0, 0, DM, DM, 1, 8192, 8192);

    // 3) depthwise conv + silu -> xc hi/lo  (x4 vectorized)  [PROFILED SLOT]
    k_conv<<<(unsigned)(((size_t)2 * M_ROWS * (DI / 4) + 255) / 256), 256>>>(conv_w, conv_b);

    // 4) x_proj (both dirs, split-K x2): partials = xc @ x_proj_w^T
    k_gemm_z<<<dim3(1, 64, 4), 256, GEMM_SMEM>>>(
        xchi, xclo, (size_t)M_ROWS * DI, xwhi, xwlo, (size_t)96 * DI,
        projpart, (size_t)2 * M_ROWS * 96, (size_t)M_ROWS * 96,
        DI, DI / 2, 2, 96, 96);

    // 5) reduce 2 partials -> g_proj, and bf16-split dt_raw -> g_dtr
    k_reduce_proj2<<<(unsigned)(((size_t)2 * M_ROWS * 96 + 255) / 256), 256>>>();

    // 6) dt_proj (both dirs): dt = dt_raw @ dt_proj_w^T (N=2048, K=64)
    k_gemm_z<<<dim3(16, 64, 2), 256, GEMM_SMEM>>>(
        dtrhi, dtrlo, (size_t)M_ROWS * DR, dtwhi, dtwlo, (size_t)DI * DR,
        dtv, (size_t)M_ROWS * DI, 0, DR, DR, 1, DI, DI);

    // 7) selective scan + gating -> y hi/lo
    k_scan<<<dim3(DI / 128, BSZ, 2), 128>>>(dt_bv, A_log, Dp);

    // 8) out_proj (both dirs, K-concatenated single pass)
    k_gemm_cat<<<dim3(8, 64, 1), 256, GEMM_SMEM>>>(
        yhi, ylo, yhi + (size_t)M_ROWS * DI, ylo + (size_t)M_ROWS * DI,
        owhi, owlo, owhi + (size_t)DM * DI, owlo + (size_t)DM * DI,
        out, DI, DM, DM);
}

// round 14
// speedup vs baseline: 2.0485x; 1.0238x over previous
#include <cuda_runtime.h>
#include <cuda_bf16.h>
#include <cstdint>
#include <math.h>

// Problem dims
#define L_SEQ 2048
#define BSZ   4
#define DM    1024
#define DI    2048
#define DS    16
#define DR    64
#define M_ROWS 8192   // BSZ * L_SEQ

// ============================================================================
// Scratch (static device arrays)
// ============================================================================
__device__ float g_xz  [(size_t)M_ROWS * 8192];             // in_proj output (xi|z per dir)
__device__ float g_proj[2 * (size_t)M_ROWS * 96];           // x_proj output (dt_raw|B|C)
__device__ float g_proj_part[4 * (size_t)M_ROWS * 96];      // x_proj split-K partials [dir][ks]
__device__ float g_dt  [2 * (size_t)M_ROWS * DI];           // dt_proj output (pre-softplus)

// bf16 hi/lo operand planes
__device__ __nv_bfloat16 g_x_hi  [(size_t)M_ROWS * DM],  g_x_lo  [(size_t)M_ROWS * DM];
__device__ __nv_bfloat16 g_inw_hi[(size_t)8192 * DM],    g_inw_lo[(size_t)8192 * DM];
__device__ __nv_bfloat16 g_xw_hi [2 * 96 * (size_t)DI],  g_xw_lo [2 * 96 * (size_t)DI];
__device__ __nv_bfloat16 g_dtw_hi[2 * (size_t)DI * DR],  g_dtw_lo[2 * (size_t)DI * DR];
__device__ __nv_bfloat16 g_ow_hi [2 * (size_t)DM * DI],  g_ow_lo [2 * (size_t)DM * DI];
__device__ __nv_bfloat16 g_xc_hi [2 * (size_t)M_ROWS * DI], g_xc_lo[2 * (size_t)M_ROWS * DI];
__device__ __nv_bfloat16 g_dtr_hi[2 * (size_t)M_ROWS * DR], g_dtr_lo[2 * (size_t)M_ROWS * DR];
__device__ __nv_bfloat16 g_y_hi  [2 * (size_t)M_ROWS * DI], g_y_lo [2 * (size_t)M_ROWS * DI];

__device__ __forceinline__ void split2(float v, __nv_bfloat16& h, __nv_bfloat16& l) {
    h = __float2bfloat16_rn(v);
    l = __float2bfloat16_rn(v - __bfloat162float(h));
}

// ============================================================================
// PTX helpers (sm_80-class only: valid on base sm_103 target)
// ============================================================================
__device__ __forceinline__ uint32_t smem_u32(const void* p) {
    uint32_t a;
    asm("{ .reg .u64 t; cvta.to.shared.u64 t, %1; cvt.u32.u64 %0, t; }" : "=r"(a) : "l"(p));
    return a;
}
__device__ __forceinline__ void cpa16(uint32_t dst, const void* src) {
    asm volatile("cp.async.cg.shared.global [%0], [%1], 16;" :: "r"(dst), "l"(src) : "memory");
}
__device__ __forceinline__ void cpa16p(uint32_t dst, const void* src, int sz) {
    asm volatile("cp.async.cg.shared.global [%0], [%1], 16, %2;" :: "r"(dst), "l"(src), "r"(sz) : "memory");
}
__device__ __forceinline__ void cp_commit() {
    asm volatile("cp.async.commit_group;" ::: "memory");
}
template <int N>
__device__ __forceinline__ void cp_wait() {
    asm volatile("cp.async.wait_group %0;" :: "n"(N) : "memory");
}
__device__ __forceinline__ void ldsm_x4(uint32_t* r, uint32_t addr) {
    asm volatile("ldmatrix.sync.aligned.m8n8.x4.shared.b16 {%0,%1,%2,%3}, [%4];"
                 : "=r"(r[0]), "=r"(r[1]), "=r"(r[2]), "=r"(r[3]) : "r"(addr));
}
__device__ __forceinline__ void ldsm_x2(uint32_t* r, uint32_t addr) {
    asm volatile("ldmatrix.sync.aligned.m8n8.x2.shared.b16 {%0,%1}, [%2];"
                 : "=r"(r[0]), "=r"(r[1]) : "r"(addr));
}
__device__ __forceinline__ void mma_bf16(float* d, const uint32_t* a, const uint32_t* b) {
    asm volatile("mma.sync.aligned.m16n8k16.row.col.f32.bf16.bf16.f32 "
                 "{%0,%1,%2,%3}, {%4,%5,%6,%7}, {%8,%9}, {%0,%1,%2,%3};"
                 : "+f"(d[0]), "+f"(d[1]), "+f"(d[2]), "+f"(d[3])
                 : "r"(a[0]), "r"(a[1]), "r"(a[2]), "r"(a[3]), "r"(b[0]), "r"(b[1]));
}

// ============================================================================
// GEMM machinery (R11 WINNER config): 128x128 tile, K-chunk 32 (64B rows),
// 256 threads (2x4 warps, 64x32 warp tiles), XOR-swizzled smem (no padding),
// 3-stage cp.async pipeline, ONE __syncthreads per chunk.
// Static accumulator indexing ONLY (dynamic => spills).
// bf16x3 split: acc += Ah*Bh + Ah*Bl + Al*Bh  (fp32 accumulate)
// ============================================================================
#define PLANE 8192                       // 128 rows x 64 B, no padding
#define OFF_AH 0
#define OFF_AL (PLANE)
#define OFF_BH (2 * PLANE)
#define OFF_BL (3 * PLANE)
#define STAGE  (4 * PLANE)               // 32768 B
#define NSTAGE 3
#define GEMM_SMEM (NSTAGE * STAGE)       // 98304 B (2 CTAs/SM)
#define SW64(o) ((o) ^ (((o) >> 3) & 0x30))

struct GemmCtx {
    uint32_t sb;
    int tid, lane, warp, wm, wn, bm, bn;
    uint32_t a_lane_off, b_lane_off;
};

__device__ __forceinline__ void gemm_init(GemmCtx& g, char* smem) {
    g.sb = smem_u32(smem);
    g.tid = threadIdx.x;
    g.lane = g.tid & 31;
    g.warp = g.tid >> 5;
    g.wm = g.warp >> 2;
    g.wn = g.warp & 3;
    g.bm = blockIdx.y * 128;
    g.bn = blockIdx.x * 128;
    g.a_lane_off = (uint32_t)((g.lane & 15) * 64 + (g.lane >> 4) * 16);        // bytes
    g.b_lane_off = (uint32_t)((g.lane & 7) * 64 + ((g.lane >> 3) & 1) * 16);   // bytes
}

__device__ __forceinline__ void gemm_load_chunk(
    const GemmCtx& g, int s, int k0, int K,
    const __nv_bfloat16* __restrict__ Ahi, const __nv_bfloat16* __restrict__ Alo,
    const __nv_bfloat16* __restrict__ Bhi, const __nv_bfloat16* __restrict__ Blo,
    int Nact)
{
    const uint32_t st = g.sb + s * STAGE;
#pragma unroll
    for (int it = 0; it < 2; ++it) {
        const int i   = g.tid + it * 256;
        const int row = i >> 2;
        const int c8  = (i & 3) * 8;
        const uint32_t so = SW64((uint32_t)(row * 64 + c8 * 2));
        const size_t ga = (size_t)(g.bm + row) * K + k0 + c8;
        cpa16(st + OFF_AH + so, Ahi + ga);
        cpa16(st + OFF_AL + so, Alo + ga);
        const size_t gb = (size_t)(g.bn + row) * K + k0 + c8;
        const int sz = (g.bn + row < Nact) ? 16 : 0;
        cpa16p(st + OFF_BH + so, Bhi + gb, sz);
        cpa16p(st + OFF_BL + so, Blo + gb, sz);
    }
}

__device__ __forceinline__ void gemm_compute_chunk(const GemmCtx& g, int s, float acc[4][4][4]) {
    const uint32_t st = g.sb + s * STAGE;
#pragma unroll
    for (int k16 = 0; k16 < 32; k16 += 16) {
        const uint32_t ak = g.a_lane_off + k16 * 2;
        const uint32_t bk = g.b_lane_off + k16 * 2;
        uint32_t bh[4][2], bl[4][2];
#pragma unroll
        for (int j = 0; j < 4; ++j) {
            const uint32_t bo = (uint32_t)((g.wn * 32 + j * 8) * 64) + bk;
            const uint32_t bos = SW64(bo);
            ldsm_x2(bh[j], st + OFF_BH + bos);
            ldsm_x2(bl[j], st + OFF_BL + bos);
        }
#pragma unroll
        for (int i = 0; i < 4; ++i) {
            const uint32_t ao = (uint32_t)((g.wm * 64 + i * 16) * 64) + ak;
            const uint32_t aos = SW64(ao);
            uint32_t ah[4], al[4];
            ldsm_x4(ah, st + OFF_AH + aos);
            ldsm_x4(al, st + OFF_AL + aos);
#pragma unroll
            for (int j = 0; j < 4; ++j) mma_bf16(acc[i][j], ah, bh[j]);
#pragma unroll
            for (int j = 0; j < 4; ++j) mma_bf16(acc[i][j], ah, bl[j]);
#pragma unroll
            for (int j = 0; j < 4; ++j) mma_bf16(acc[i][j], al, bh[j]);
        }
    }
}

// ============================================================================
// k_gemm_z: split-K capable. blockIdx.z = dir * nsplit + ks; kStart = ks*kLen.
// C target = C + dir*cStride + ks*partStride.
// ============================================================================
__global__ void __launch_bounds__(256, 2) k_gemm_z(
    const __nv_bfloat16* __restrict__ Ahi, const __nv_bfloat16* __restrict__ Alo, size_t aStride,
    const __nv_bfloat16* __restrict__ Bhi, const __nv_bfloat16* __restrict__ Blo, size_t bStride,
    float* __restrict__ C, size_t cStride, size_t partStride,
    int K_ld, int kLen, int nsplit, int Nact, int ldc)
{
    extern __shared__ __align__(1024) char smem[];
    GemmCtx g;
    gemm_init(g, smem);
    const int dir = blockIdx.z / nsplit;
    const int ks  = blockIdx.z % nsplit;
    const int kStart = ks * kLen;
    Ahi += (size_t)dir * aStride; Alo += (size_t)dir * aStride;
    Bhi += (size_t)dir * bStride; Blo += (size_t)dir * bStride;
    C   += (size_t)dir * cStride + (size_t)ks * partStride;
    const int nch = kLen >> 5;

    float acc[4][4][4];
#pragma unroll
    for (int i = 0; i < 4; i++)
#pragma unroll
        for (int j = 0; j < 4; j++)
#pragma unroll
            for (int k = 0; k < 4; k++) acc[i][j][k] = 0.f;

    gemm_load_chunk(g, 0, kStart, K_ld, Ahi, Alo, Bhi, Blo, Nact);
    cp_commit();
    if (1 < nch) gemm_load_chunk(g, 1, kStart + 32, K_ld, Ahi, Alo, Bhi, Blo, Nact);
    cp_commit();

    for (int c = 0; c < nch; ++c) {
        cp_wait<1>();
        __syncthreads();
        if (c + 2 < nch)
            gemm_load_chunk(g, (c + 2) % NSTAGE, kStart + ((c + 2) << 5), K_ld, Ahi, Alo, Bhi, Blo, Nact);
        cp_commit();
        gemm_compute_chunk(g, c % NSTAGE, acc);
    }

    const int gid = g.lane >> 2;
    const int tig = g.lane & 3;
#pragma unroll
    for (int i = 0; i < 4; ++i) {
        const int row = g.bm + g.wm * 64 + i * 16 + gid;
#pragma unroll
        for (int j = 0; j < 4; ++j) {
            const int col = g.bn + g.wn * 32 + j * 8 + tig * 2;
            if (col < Nact) {
                *(float2*)&C[(size_t)row * ldc + col]       = make_float2(acc[i][j][0], acc[i][j][1]);
                *(float2*)&C[(size_t)(row + 8) * ldc + col] = make_float2(acc[i][j][2], acc[i][j][3]);
            }
        }
    }
}

// ============================================================================
// k_gemm_cat: out = y0 @ ow0^T + y1 @ ow1^T  (K-concatenated, single pass)
// ============================================================================
__global__ void __launch_bounds__(256, 2) k_gemm_cat(
    const __nv_bfloat16* __restrict__ A0hi, const __nv_bfloat16* __restrict__ A0lo,
    const __nv_bfloat16* __restrict__ A1hi, const __nv_bfloat16* __restrict__ A1lo,
    const __nv_bfloat16* __restrict__ B0hi, const __nv_bfloat16* __restrict__ B0lo,
    const __nv_bfloat16* __restrict__ B1hi, const __nv_bfloat16* __restrict__ B1lo,
    float* __restrict__ C, int Kh, int Nact, int ldc)
{
    extern __shared__ __align__(1024) char smem[];
    GemmCtx g;
    gemm_init(g, smem);
    const int nch_h = Kh >> 5;
    const int nch = nch_h * 2;

    float acc[4][4][4];
#pragma unroll
    for (int i = 0; i < 4; i++)
#pragma unroll
        for (int j = 0; j < 4; j++)
#pragma unroll
            for (int k = 0; k < 4; k++) acc[i][j][k] = 0.f;

    auto load = [&](int c, int s) {
        if (c < nch_h)
            gemm_load_chunk(g, s, c << 5, Kh, A0hi, A0lo, B0hi, B0lo, Nact);
        else
            gemm_load_chunk(g, s, (c - nch_h) << 5, Kh, A1hi, A1lo, B1hi, B1lo, Nact);
    };

    load(0, 0);
    cp_commit();
    if (1 < nch) load(1, 1);
    cp_commit();

    for (int c = 0; c < nch; ++c) {
        cp_wait<1>();
        __syncthreads();
        if (c + 2 < nch) load(c + 2, (c + 2) % NSTAGE);
        cp_commit();
        gemm_compute_chunk(g, c % NSTAGE, acc);
    }

    const int gid = g.lane >> 2;
    const int tig = g.lane & 3;
#pragma unroll
    for (int i = 0; i < 4; ++i) {
        const int row = g.bm + g.wm * 64 + i * 16 + gid;
#pragma unroll
        for (int j = 0; j < 4; ++j) {
            const int col = g.bn + g.wn * 32 + j * 8 + tig * 2;
            if (col < Nact) {
                *(float2*)&C[(size_t)row * ldc + col]       = make_float2(acc[i][j][0], acc[i][j][1]);
                *(float2*)&C[(size_t)(row + 8) * ldc + col] = make_float2(acc[i][j][2], acc[i][j][3]);
            }
        }
    }
}

// ============================================================================
// k_reduce_proj2: g_proj = sum of 2 split-K partials; cols<64 also -> dtr hi/lo
// ============================================================================
__global__ void k_reduce_proj2() {
    size_t idx = (size_t)blockIdx.x * blockDim.x + threadIdx.x;
    const size_t total = (size_t)2 * M_ROWS * 96;
    if (idx >= total) return;
    const int dir = (int)(idx / ((size_t)M_ROWS * 96));
    const size_t off = idx % ((size_t)M_ROWS * 96);
    const float* base = g_proj_part + (size_t)dir * 2 * M_ROWS * 96;
    float v = base[off] + base[off + (size_t)M_ROWS * 96];
    g_proj[idx] = v;
    const int col = (int)(off % 96);
    if (col < DR) {
        const size_t row = off / 96;
        __nv_bfloat16 h, l;
        split2(v, h, l);
        const size_t d = ((size_t)dir * M_ROWS + row) * DR + col;
        g_dtr_hi[d] = h;
        g_dtr_lo[d] = l;
    }
}

// ============================================================================
// fp32 -> bf16 hi/lo conversions, TWO launches (so conv lands at slot 3).
// ============================================================================
#define N4_X   2097152u   // 8192*1024/4
#define N4_INW 2097152u   // 8192*1024/4
#define N4_A   (N4_X + N4_INW)
#define N4_XW  98304u     // 2*96*2048/4
#define N4_DTW 65536u     // 2*2048*64/4
#define N4_OW  1048576u   // 2*1024*2048/4
#define N4_B   (N4_XW + N4_DTW + N4_OW)

__global__ void k_cvt_a(const float4* __restrict__ x, const float4* __restrict__ inw) {
    uint32_t i = blockIdx.x * blockDim.x + threadIdx.x;
    if (i >= N4_A) return;
    const float4* src;
    __nv_bfloat16 *hi, *lo;
    uint32_t off = i;
    if (i < N4_X) { src = x;   hi = g_x_hi;   lo = g_x_lo; }
    else { off -= N4_X; src = inw; hi = g_inw_hi; lo = g_inw_lo; }
    float4 v = src[off];
    __nv_bfloat16 h0, h1, h2, h3, l0, l1, l2, l3;
    split2(v.x, h0, l0); split2(v.y, h1, l1); split2(v.z, h2, l2); split2(v.w, h3, l3);
    __nv_bfloat162* H = (__nv_bfloat162*)hi;
    __nv_bfloat162* L = (__nv_bfloat162*)lo;
    H[2 * (size_t)off]     = __nv_bfloat162(h0, h1);
    H[2 * (size_t)off + 1] = __nv_bfloat162(h2, h3);
    L[2 * (size_t)off]     = __nv_bfloat162(l0, l1);
    L[2 * (size_t)off + 1] = __nv_bfloat162(l2, l3);
}

__global__ void k_cvt_b(const float4* __restrict__ xw, const float4* __restrict__ dtw,
                        const float4* __restrict__ ow) {
    uint32_t i = blockIdx.x * blockDim.x + threadIdx.x;
    if (i >= N4_B) return;
    const float4* src;
    __nv_bfloat16 *hi, *lo;
    uint32_t off = i;
    if (i < N4_XW)                      { src = xw;  hi = g_xw_hi;  lo = g_xw_lo; }
    else if ((off -= N4_XW) < N4_DTW)   { src = dtw; hi = g_dtw_hi; lo = g_dtw_lo; }
    else { off -= N4_DTW;                 src = ow;  hi = g_ow_hi;  lo = g_ow_lo; }
    float4 v = src[off];
    __nv_bfloat16 h0, h1, h2, h3, l0, l1, l2, l3;
    split2(v.x, h0, l0); split2(v.y, h1, l1); split2(v.z, h2, l2); split2(v.w, h3, l3);
    __nv_bfloat162* H = (__nv_bfloat162*)hi;
    __nv_bfloat162* L = (__nv_bfloat162*)lo;
    H[2 * (size_t)off]     = __nv_bfloat162(h0, h1);
    H[2 * (size_t)off + 1] = __nv_bfloat162(h2, h3);
    L[2 * (size_t)off]     = __nv_bfloat162(l0, l1);
    L[2 * (size_t)off + 1] = __nv_bfloat162(l2, l3);
}

// ============================================================================
// Depthwise conv + SiLU v3: thread = (dir, b, 4 L-positions, 4 channels).
// 7 consecutive xi rows cover all taps of 4 outputs; weights loaded ONCE per
// 16 outputs (12 x 16B loads / 16 elems = 3x less L1 traffic than v2).
// Both dirs use stencil acc_u = bias + sum_j w'[j]*row[u+j]:
//   dir0: w' = cw,            rows l0-3 .. l0+3
//   dir1: w' = reverse(cw),   rows l0   .. l0+6
// [PROFILED SLOT]
// ============================================================================
#define CONV_THREADS ((size_t)2 * BSZ * (L_SEQ / 4) * (DI / 4))   // 2,097,152

__global__ void __launch_bounds__(256) k_conv(const float* __restrict__ cw,
                                              const float* __restrict__ cb) {
    const size_t idx = (size_t)blockIdx.x * 256 + threadIdx.x;
    if (idx >= CONV_THREADS) return;
    const int eg  = (int)(idx & (DI / 4 - 1));          // 0..511
    size_t r      = idx >> 9;
    const int lb  = (int)(r & (L_SEQ / 4 - 1));         // 0..511
    r >>= 9;
    const int b   = (int)(r & 3);
    const int dir = (int)(r >> 2);
    const int e   = eg * 4;
    const int l0  = lb * 4;

    // weights (reversed for dir1) + bias, one load each per 16 outputs
    const float4* wv = (const float4*)(cw + ((size_t)dir * DI + e) * 4);
    float4 wc[4];                       // wc[c] = taps of channel e+c
#pragma unroll
    for (int c = 0; c < 4; c++) wc[c] = wv[c];
    float w[4][4];                      // w[j][c]
#pragma unroll
    for (int c = 0; c < 4; c++) {
        const float t0 = wc[c].x, t1 = wc[c].y, t2 = wc[c].z, t3 = wc[c].w;
        if (dir == 0) { w[0][c] = t0; w[1][c] = t1; w[2][c] = t2; w[3][c] = t3; }
        else          { w[0][c] = t3; w[1][c] = t2; w[2][c] = t1; w[3][c] = t0; }
    }
    const float4 bias = *(const float4*)(cb + dir * DI + e);

    // 7 tap rows
    const int base = (dir == 0) ? (l0 - 3) : l0;
    const size_t xibase = (size_t)(b * L_SEQ) * 8192 + (size_t)dir * 4096 + e;
    float4 row[7];
#pragma unroll
    for (int i = 0; i < 7; i++) {
        const int tl = base + i;
        row[i] = (tl >= 0 && tl < L_SEQ) ? *(const float4*)(g_xz + xibase + (size_t)tl * 8192)
                                         : make_float4(0.f, 0.f, 0.f, 0.f);
    }

    const size_t obase = ((size_t)dir * M_ROWS + (size_t)b * L_SEQ + l0) * DI + e;
#pragma unroll
    for (int u = 0; u < 4; u++) {
        float4 acc = bias;
#pragma unroll
        for (int j = 0; j < 4; j++) {
            const float4 xi = row[u + j];
            acc.x = fmaf(w[j][0], xi.x, acc.x);
            acc.y = fmaf(w[j][1], xi.y, acc.y);
            acc.z = fmaf(w[j][2], xi.z, acc.z);
            acc.w = fmaf(w[j][3], xi.w, acc.w);
        }
        const float xc0 = acc.x / (1.f + __expf(-acc.x));
        const float xc1 = acc.y / (1.f + __expf(-acc.y));
        const float xc2 = acc.z / (1.f + __expf(-acc.z));
        const float xc3 = acc.w / (1.f + __expf(-acc.w));
        __nv_bfloat16 h0, h1, h2, h3, lo0, lo1, lo2, lo3;
        split2(xc0, h0, lo0); split2(xc1, h1, lo1);
        split2(xc2, h2, lo2); split2(xc3, h3, lo3);
        const size_t o = obase + (size_t)u * DI;
        __nv_bfloat162 hp0(h0, h1), hp1(h2, h3), lp0(lo0, lo1), lp1(lo2, lo3);
        *(uint2*)(g_xc_hi + o) = make_uint2(*(uint32_t*)&hp0, *(uint32_t*)&hp1);
        *(uint2*)(g_xc_lo + o) = make_uint2(*(uint32_t*)&lp0, *(uint32_t*)&lp1);
    }
}

// ============================================================================
// Selective scan (R5 v1): 128-thread blocks, 4-deep register-ring prefetch.
// Fuses softplus, recurrence, D-skip, silu(z) gating. Writes y hi/lo planes.
// ============================================================================
__global__ void __launch_bounds__(128) k_scan(const float* __restrict__ dt_b,
                                              const float* __restrict__ A_log,
                                              const float* __restrict__ Dp) {
    const int tid  = threadIdx.x;
    const int lane = tid & 31;
    const int warp = tid >> 5;
    const int dir  = blockIdx.z;
    const int b    = blockIdx.y;
    const int e    = blockIdx.x * 128 + tid;

    __shared__ float sB[4][16], sC[4][16];

    float a[16];
#pragma unroll
    for (int s = 0; s < 16; s++)
        a[s] = -__expf(A_log[((size_t)dir * DI + e) * 16 + s]);

    const float bias  = dt_b[dir * DI + e];
    const float dcoef = Dp[dir * DI + e];

    float h[16];
#pragma unroll
    for (int s = 0; s < 16; s++) h[s] = 0.f;

    const size_t base_de   = (size_t)dir * M_ROWS * DI;
    const size_t proj_base = (size_t)dir * M_ROWS * 96;
    const size_t brow      = (size_t)b * L_SEQ;

    float rbc[4], rdt[4], rxh[4], rxl[4], rz[4];
#pragma unroll
    for (int p = 0; p < 4; p++) {
        const int tt = dir ? (L_SEQ - 1 - p) : p;
        const size_t m = brow + tt;
        rbc[p] = g_proj[proj_base + m * 96 + 64 + lane];
        rdt[p] = g_dt[base_de + m * DI + e];
        rxh[p] = __bfloat162float(g_xc_hi[base_de + m * DI + e]);
        rxl[p] = __bfloat162float(g_xc_lo[base_de + m * DI + e]);
        rz[p]  = g_xz[m * 8192 + dir * 4096 + 2048 + e];
    }

    for (int t0 = 0; t0 < L_SEQ; t0 += 4) {
#pragma unroll
        for (int u = 0; u < 4; u++) {
            const int t  = t0 + u;
            const int tt = dir ? (L_SEQ - 1 - t) : t;
            const size_t m = brow + tt;

            const float bc = rbc[u], dtv = rdt[u], xh = rxh[u], xl = rxl[u], zz = rz[u];

            const int tp = t + 4;
            if (tp < L_SEQ) {
                const int tq = dir ? (L_SEQ - 1 - tp) : tp;
                const size_t mp = brow + tq;
                rbc[u] = g_proj[proj_base + mp * 96 + 64 + lane];
                rdt[u] = g_dt[base_de + mp * DI + e];
                rxh[u] = __bfloat162float(g_xc_hi[base_de + mp * DI + e]);
                rxl[u] = __bfloat162float(g_xc_lo[base_de + mp * DI + e]);
                rz[u]  = g_xz[mp * 8192 + dir * 4096 + 2048 + e];
            }

            if (lane < 16) sB[warp][lane] = bc; else sC[warp][lane - 16] = bc;
            __syncwarp();

            const float v   = dtv + bias;
            const float dt  = (v > 15.f) ? v : log1pf(__expf(v));
            const float x   = xh + xl;
            const float dtx = dt * x;

            float y = 0.f;
#pragma unroll
            for (int s = 0; s < 16; s++) {
                float dA = __expf(dt * a[s]);
                h[s] = fmaf(h[s], dA, dtx * sB[warp][s]);
                y    = fmaf(h[s], sC[warp][s], y);
            }
            const float yv  = fmaf(x, dcoef, y);
            const float sz  = zz / (1.f + __expf(-zz));
            const float out = yv * sz;
            __nv_bfloat16 hh, ll;
            split2(out, hh, ll);
            const size_t o = base_de + m * DI + e;
            g_y_hi[o] = hh;
            g_y_lo[o] = ll;
            __syncwarp();
        }
    }
}

// ============================================================================
extern "C" void kernel_launch(void* const* d_in, const int* in_sizes, int n_in,
                              void* d_out, int out_size) {
    const float* x      = (const float*)d_in[0];
    const float* in_w   = (const float*)d_in[1];
    const float* conv_w = (const float*)d_in[2];
    const float* conv_b = (const float*)d_in[3];
    const float* x_w    = (const float*)d_in[4];
    const float* dt_w   = (const float*)d_in[5];
    const float* dt_bv  = (const float*)d_in[6];
    const float* A_log  = (const float*)d_in[7];
    const float* Dp     = (const float*)d_in[8];
    const float* out_w  = (const float*)d_in[9];
    float* out = (float*)d_out;

    cudaFuncSetAttribute(k_gemm_z,   cudaFuncAttributeMaxDynamicSharedMemorySize, GEMM_SMEM);
    cudaFuncSetAttribute(k_gemm_cat, cudaFuncAttributeMaxDynamicSharedMemorySize, GEMM_SMEM);

    float *xz, *projpart, *dtv;
    __nv_bfloat16 *xhi, *xlo, *inwhi, *inwlo, *xwhi, *xwlo, *dtwhi, *dtwlo, *owhi, *owlo;
    __nv_bfloat16 *xchi, *xclo, *dtrhi, *dtrlo, *yhi, *ylo;
    cudaGetSymbolAddress((void**)&xz, g_xz);
    cudaGetSymbolAddress((void**)&projpart, g_proj_part);
    cudaGetSymbolAddress((void**)&dtv, g_dt);
    cudaGetSymbolAddress((void**)&xhi, g_x_hi);     cudaGetSymbolAddress((void**)&xlo, g_x_lo);
    cudaGetSymbolAddress((void**)&inwhi, g_inw_hi); cudaGetSymbolAddress((void**)&inwlo, g_inw_lo);
    cudaGetSymbolAddress((void**)&xwhi, g_xw_hi);   cudaGetSymbolAddress((void**)&xwlo, g_xw_lo);
    cudaGetSymbolAddress((void**)&dtwhi, g_dtw_hi); cudaGetSymbolAddress((void**)&dtwlo, g_dtw_lo);
    cudaGetSymbolAddress((void**)&owhi, g_ow_hi);   cudaGetSymbolAddress((void**)&owlo, g_ow_lo);
    cudaGetSymbolAddress((void**)&xchi, g_xc_hi);   cudaGetSymbolAddress((void**)&xclo, g_xc_lo);
    cudaGetSymbolAddress((void**)&dtrhi, g_dtr_hi); cudaGetSymbolAddress((void**)&dtrlo, g_dtr_lo);
    cudaGetSymbolAddress((void**)&yhi, g_y_hi);     cudaGetSymbolAddress((void**)&ylo, g_y_lo);

    // 0-1) conversions (2 launches -> conv sits at profiled slot 3)
    k_cvt_a<<<(N4_A + 255) / 256, 256>>>((const float4*)x, (const float4*)in_w);
    k_cvt_b<<<(N4_B + 255) / 256, 256>>>((const float4*)x_w, (const float4*)dt_w,
                                         (const float4*)out_w);

    // 2) in_proj: xz = x @ in_w^T  (M=8192, N=8192, K=1024)
    k_gemm_z<<<dim3(64, 64, 1), 256, GEMM_SMEM>>>(
        xhi, xlo, 0, inwhi, inwlo, 0,
        xz, 0, 0, DM, DM, 1, 8192, 8192);

    // 3) depthwise conv + silu -> xc hi/lo (v3: 4L x 4E per thread)  [PROFILED]
    k_conv<<<(unsigned)((CONV_THREADS + 255) / 256), 256>>>(conv_w, conv_b);

    // 4) x_proj (both dirs, split-K x2): partials = xc @ x_proj_w^T
    k_gemm_z<<<dim3(1, 64, 4), 256, GEMM_SMEM>>>(
        xchi, xclo, (size_t)M_ROWS * DI, xwhi, xwlo, (size_t)96 * DI,
        projpart, (size_t)2 * M_ROWS * 96, (size_t)M_ROWS * 96,
        DI, DI / 2, 2, 96, 96);

    // 5) reduce 2 partials -> g_proj, and bf16-split dt_raw -> g_dtr
    k_reduce_proj2<<<(unsigned)(((size_t)2 * M_ROWS * 96 + 255) / 256), 256>>>();

    // 6) dt_proj (both dirs): dt = dt_raw @ dt_proj_w^T (N=2048, K=64)
    k_gemm_z<<<dim3(16, 64, 2), 256, GEMM_SMEM>>>(
        dtrhi, dtrlo, (size_t)M_ROWS * DR, dtwhi, dtwlo, (size_t)DI * DR,
        dtv, (size_t)M_ROWS * DI, 0, DR, DR, 1, DI, DI);

    // 7) selective scan + gating -> y hi/lo
    k_scan<<<dim3(DI / 128, BSZ, 2), 128>>>(dt_bv, A_log, Dp);

    // 8) out_proj (both dirs, K-concatenated single pass)
    k_gemm_cat<<<dim3(8, 64, 1), 256, GEMM_SMEM>>>(
        yhi, ylo, yhi + (size_t)M_ROWS * DI, ylo + (size_t)M_ROWS * DI,
        owhi, owlo, owhi + (size_t)DM * DI, owlo + (size_t)DM * DI,
        out, DI, DM, DM);
}

// round 15
// speedup vs baseline: 2.6529x; 1.2950x over previous
#include <cuda_runtime.h>
#include <cuda_bf16.h>
#include <cstdint>
#include <math.h>

// Problem dims
#define L_SEQ 2048
#define BSZ   4
#define DM    1024
#define DI    2048
#define DS    16
#define DR    64
#define M_ROWS 8192   // BSZ * L_SEQ

// Scan chunking
#define SCH   4                 // chunks
#define SCL   (L_SEQ / SCH)     // 512 steps per chunk

// ============================================================================
// Scratch (static device arrays)
// ============================================================================
__device__ float g_xz  [(size_t)M_ROWS * 8192];             // in_proj output (xi|z per dir)
__device__ float g_proj[2 * (size_t)M_ROWS * 96];           // x_proj output (dt_raw|B|C)
__device__ float g_proj_part[4 * (size_t)M_ROWS * 96];      // x_proj split-K partials [dir][ks]
__device__ float g_dt  [2 * (size_t)M_ROWS * DI];           // dt_proj output (pre-softplus)

// chunked-scan state buffers (chunks 0..2): [dir][b][c][s][e]
__device__ float g_hP [2 * 4 * 3 * 16 * 2048];
__device__ float g_hL [2 * 4 * 3 * 16 * 2048];
__device__ float g_hin[2 * 4 * 3 * 16 * 2048];              // h_in for chunks 1..3

// bf16 hi/lo operand planes
__device__ __nv_bfloat16 g_x_hi  [(size_t)M_ROWS * DM],  g_x_lo  [(size_t)M_ROWS * DM];
__device__ __nv_bfloat16 g_inw_hi[(size_t)8192 * DM],    g_inw_lo[(size_t)8192 * DM];
__device__ __nv_bfloat16 g_xw_hi [2 * 96 * (size_t)DI],  g_xw_lo [2 * 96 * (size_t)DI];
__device__ __nv_bfloat16 g_dtw_hi[2 * (size_t)DI * DR],  g_dtw_lo[2 * (size_t)DI * DR];
__device__ __nv_bfloat16 g_ow_hi [2 * (size_t)DM * DI],  g_ow_lo [2 * (size_t)DM * DI];
__device__ __nv_bfloat16 g_xc_hi [2 * (size_t)M_ROWS * DI], g_xc_lo[2 * (size_t)M_ROWS * DI];
__device__ __nv_bfloat16 g_dtr_hi[2 * (size_t)M_ROWS * DR], g_dtr_lo[2 * (size_t)M_ROWS * DR];
__device__ __nv_bfloat16 g_y_hi  [2 * (size_t)M_ROWS * DI], g_y_lo [2 * (size_t)M_ROWS * DI];

__device__ __forceinline__ void split2(float v, __nv_bfloat16& h, __nv_bfloat16& l) {
    h = __float2bfloat16_rn(v);
    l = __float2bfloat16_rn(v - __bfloat162float(h));
}

// ============================================================================
// PTX helpers (sm_80-class only: valid on base sm_103 target)
// ============================================================================
__device__ __forceinline__ uint32_t smem_u32(const void* p) {
    uint32_t a;
    asm("{ .reg .u64 t; cvta.to.shared.u64 t, %1; cvt.u32.u64 %0, t; }" : "=r"(a) : "l"(p));
    return a;
}
__device__ __forceinline__ void cpa16(uint32_t dst, const void* src) {
    asm volatile("cp.async.cg.shared.global [%0], [%1], 16;" :: "r"(dst), "l"(src) : "memory");
}
__device__ __forceinline__ void cpa16p(uint32_t dst, const void* src, int sz) {
    asm volatile("cp.async.cg.shared.global [%0], [%1], 16, %2;" :: "r"(dst), "l"(src), "r"(sz) : "memory");
}
__device__ __forceinline__ void cp_commit() {
    asm volatile("cp.async.commit_group;" ::: "memory");
}
template <int N>
__device__ __forceinline__ void cp_wait() {
    asm volatile("cp.async.wait_group %0;" :: "n"(N) : "memory");
}
__device__ __forceinline__ void ldsm_x4(uint32_t* r, uint32_t addr) {
    asm volatile("ldmatrix.sync.aligned.m8n8.x4.shared.b16 {%0,%1,%2,%3}, [%4];"
                 : "=r"(r[0]), "=r"(r[1]), "=r"(r[2]), "=r"(r[3]) : "r"(addr));
}
__device__ __forceinline__ void ldsm_x2(uint32_t* r, uint32_t addr) {
    asm volatile("ldmatrix.sync.aligned.m8n8.x2.shared.b16 {%0,%1}, [%2];"
                 : "=r"(r[0]), "=r"(r[1]) : "r"(addr));
}
__device__ __forceinline__ void mma_bf16(float* d, const uint32_t* a, const uint32_t* b) {
    asm volatile("mma.sync.aligned.m16n8k16.row.col.f32.bf16.bf16.f32 "
                 "{%0,%1,%2,%3}, {%4,%5,%6,%7}, {%8,%9}, {%0,%1,%2,%3};"
                 : "+f"(d[0]), "+f"(d[1]), "+f"(d[2]), "+f"(d[3])
                 : "r"(a[0]), "r"(a[1]), "r"(a[2]), "r"(a[3]), "r"(b[0]), "r"(b[1]));
}

// ============================================================================
// GEMM machinery (R11 WINNER config) — FROZEN
// ============================================================================
#define PLANE 8192
#define OFF_AH 0
#define OFF_AL (PLANE)
#define OFF_BH (2 * PLANE)
#define OFF_BL (3 * PLANE)
#define STAGE  (4 * PLANE)
#define NSTAGE 3
#define GEMM_SMEM (NSTAGE * STAGE)
#define SW64(o) ((o) ^ (((o) >> 3) & 0x30))

struct GemmCtx {
    uint32_t sb;
    int tid, lane, warp, wm, wn, bm, bn;
    uint32_t a_lane_off, b_lane_off;
};

__device__ __forceinline__ void gemm_init(GemmCtx& g, char* smem) {
    g.sb = smem_u32(smem);
    g.tid = threadIdx.x;
    g.lane = g.tid & 31;
    g.warp = g.tid >> 5;
    g.wm = g.warp >> 2;
    g.wn = g.warp & 3;
    g.bm = blockIdx.y * 128;
    g.bn = blockIdx.x * 128;
    g.a_lane_off = (uint32_t)((g.lane & 15) * 64 + (g.lane >> 4) * 16);
    g.b_lane_off = (uint32_t)((g.lane & 7) * 64 + ((g.lane >> 3) & 1) * 16);
}

__device__ __forceinline__ void gemm_load_chunk(
    const GemmCtx& g, int s, int k0, int K,
    const __nv_bfloat16* __restrict__ Ahi, const __nv_bfloat16* __restrict__ Alo,
    const __nv_bfloat16* __restrict__ Bhi, const __nv_bfloat16* __restrict__ Blo,
    int Nact)
{
    const uint32_t st = g.sb + s * STAGE;
#pragma unroll
    for (int it = 0; it < 2; ++it) {
        const int i   = g.tid + it * 256;
        const int row = i >> 2;
        const int c8  = (i & 3) * 8;
        const uint32_t so = SW64((uint32_t)(row * 64 + c8 * 2));
        const size_t ga = (size_t)(g.bm + row) * K + k0 + c8;
        cpa16(st + OFF_AH + so, Ahi + ga);
        cpa16(st + OFF_AL + so, Alo + ga);
        const size_t gb = (size_t)(g.bn + row) * K + k0 + c8;
        const int sz = (g.bn + row < Nact) ? 16 : 0;
        cpa16p(st + OFF_BH + so, Bhi + gb, sz);
        cpa16p(st + OFF_BL + so, Blo + gb, sz);
    }
}

__device__ __forceinline__ void gemm_compute_chunk(const GemmCtx& g, int s, float acc[4][4][4]) {
    const uint32_t st = g.sb + s * STAGE;
#pragma unroll
    for (int k16 = 0; k16 < 32; k16 += 16) {
        const uint32_t ak = g.a_lane_off + k16 * 2;
        const uint32_t bk = g.b_lane_off + k16 * 2;
        uint32_t bh[4][2], bl[4][2];
#pragma unroll
        for (int j = 0; j < 4; ++j) {
            const uint32_t bo = (uint32_t)((g.wn * 32 + j * 8) * 64) + bk;
            const uint32_t bos = SW64(bo);
            ldsm_x2(bh[j], st + OFF_BH + bos);
            ldsm_x2(bl[j], st + OFF_BL + bos);
        }
#pragma unroll
        for (int i = 0; i < 4; ++i) {
            const uint32_t ao = (uint32_t)((g.wm * 64 + i * 16) * 64) + ak;
            const uint32_t aos = SW64(ao);
            uint32_t ah[4], al[4];
            ldsm_x4(ah, st + OFF_AH + aos);
            ldsm_x4(al, st + OFF_AL + aos);
#pragma unroll
            for (int j = 0; j < 4; ++j) mma_bf16(acc[i][j], ah, bh[j]);
#pragma unroll
            for (int j = 0; j < 4; ++j) mma_bf16(acc[i][j], ah, bl[j]);
#pragma unroll
            for (int j = 0; j < 4; ++j) mma_bf16(acc[i][j], al, bh[j]);
        }
    }
}

__global__ void __launch_bounds__(256, 2) k_gemm_z(
    const __nv_bfloat16* __restrict__ Ahi, const __nv_bfloat16* __restrict__ Alo, size_t aStride,
    const __nv_bfloat16* __restrict__ Bhi, const __nv_bfloat16* __restrict__ Blo, size_t bStride,
    float* __restrict__ C, size_t cStride, size_t partStride,
    int K_ld, int kLen, int nsplit, int Nact, int ldc)
{
    extern __shared__ __align__(1024) char smem[];
    GemmCtx g;
    gemm_init(g, smem);
    const int dir = blockIdx.z / nsplit;
    const int ks  = blockIdx.z % nsplit;
    const int kStart = ks * kLen;
    Ahi += (size_t)dir * aStride; Alo += (size_t)dir * aStride;
    Bhi += (size_t)dir * bStride; Blo += (size_t)dir * bStride;
    C   += (size_t)dir * cStride + (size_t)ks * partStride;
    const int nch = kLen >> 5;

    float acc[4][4][4];
#pragma unroll
    for (int i = 0; i < 4; i++)
#pragma unroll
        for (int j = 0; j < 4; j++)
#pragma unroll
            for (int k = 0; k < 4; k++) acc[i][j][k] = 0.f;

    gemm_load_chunk(g, 0, kStart, K_ld, Ahi, Alo, Bhi, Blo, Nact);
    cp_commit();
    if (1 < nch) gemm_load_chunk(g, 1, kStart + 32, K_ld, Ahi, Alo, Bhi, Blo, Nact);
    cp_commit();

    for (int c = 0; c < nch; ++c) {
        cp_wait<1>();
        __syncthreads();
        if (c + 2 < nch)
            gemm_load_chunk(g, (c + 2) % NSTAGE, kStart + ((c + 2) << 5), K_ld, Ahi, Alo, Bhi, Blo, Nact);
        cp_commit();
        gemm_compute_chunk(g, c % NSTAGE, acc);
    }

    const int gid = g.lane >> 2;
    const int tig = g.lane & 3;
#pragma unroll
    for (int i = 0; i < 4; ++i) {
        const int row = g.bm + g.wm * 64 + i * 16 + gid;
#pragma unroll
        for (int j = 0; j < 4; ++j) {
            const int col = g.bn + g.wn * 32 + j * 8 + tig * 2;
            if (col < Nact) {
                *(float2*)&C[(size_t)row * ldc + col]       = make_float2(acc[i][j][0], acc[i][j][1]);
                *(float2*)&C[(size_t)(row + 8) * ldc + col] = make_float2(acc[i][j][2], acc[i][j][3]);
            }
        }
    }
}

__global__ void __launch_bounds__(256, 2) k_gemm_cat(
    const __nv_bfloat16* __restrict__ A0hi, const __nv_bfloat16* __restrict__ A0lo,
    const __nv_bfloat16* __restrict__ A1hi, const __nv_bfloat16* __restrict__ A1lo,
    const __nv_bfloat16* __restrict__ B0hi, const __nv_bfloat16* __restrict__ B0lo,
    const __nv_bfloat16* __restrict__ B1hi, const __nv_bfloat16* __restrict__ B1lo,
    float* __restrict__ C, int Kh, int Nact, int ldc)
{
    extern __shared__ __align__(1024) char smem[];
    GemmCtx g;
    gemm_init(g, smem);
    const int nch_h = Kh >> 5;
    const int nch = nch_h * 2;

    float acc[4][4][4];
#pragma unroll
    for (int i = 0; i < 4; i++)
#pragma unroll
        for (int j = 0; j < 4; j++)
#pragma unroll
            for (int k = 0; k < 4; k++) acc[i][j][k] = 0.f;

    auto load = [&](int c, int s) {
        if (c < nch_h)
            gemm_load_chunk(g, s, c << 5, Kh, A0hi, A0lo, B0hi, B0lo, Nact);
        else
            gemm_load_chunk(g, s, (c - nch_h) << 5, Kh, A1hi, A1lo, B1hi, B1lo, Nact);
    };

    load(0, 0);
    cp_commit();
    if (1 < nch) load(1, 1);
    cp_commit();

    for (int c = 0; c < nch; ++c) {
        cp_wait<1>();
        __syncthreads();
        if (c + 2 < nch) load(c + 2, (c + 2) % NSTAGE);
        cp_commit();
        gemm_compute_chunk(g, c % NSTAGE, acc);
    }

    const int gid = g.lane >> 2;
    const int tig = g.lane & 3;
#pragma unroll
    for (int i = 0; i < 4; ++i) {
        const int row = g.bm + g.wm * 64 + i * 16 + gid;
#pragma unroll
        for (int j = 0; j < 4; ++j) {
            const int col = g.bn + g.wn * 32 + j * 8 + tig * 2;
            if (col < Nact) {
                *(float2*)&C[(size_t)row * ldc + col]       = make_float2(acc[i][j][0], acc[i][j][1]);
                *(float2*)&C[(size_t)(row + 8) * ldc + col] = make_float2(acc[i][j][2], acc[i][j][3]);
            }
        }
    }
}

// ============================================================================
// k_reduce_proj2: g_proj = sum of 2 split-K partials; cols<64 also -> dtr hi/lo
// ============================================================================
__global__ void k_reduce_proj2() {
    size_t idx = (size_t)blockIdx.x * blockDim.x + threadIdx.x;
    const size_t total = (size_t)2 * M_ROWS * 96;
    if (idx >= total) return;
    const int dir = (int)(idx / ((size_t)M_ROWS * 96));
    const size_t off = idx % ((size_t)M_ROWS * 96);
    const float* base = g_proj_part + (size_t)dir * 2 * M_ROWS * 96;
    float v = base[off] + base[off + (size_t)M_ROWS * 96];
    g_proj[idx] = v;
    const int col = (int)(off % 96);
    if (col < DR) {
        const size_t row = off / 96;
        __nv_bfloat16 h, l;
        split2(v, h, l);
        const size_t d = ((size_t)dir * M_ROWS + row) * DR + col;
        g_dtr_hi[d] = h;
        g_dtr_lo[d] = l;
    }
}

// ============================================================================
// fp32 -> bf16 hi/lo conversions (two launches)
// ============================================================================
#define N4_X   2097152u
#define N4_INW 2097152u
#define N4_A   (N4_X + N4_INW)
#define N4_XW  98304u
#define N4_DTW 65536u
#define N4_OW  1048576u
#define N4_B   (N4_XW + N4_DTW + N4_OW)

__global__ void k_cvt_a(const float4* __restrict__ x, const float4* __restrict__ inw) {
    uint32_t i = blockIdx.x * blockDim.x + threadIdx.x;
    if (i >= N4_A) return;
    const float4* src;
    __nv_bfloat16 *hi, *lo;
    uint32_t off = i;
    if (i < N4_X) { src = x;   hi = g_x_hi;   lo = g_x_lo; }
    else { off -= N4_X; src = inw; hi = g_inw_hi; lo = g_inw_lo; }
    float4 v = src[off];
    __nv_bfloat16 h0, h1, h2, h3, l0, l1, l2, l3;
    split2(v.x, h0, l0); split2(v.y, h1, l1); split2(v.z, h2, l2); split2(v.w, h3, l3);
    __nv_bfloat162* H = (__nv_bfloat162*)hi;
    __nv_bfloat162* L = (__nv_bfloat162*)lo;
    H[2 * (size_t)off]     = __nv_bfloat162(h0, h1);
    H[2 * (size_t)off + 1] = __nv_bfloat162(h2, h3);
    L[2 * (size_t)off]     = __nv_bfloat162(l0, l1);
    L[2 * (size_t)off + 1] = __nv_bfloat162(l2, l3);
}

__global__ void k_cvt_b(const float4* __restrict__ xw, const float4* __restrict__ dtw,
                        const float4* __restrict__ ow) {
    uint32_t i = blockIdx.x * blockDim.x + threadIdx.x;
    if (i >= N4_B) return;
    const float4* src;
    __nv_bfloat16 *hi, *lo;
    uint32_t off = i;
    if (i < N4_XW)                      { src = xw;  hi = g_xw_hi;  lo = g_xw_lo; }
    else if ((off -= N4_XW) < N4_DTW)   { src = dtw; hi = g_dtw_hi; lo = g_dtw_lo; }
    else { off -= N4_DTW;                 src = ow;  hi = g_ow_hi;  lo = g_ow_lo; }
    float4 v = src[off];
    __nv_bfloat16 h0, h1, h2, h3, l0, l1, l2, l3;
    split2(v.x, h0, l0); split2(v.y, h1, l1); split2(v.z, h2, l2); split2(v.w, h3, l3);
    __nv_bfloat162* H = (__nv_bfloat162*)hi;
    __nv_bfloat162* L = (__nv_bfloat162*)lo;
    H[2 * (size_t)off]     = __nv_bfloat162(h0, h1);
    H[2 * (size_t)off + 1] = __nv_bfloat162(h2, h3);
    L[2 * (size_t)off]     = __nv_bfloat162(l0, l1);
    L[2 * (size_t)off + 1] = __nv_bfloat162(l2, l3);
}

// ============================================================================
// Depthwise conv + SiLU v3 (R14 winner) — FROZEN
// ============================================================================
#define CONV_THREADS ((size_t)2 * BSZ * (L_SEQ / 4) * (DI / 4))

__global__ void __launch_bounds__(256) k_conv(const float* __restrict__ cw,
                                              const float* __restrict__ cb) {
    const size_t idx = (size_t)blockIdx.x * 256 + threadIdx.x;
    if (idx >= CONV_THREADS) return;
    const int eg  = (int)(idx & (DI / 4 - 1));
    size_t r      = idx >> 9;
    const int lb  = (int)(r & (L_SEQ / 4 - 1));
    r >>= 9;
    const int b   = (int)(r & 3);
    const int dir = (int)(r >> 2);
    const int e   = eg * 4;
    const int l0  = lb * 4;

    const float4* wv = (const float4*)(cw + ((size_t)dir * DI + e) * 4);
    float4 wc[4];
#pragma unroll
    for (int c = 0; c < 4; c++) wc[c] = wv[c];
    float w[4][4];
#pragma unroll
    for (int c = 0; c < 4; c++) {
        const float t0 = wc[c].x, t1 = wc[c].y, t2 = wc[c].z, t3 = wc[c].w;
        if (dir == 0) { w[0][c] = t0; w[1][c] = t1; w[2][c] = t2; w[3][c] = t3; }
        else          { w[0][c] = t3; w[1][c] = t2; w[2][c] = t1; w[3][c] = t0; }
    }
    const float4 bias = *(const float4*)(cb + dir * DI + e);

    const int base = (dir == 0) ? (l0 - 3) : l0;
    const size_t xibase = (size_t)(b * L_SEQ) * 8192 + (size_t)dir * 4096 + e;
    float4 row[7];
#pragma unroll
    for (int i = 0; i < 7; i++) {
        const int tl = base + i;
        row[i] = (tl >= 0 && tl < L_SEQ) ? *(const float4*)(g_xz + xibase + (size_t)tl * 8192)
                                         : make_float4(0.f, 0.f, 0.f, 0.f);
    }

    const size_t obase = ((size_t)dir * M_ROWS + (size_t)b * L_SEQ + l0) * DI + e;
#pragma unroll
    for (int u = 0; u < 4; u++) {
        float4 acc = bias;
#pragma unroll
        for (int j = 0; j < 4; j++) {
            const float4 xi = row[u + j];
            acc.x = fmaf(w[j][0], xi.x, acc.x);
            acc.y = fmaf(w[j][1], xi.y, acc.y);
            acc.z = fmaf(w[j][2], xi.z, acc.z);
            acc.w = fmaf(w[j][3], xi.w, acc.w);
        }
        const float xc0 = acc.x / (1.f + __expf(-acc.x));
        const float xc1 = acc.y / (1.f + __expf(-acc.y));
        const float xc2 = acc.z / (1.f + __expf(-acc.z));
        const float xc3 = acc.w / (1.f + __expf(-acc.w));
        __nv_bfloat16 h0, h1, h2, h3, lo0, lo1, lo2, lo3;
        split2(xc0, h0, lo0); split2(xc1, h1, lo1);
        split2(xc2, h2, lo2); split2(xc3, h3, lo3);
        const size_t o = obase + (size_t)u * DI;
        __nv_bfloat162 hp0(h0, h1), hp1(h2, h3), lp0(lo0, lo1), lp1(lo2, lo3);
        *(uint2*)(g_xc_hi + o) = make_uint2(*(uint32_t*)&hp0, *(uint32_t*)&hp1);
        *(uint2*)(g_xc_lo + o) = make_uint2(*(uint32_t*)&lp0, *(uint32_t*)&lp1);
    }
}

// ============================================================================
// Chunked selective scan.
// tau = scan-time index 0..2047; tt = dir ? L-1-tau : tau.
// Chunk c covers tau in [c*512, (c+1)*512).
// Pass 1 (chunks 0..2): P[s] = prod dA, hl[s] = local scan (h_in = 0).
// Combine: h_in[c+1] = P[c]*h_in[c] + hl[c],  h_in[0] = 0.
// Pass 2 (all 4 chunks): full scan seeded with h_in; identical fma chain.
// ============================================================================
__global__ void __launch_bounds__(128) k_scan1(const float* __restrict__ dt_b,
                                               const float* __restrict__ A_log) {
    const int tid  = threadIdx.x;
    const int lane = tid & 31;
    const int warp = tid >> 5;
    const int dir  = blockIdx.z;
    const int b    = blockIdx.y / 3;
    const int c    = blockIdx.y % 3;
    const int e    = blockIdx.x * 128 + tid;
    const int tau0 = c * SCL;

    __shared__ float sB[4][16];

    float a[16];
#pragma unroll
    for (int s = 0; s < 16; s++)
        a[s] = -__expf(A_log[((size_t)dir * DI + e) * 16 + s]);

    const float bias = dt_b[dir * DI + e];

    float P[16], hl[16];
#pragma unroll
    for (int s = 0; s < 16; s++) { P[s] = 1.f; hl[s] = 0.f; }

    const size_t base_de   = (size_t)dir * M_ROWS * DI;
    const size_t proj_base = (size_t)dir * M_ROWS * 96;
    const size_t brow      = (size_t)b * L_SEQ;

    float rbc[4], rdt[4], rxh[4], rxl[4];
#pragma unroll
    for (int p = 0; p < 4; p++) {
        const int tau = tau0 + p;
        const int tt = dir ? (L_SEQ - 1 - tau) : tau;
        const size_t m = brow + tt;
        rbc[p] = g_proj[proj_base + m * 96 + 64 + lane];
        rdt[p] = g_dt[base_de + m * DI + e];
        rxh[p] = __bfloat162float(g_xc_hi[base_de + m * DI + e]);
        rxl[p] = __bfloat162float(g_xc_lo[base_de + m * DI + e]);
    }

    for (int t0 = tau0; t0 < tau0 + SCL; t0 += 4) {
#pragma unroll
        for (int u = 0; u < 4; u++) {
            const int tau = t0 + u;
            const float bc = rbc[u], dtv = rdt[u], xh = rxh[u], xl = rxl[u];

            const int tp = tau + 4;
            if (tp < tau0 + SCL) {
                const int tq = dir ? (L_SEQ - 1 - tp) : tp;
                const size_t mp = brow + tq;
                rbc[u] = g_proj[proj_base + mp * 96 + 64 + lane];
                rdt[u] = g_dt[base_de + mp * DI + e];
                rxh[u] = __bfloat162float(g_xc_hi[base_de + mp * DI + e]);
                rxl[u] = __bfloat162float(g_xc_lo[base_de + mp * DI + e]);
            }

            if (lane < 16) sB[warp][lane] = bc;
            __syncwarp();

            const float v   = dtv + bias;
            const float dt  = (v > 15.f) ? v : log1pf(__expf(v));
            const float x   = xh + xl;
            const float dtx = dt * x;

#pragma unroll
            for (int s = 0; s < 16; s++) {
                float dA = __expf(dt * a[s]);
                P[s] *= dA;
                hl[s] = fmaf(hl[s], dA, dtx * sB[warp][s]);
            }
            __syncwarp();
        }
    }

    const size_t obase = ((((size_t)dir * 4 + b) * 3 + c) * 16) * 2048 + e;
#pragma unroll
    for (int s = 0; s < 16; s++) {
        g_hP[obase + (size_t)s * 2048] = P[s];
        g_hL[obase + (size_t)s * 2048] = hl[s];
    }
}

__global__ void k_scomb() {
    const uint32_t idx = blockIdx.x * blockDim.x + threadIdx.x;
    if (idx >= 2u * 4 * 16 * 2048) return;
    const int e = idx & 2047;
    const int s = (idx >> 11) & 15;
    const int b = (idx >> 15) & 3;
    const int dir = idx >> 17;
    float h = 0.f;
#pragma unroll
    for (int c = 0; c < 3; c++) {
        const size_t base = ((((size_t)dir * 4 + b) * 3 + c) * 16 + s) * 2048 + e;
        h = fmaf(g_hP[base], h, g_hL[base]);
        g_hin[base] = h;             // h_in for chunk c+1
    }
}

__global__ void __launch_bounds__(128) k_scan2(const float* __restrict__ dt_b,
                                               const float* __restrict__ A_log,
                                               const float* __restrict__ Dp) {
    const int tid  = threadIdx.x;
    const int lane = tid & 31;
    const int warp = tid >> 5;
    const int dir  = blockIdx.z;
    const int b    = blockIdx.y >> 2;
    const int c    = blockIdx.y & 3;
    const int e    = blockIdx.x * 128 + tid;
    const int tau0 = c * SCL;

    __shared__ float sB[4][16], sC[4][16];

    float a[16];
#pragma unroll
    for (int s = 0; s < 16; s++)
        a[s] = -__expf(A_log[((size_t)dir * DI + e) * 16 + s]);

    const float bias  = dt_b[dir * DI + e];
    const float dcoef = Dp[dir * DI + e];

    float h[16];
    if (c == 0) {
#pragma unroll
        for (int s = 0; s < 16; s++) h[s] = 0.f;
    } else {
        const size_t ibase = ((((size_t)dir * 4 + b) * 3 + (c - 1)) * 16) * 2048 + e;
#pragma unroll
        for (int s = 0; s < 16; s++) h[s] = g_hin[ibase + (size_t)s * 2048];
    }

    const size_t base_de   = (size_t)dir * M_ROWS * DI;
    const size_t proj_base = (size_t)dir * M_ROWS * 96;
    const size_t brow      = (size_t)b * L_SEQ;

    float rbc[4], rdt[4], rxh[4], rxl[4], rz[4];
#pragma unroll
    for (int p = 0; p < 4; p++) {
        const int tau = tau0 + p;
        const int tt = dir ? (L_SEQ - 1 - tau) : tau;
        const size_t m = brow + tt;
        rbc[p] = g_proj[proj_base + m * 96 + 64 + lane];
        rdt[p] = g_dt[base_de + m * DI + e];
        rxh[p] = __bfloat162float(g_xc_hi[base_de + m * DI + e]);
        rxl[p] = __bfloat162float(g_xc_lo[base_de + m * DI + e]);
        rz[p]  = g_xz[m * 8192 + dir * 4096 + 2048 + e];
    }

    for (int t0 = tau0; t0 < tau0 + SCL; t0 += 4) {
#pragma unroll
        for (int u = 0; u < 4; u++) {
            const int tau = t0 + u;
            const int tt = dir ? (L_SEQ - 1 - tau) : tau;
            const size_t m = brow + tt;

            const float bc = rbc[u], dtv = rdt[u], xh = rxh[u], xl = rxl[u], zz = rz[u];

            const int tp = tau + 4;
            if (tp < tau0 + SCL) {
                const int tq = dir ? (L_SEQ - 1 - tp) : tp;
                const size_t mp = brow + tq;
                rbc[u] = g_proj[proj_base + mp * 96 + 64 + lane];
                rdt[u] = g_dt[base_de + mp * DI + e];
                rxh[u] = __bfloat162float(g_xc_hi[base_de + mp * DI + e]);
                rxl[u] = __bfloat162float(g_xc_lo[base_de + mp * DI + e]);
                rz[u]  = g_xz[mp * 8192 + dir * 4096 + 2048 + e];
            }

            if (lane < 16) sB[warp][lane] = bc; else sC[warp][lane - 16] = bc;
            __syncwarp();

            const float v   = dtv + bias;
            const float dt  = (v > 15.f) ? v : log1pf(__expf(v));
            const float x   = xh + xl;
            const float dtx = dt * x;

            float y = 0.f;
#pragma unroll
            for (int s = 0; s < 16; s++) {
                float dA = __expf(dt * a[s]);
                h[s] = fmaf(h[s], dA, dtx * sB[warp][s]);
                y    = fmaf(h[s], sC[warp][s], y);
            }
            const float yv  = fmaf(x, dcoef, y);
            const float sz  = zz / (1.f + __expf(-zz));
            const float out = yv * sz;
            __nv_bfloat16 hh, ll;
            split2(out, hh, ll);
            const size_t o = base_de + m * DI + e;
            g_y_hi[o] = hh;
            g_y_lo[o] = ll;
            __syncwarp();
        }
    }
}

// ============================================================================
extern "C" void kernel_launch(void* const* d_in, const int* in_sizes, int n_in,
                              void* d_out, int out_size) {
    const float* x      = (const float*)d_in[0];
    const float* in_w   = (const float*)d_in[1];
    const float* conv_w = (const float*)d_in[2];
    const float* conv_b = (const float*)d_in[3];
    const float* x_w    = (const float*)d_in[4];
    const float* dt_w   = (const float*)d_in[5];
    const float* dt_bv  = (const float*)d_in[6];
    const float* A_log  = (const float*)d_in[7];
    const float* Dp     = (const float*)d_in[8];
    const float* out_w  = (const float*)d_in[9];
    float* out = (float*)d_out;

    cudaFuncSetAttribute(k_gemm_z,   cudaFuncAttributeMaxDynamicSharedMemorySize, GEMM_SMEM);
    cudaFuncSetAttribute(k_gemm_cat, cudaFuncAttributeMaxDynamicSharedMemorySize, GEMM_SMEM);

    float *xz, *projpart, *dtv;
    __nv_bfloat16 *xhi, *xlo, *inwhi, *inwlo, *xwhi, *xwlo, *dtwhi, *dtwlo, *owhi, *owlo;
    __nv_bfloat16 *xchi, *xclo, *dtrhi, *dtrlo, *yhi, *ylo;
    cudaGetSymbolAddress((void**)&xz, g_xz);
    cudaGetSymbolAddress((void**)&projpart, g_proj_part);
    cudaGetSymbolAddress((void**)&dtv, g_dt);
    cudaGetSymbolAddress((void**)&xhi, g_x_hi);     cudaGetSymbolAddress((void**)&xlo, g_x_lo);
    cudaGetSymbolAddress((void**)&inwhi, g_inw_hi); cudaGetSymbolAddress((void**)&inwlo, g_inw_lo);
    cudaGetSymbolAddress((void**)&xwhi, g_xw_hi);   cudaGetSymbolAddress((void**)&xwlo, g_xw_lo);
    cudaGetSymbolAddress((void**)&dtwhi, g_dtw_hi); cudaGetSymbolAddress((void**)&dtwlo, g_dtw_lo);
    cudaGetSymbolAddress((void**)&owhi, g_ow_hi);   cudaGetSymbolAddress((void**)&owlo, g_ow_lo);
    cudaGetSymbolAddress((void**)&xchi, g_xc_hi);   cudaGetSymbolAddress((void**)&xclo, g_xc_lo);
    cudaGetSymbolAddress((void**)&dtrhi, g_dtr_hi); cudaGetSymbolAddress((void**)&dtrlo, g_dtr_lo);
    cudaGetSymbolAddress((void**)&yhi, g_y_hi);     cudaGetSymbolAddress((void**)&ylo, g_y_lo);

    // 0-1) conversions
    k_cvt_a<<<(N4_A + 255) / 256, 256>>>((const float4*)x, (const float4*)in_w);
    k_cvt_b<<<(N4_B + 255) / 256, 256>>>((const float4*)x_w, (const float4*)dt_w,
                                         (const float4*)out_w);

    // 2) in_proj: xz = x @ in_w^T  (M=8192, N=8192, K=1024)
    k_gemm_z<<<dim3(64, 64, 1), 256, GEMM_SMEM>>>(
        xhi, xlo, 0, inwhi, inwlo, 0,
        xz, 0, 0, DM, DM, 1, 8192, 8192);

    // 3) depthwise conv + silu -> xc hi/lo
    k_conv<<<(unsigned)((CONV_THREADS + 255) / 256), 256>>>(conv_w, conv_b);

    // 4) x_proj (both dirs, split-K x2)
    k_gemm_z<<<dim3(1, 64, 4), 256, GEMM_SMEM>>>(
        xchi, xclo, (size_t)M_ROWS * DI, xwhi, xwlo, (size_t)96 * DI,
        projpart, (size_t)2 * M_ROWS * 96, (size_t)M_ROWS * 96,
        DI, DI / 2, 2, 96, 96);

    // 5) reduce partials -> g_proj + dtr hi/lo
    k_reduce_proj2<<<(unsigned)(((size_t)2 * M_ROWS * 96 + 255) / 256), 256>>>();

    // 6) dt_proj (both dirs)
    k_gemm_z<<<dim3(16, 64, 2), 256, GEMM_SMEM>>>(
        dtrhi, dtrlo, (size_t)M_ROWS * DR, dtwhi, dtwlo, (size_t)DI * DR,
        dtv, (size_t)M_ROWS * DI, 0, DR, DR, 1, DI, DI);

    // 7) chunked selective scan: pass1 (chunks 0..2) -> combine -> pass2 (all)
    k_scan1<<<dim3(DI / 128, BSZ * 3, 2), 128>>>(dt_bv, A_log);
    k_scomb<<<(2u * 4 * 16 * 2048 + 255) / 256, 256>>>();
    k_scan2<<<dim3(DI / 128, BSZ * 4, 2), 128>>>(dt_bv, A_log, Dp);

    // 8) out_proj (both dirs, K-concatenated single pass)
    k_gemm_cat<<<dim3(8, 64, 1), 256, GEMM_SMEM>>>(
        yhi, ylo, yhi + (size_t)M_ROWS * DI, ylo + (size_t)M_ROWS * DI,
        owhi, owlo, owhi + (size_t)DM * DI, owlo + (size_t)DM * DI,
        out, DI, DM, DM);
}

// round 16
// speedup vs baseline: 2.7547x; 1.0384x over previous
#include <cuda_runtime.h>
#include <cuda_bf16.h>
#include <cstdint>
#include <math.h>

// Problem dims
#define L_SEQ 2048
#define BSZ   4
#define DM    1024
#define DI    2048
#define DS    16
#define DR    64
#define M_ROWS 8192   // BSZ * L_SEQ

// Scan chunking
#define SCH   16                // chunks
#define SCL   (L_SEQ / SCH)     // 128 steps per chunk
#define SCM   (SCH - 1)         // stored chunk states (0..14)

// ============================================================================
// Scratch (static device arrays)
// ============================================================================
__device__ float g_xz  [(size_t)M_ROWS * 8192];             // in_proj output (xi|z per dir)
__device__ float g_proj[2 * (size_t)M_ROWS * 96];           // x_proj output (dt_raw|B|C)
__device__ float g_proj_part[4 * (size_t)M_ROWS * 96];      // x_proj split-K partials [dir][ks]
__device__ float g_dt  [2 * (size_t)M_ROWS * DI];           // dt_proj output (pre-softplus)

// chunked-scan state buffers (chunks 0..SCM-1): [dir][b][c][s][e]
__device__ float g_hP [2 * 4 * SCM * 16 * 2048];
__device__ float g_hL [2 * 4 * SCM * 16 * 2048];
__device__ float g_hin[2 * 4 * SCM * 16 * 2048];            // h_in for chunks 1..SCH-1

// bf16 hi/lo operand planes
__device__ __nv_bfloat16 g_x_hi  [(size_t)M_ROWS * DM],  g_x_lo  [(size_t)M_ROWS * DM];
__device__ __nv_bfloat16 g_inw_hi[(size_t)8192 * DM],    g_inw_lo[(size_t)8192 * DM];
__device__ __nv_bfloat16 g_xw_hi [2 * 96 * (size_t)DI],  g_xw_lo [2 * 96 * (size_t)DI];
__device__ __nv_bfloat16 g_dtw_hi[2 * (size_t)DI * DR],  g_dtw_lo[2 * (size_t)DI * DR];
__device__ __nv_bfloat16 g_ow_hi [2 * (size_t)DM * DI],  g_ow_lo [2 * (size_t)DM * DI];
__device__ __nv_bfloat16 g_xc_hi [2 * (size_t)M_ROWS * DI], g_xc_lo[2 * (size_t)M_ROWS * DI];
__device__ __nv_bfloat16 g_dtr_hi[2 * (size_t)M_ROWS * DR], g_dtr_lo[2 * (size_t)M_ROWS * DR];
__device__ __nv_bfloat16 g_y_hi  [2 * (size_t)M_ROWS * DI], g_y_lo [2 * (size_t)M_ROWS * DI];

__device__ __forceinline__ void split2(float v, __nv_bfloat16& h, __nv_bfloat16& l) {
    h = __float2bfloat16_rn(v);
    l = __float2bfloat16_rn(v - __bfloat162float(h));
}

// ============================================================================
// PTX helpers (sm_80-class only: valid on base sm_103 target)
// ============================================================================
__device__ __forceinline__ uint32_t smem_u32(const void* p) {
    uint32_t a;
    asm("{ .reg .u64 t; cvta.to.shared.u64 t, %1; cvt.u32.u64 %0, t; }" : "=r"(a) : "l"(p));
    return a;
}
__device__ __forceinline__ void cpa16(uint32_t dst, const void* src) {
    asm volatile("cp.async.cg.shared.global [%0], [%1], 16;" :: "r"(dst), "l"(src) : "memory");
}
__device__ __forceinline__ void cpa16p(uint32_t dst, const void* src, int sz) {
    asm volatile("cp.async.cg.shared.global [%0], [%1], 16, %2;" :: "r"(dst), "l"(src), "r"(sz) : "memory");
}
__device__ __forceinline__ void cp_commit() {
    asm volatile("cp.async.commit_group;" ::: "memory");
}
template <int N>
__device__ __forceinline__ void cp_wait() {
    asm volatile("cp.async.wait_group %0;" :: "n"(N) : "memory");
}
__device__ __forceinline__ void ldsm_x4(uint32_t* r, uint32_t addr) {
    asm volatile("ldmatrix.sync.aligned.m8n8.x4.shared.b16 {%0,%1,%2,%3}, [%4];"
                 : "=r"(r[0]), "=r"(r[1]), "=r"(r[2]), "=r"(r[3]) : "r"(addr));
}
__device__ __forceinline__ void ldsm_x2(uint32_t* r, uint32_t addr) {
    asm volatile("ldmatrix.sync.aligned.m8n8.x2.shared.b16 {%0,%1}, [%2];"
                 : "=r"(r[0]), "=r"(r[1]) : "r"(addr));
}
__device__ __forceinline__ void mma_bf16(float* d, const uint32_t* a, const uint32_t* b) {
    asm volatile("mma.sync.aligned.m16n8k16.row.col.f32.bf16.bf16.f32 "
                 "{%0,%1,%2,%3}, {%4,%5,%6,%7}, {%8,%9}, {%0,%1,%2,%3};"
                 : "+f"(d[0]), "+f"(d[1]), "+f"(d[2]), "+f"(d[3])
                 : "r"(a[0]), "r"(a[1]), "r"(a[2]), "r"(a[3]), "r"(b[0]), "r"(b[1]));
}

// ============================================================================
// GEMM machinery (R11 WINNER config) — FROZEN
// ============================================================================
#define PLANE 8192
#define OFF_AH 0
#define OFF_AL (PLANE)
#define OFF_BH (2 * PLANE)
#define OFF_BL (3 * PLANE)
#define STAGE  (4 * PLANE)
#define NSTAGE 3
#define GEMM_SMEM (NSTAGE * STAGE)
#define SW64(o) ((o) ^ (((o) >> 3) & 0x30))

struct GemmCtx {
    uint32_t sb;
    int tid, lane, warp, wm, wn, bm, bn;
    uint32_t a_lane_off, b_lane_off;
};

__device__ __forceinline__ void gemm_init(GemmCtx& g, char* smem) {
    g.sb = smem_u32(smem);
    g.tid = threadIdx.x;
    g.lane = g.tid & 31;
    g.warp = g.tid >> 5;
    g.wm = g.warp >> 2;
    g.wn = g.warp & 3;
    g.bm = blockIdx.y * 128;
    g.bn = blockIdx.x * 128;
    g.a_lane_off = (uint32_t)((g.lane & 15) * 64 + (g.lane >> 4) * 16);
    g.b_lane_off = (uint32_t)((g.lane & 7) * 64 + ((g.lane >> 3) & 1) * 16);
}

__device__ __forceinline__ void gemm_load_chunk(
    const GemmCtx& g, int s, int k0, int K,
    const __nv_bfloat16* __restrict__ Ahi, const __nv_bfloat16* __restrict__ Alo,
    const __nv_bfloat16* __restrict__ Bhi, const __nv_bfloat16* __restrict__ Blo,
    int Nact)
{
    const uint32_t st = g.sb + s * STAGE;
#pragma unroll
    for (int it = 0; it < 2; ++it) {
        const int i   = g.tid + it * 256;
        const int row = i >> 2;
        const int c8  = (i & 3) * 8;
        const uint32_t so = SW64((uint32_t)(row * 64 + c8 * 2));
        const size_t ga = (size_t)(g.bm + row) * K + k0 + c8;
        cpa16(st + OFF_AH + so, Ahi + ga);
        cpa16(st + OFF_AL + so, Alo + ga);
        const size_t gb = (size_t)(g.bn + row) * K + k0 + c8;
        const int sz = (g.bn + row < Nact) ? 16 : 0;
        cpa16p(st + OFF_BH + so, Bhi + gb, sz);
        cpa16p(st + OFF_BL + so, Blo + gb, sz);
    }
}

__device__ __forceinline__ void gemm_compute_chunk(const GemmCtx& g, int s, float acc[4][4][4]) {
    const uint32_t st = g.sb + s * STAGE;
#pragma unroll
    for (int k16 = 0; k16 < 32; k16 += 16) {
        const uint32_t ak = g.a_lane_off + k16 * 2;
        const uint32_t bk = g.b_lane_off + k16 * 2;
        uint32_t bh[4][2], bl[4][2];
#pragma unroll
        for (int j = 0; j < 4; ++j) {
            const uint32_t bo = (uint32_t)((g.wn * 32 + j * 8) * 64) + bk;
            const uint32_t bos = SW64(bo);
            ldsm_x2(bh[j], st + OFF_BH + bos);
            ldsm_x2(bl[j], st + OFF_BL + bos);
        }
#pragma unroll
        for (int i = 0; i < 4; ++i) {
            const uint32_t ao = (uint32_t)((g.wm * 64 + i * 16) * 64) + ak;
            const uint32_t aos = SW64(ao);
            uint32_t ah[4], al[4];
            ldsm_x4(ah, st + OFF_AH + aos);
            ldsm_x4(al, st + OFF_AL + aos);
#pragma unroll
            for (int j = 0; j < 4; ++j) mma_bf16(acc[i][j], ah, bh[j]);
#pragma unroll
            for (int j = 0; j < 4; ++j) mma_bf16(acc[i][j], ah, bl[j]);
#pragma unroll
            for (int j = 0; j < 4; ++j) mma_bf16(acc[i][j], al, bh[j]);
        }
    }
}

__global__ void __launch_bounds__(256, 2) k_gemm_z(
    const __nv_bfloat16* __restrict__ Ahi, const __nv_bfloat16* __restrict__ Alo, size_t aStride,
    const __nv_bfloat16* __restrict__ Bhi, const __nv_bfloat16* __restrict__ Blo, size_t bStride,
    float* __restrict__ C, size_t cStride, size_t partStride,
    int K_ld, int kLen, int nsplit, int Nact, int ldc)
{
    extern __shared__ __align__(1024) char smem[];
    GemmCtx g;
    gemm_init(g, smem);
    const int dir = blockIdx.z / nsplit;
    const int ks  = blockIdx.z % nsplit;
    const int kStart = ks * kLen;
    Ahi += (size_t)dir * aStride; Alo += (size_t)dir * aStride;
    Bhi += (size_t)dir * bStride; Blo += (size_t)dir * bStride;
    C   += (size_t)dir * cStride + (size_t)ks * partStride;
    const int nch = kLen >> 5;

    float acc[4][4][4];
#pragma unroll
    for (int i = 0; i < 4; i++)
#pragma unroll
        for (int j = 0; j < 4; j++)
#pragma unroll
            for (int k = 0; k < 4; k++) acc[i][j][k] = 0.f;

    gemm_load_chunk(g, 0, kStart, K_ld, Ahi, Alo, Bhi, Blo, Nact);
    cp_commit();
    if (1 < nch) gemm_load_chunk(g, 1, kStart + 32, K_ld, Ahi, Alo, Bhi, Blo, Nact);
    cp_commit();

    for (int c = 0; c < nch; ++c) {
        cp_wait<1>();
        __syncthreads();
        if (c + 2 < nch)
            gemm_load_chunk(g, (c + 2) % NSTAGE, kStart + ((c + 2) << 5), K_ld, Ahi, Alo, Bhi, Blo, Nact);
        cp_commit();
        gemm_compute_chunk(g, c % NSTAGE, acc);
    }

    const int gid = g.lane >> 2;
    const int tig = g.lane & 3;
#pragma unroll
    for (int i = 0; i < 4; ++i) {
        const int row = g.bm + g.wm * 64 + i * 16 + gid;
#pragma unroll
        for (int j = 0; j < 4; ++j) {
            const int col = g.bn + g.wn * 32 + j * 8 + tig * 2;
            if (col < Nact) {
                *(float2*)&C[(size_t)row * ldc + col]       = make_float2(acc[i][j][0], acc[i][j][1]);
                *(float2*)&C[(size_t)(row + 8) * ldc + col] = make_float2(acc[i][j][2], acc[i][j][3]);
            }
        }
    }
}

__global__ void __launch_bounds__(256, 2) k_gemm_cat(
    const __nv_bfloat16* __restrict__ A0hi, const __nv_bfloat16* __restrict__ A0lo,
    const __nv_bfloat16* __restrict__ A1hi, const __nv_bfloat16* __restrict__ A1lo,
    const __nv_bfloat16* __restrict__ B0hi, const __nv_bfloat16* __restrict__ B0lo,
    const __nv_bfloat16* __restrict__ B1hi, const __nv_bfloat16* __restrict__ B1lo,
    float* __restrict__ C, int Kh, int Nact, int ldc)
{
    extern __shared__ __align__(1024) char smem[];
    GemmCtx g;
    gemm_init(g, smem);
    const int nch_h = Kh >> 5;
    const int nch = nch_h * 2;

    float acc[4][4][4];
#pragma unroll
    for (int i = 0; i < 4; i++)
#pragma unroll
        for (int j = 0; j < 4; j++)
#pragma unroll
            for (int k = 0; k < 4; k++) acc[i][j][k] = 0.f;

    auto load = [&](int c, int s) {
        if (c < nch_h)
            gemm_load_chunk(g, s, c << 5, Kh, A0hi, A0lo, B0hi, B0lo, Nact);
        else
            gemm_load_chunk(g, s, (c - nch_h) << 5, Kh, A1hi, A1lo, B1hi, B1lo, Nact);
    };

    load(0, 0);
    cp_commit();
    if (1 < nch) load(1, 1);
    cp_commit();

    for (int c = 0; c < nch; ++c) {
        cp_wait<1>();
        __syncthreads();
        if (c + 2 < nch) load(c + 2, (c + 2) % NSTAGE);
        cp_commit();
        gemm_compute_chunk(g, c % NSTAGE, acc);
    }

    const int gid = g.lane >> 2;
    const int tig = g.lane & 3;
#pragma unroll
    for (int i = 0; i < 4; ++i) {
        const int row = g.bm + g.wm * 64 + i * 16 + gid;
#pragma unroll
        for (int j = 0; j < 4; ++j) {
            const int col = g.bn + g.wn * 32 + j * 8 + tig * 2;
            if (col < Nact) {
                *(float2*)&C[(size_t)row * ldc + col]       = make_float2(acc[i][j][0], acc[i][j][1]);
                *(float2*)&C[(size_t)(row + 8) * ldc + col] = make_float2(acc[i][j][2], acc[i][j][3]);
            }
        }
    }
}

// ============================================================================
// k_reduce_proj2: g_proj = sum of 2 split-K partials; cols<64 also -> dtr hi/lo
// ============================================================================
__global__ void k_reduce_proj2() {
    size_t idx = (size_t)blockIdx.x * blockDim.x + threadIdx.x;
    const size_t total = (size_t)2 * M_ROWS * 96;
    if (idx >= total) return;
    const int dir = (int)(idx / ((size_t)M_ROWS * 96));
    const size_t off = idx % ((size_t)M_ROWS * 96);
    const float* base = g_proj_part + (size_t)dir * 2 * M_ROWS * 96;
    float v = base[off] + base[off + (size_t)M_ROWS * 96];
    g_proj[idx] = v;
    const int col = (int)(off % 96);
    if (col < DR) {
        const size_t row = off / 96;
        __nv_bfloat16 h, l;
        split2(v, h, l);
        const size_t d = ((size_t)dir * M_ROWS + row) * DR + col;
        g_dtr_hi[d] = h;
        g_dtr_lo[d] = l;
    }
}

// ============================================================================
// fp32 -> bf16 hi/lo conversions (two launches)
// ============================================================================
#define N4_X   2097152u
#define N4_INW 2097152u
#define N4_A   (N4_X + N4_INW)
#define N4_XW  98304u
#define N4_DTW 65536u
#define N4_OW  1048576u
#define N4_B   (N4_XW + N4_DTW + N4_OW)

__global__ void k_cvt_a(const float4* __restrict__ x, const float4* __restrict__ inw) {
    uint32_t i = blockIdx.x * blockDim.x + threadIdx.x;
    if (i >= N4_A) return;
    const float4* src;
    __nv_bfloat16 *hi, *lo;
    uint32_t off = i;
    if (i < N4_X) { src = x;   hi = g_x_hi;   lo = g_x_lo; }
    else { off -= N4_X; src = inw; hi = g_inw_hi; lo = g_inw_lo; }
    float4 v = src[off];
    __nv_bfloat16 h0, h1, h2, h3, l0, l1, l2, l3;
    split2(v.x, h0, l0); split2(v.y, h1, l1); split2(v.z, h2, l2); split2(v.w, h3, l3);
    __nv_bfloat162* H = (__nv_bfloat162*)hi;
    __nv_bfloat162* L = (__nv_bfloat162*)lo;
    H[2 * (size_t)off]     = __nv_bfloat162(h0, h1);
    H[2 * (size_t)off + 1] = __nv_bfloat162(h2, h3);
    L[2 * (size_t)off]     = __nv_bfloat162(l0, l1);
    L[2 * (size_t)off + 1] = __nv_bfloat162(l2, l3);
}

__global__ void k_cvt_b(const float4* __restrict__ xw, const float4* __restrict__ dtw,
                        const float4* __restrict__ ow) {
    uint32_t i = blockIdx.x * blockDim.x + threadIdx.x;
    if (i >= N4_B) return;
    const float4* src;
    __nv_bfloat16 *hi, *lo;
    uint32_t off = i;
    if (i < N4_XW)                      { src = xw;  hi = g_xw_hi;  lo = g_xw_lo; }
    else if ((off -= N4_XW) < N4_DTW)   { src = dtw; hi = g_dtw_hi; lo = g_dtw_lo; }
    else { off -= N4_DTW;                 src = ow;  hi = g_ow_hi;  lo = g_ow_lo; }
    float4 v = src[off];
    __nv_bfloat16 h0, h1, h2, h3, l0, l1, l2, l3;
    split2(v.x, h0, l0); split2(v.y, h1, l1); split2(v.z, h2, l2); split2(v.w, h3, l3);
    __nv_bfloat162* H = (__nv_bfloat162*)hi;
    __nv_bfloat162* L = (__nv_bfloat162*)lo;
    H[2 * (size_t)off]     = __nv_bfloat162(h0, h1);
    H[2 * (size_t)off + 1] = __nv_bfloat162(h2, h3);
    L[2 * (size_t)off]     = __nv_bfloat162(l0, l1);
    L[2 * (size_t)off + 1] = __nv_bfloat162(l2, l3);
}

// ============================================================================
// Depthwise conv + SiLU v3 (R14 winner) — FROZEN
// ============================================================================
#define CONV_THREADS ((size_t)2 * BSZ * (L_SEQ / 4) * (DI / 4))

__global__ void __launch_bounds__(256) k_conv(const float* __restrict__ cw,
                                              const float* __restrict__ cb) {
    const size_t idx = (size_t)blockIdx.x * 256 + threadIdx.x;
    if (idx >= CONV_THREADS) return;
    const int eg  = (int)(idx & (DI / 4 - 1));
    size_t r      = idx >> 9;
    const int lb  = (int)(r & (L_SEQ / 4 - 1));
    r >>= 9;
    const int b   = (int)(r & 3);
    const int dir = (int)(r >> 2);
    const int e   = eg * 4;
    const int l0  = lb * 4;

    const float4* wv = (const float4*)(cw + ((size_t)dir * DI + e) * 4);
    float4 wc[4];
#pragma unroll
    for (int c = 0; c < 4; c++) wc[c] = wv[c];
    float w[4][4];
#pragma unroll
    for (int c = 0; c < 4; c++) {
        const float t0 = wc[c].x, t1 = wc[c].y, t2 = wc[c].z, t3 = wc[c].w;
        if (dir == 0) { w[0][c] = t0; w[1][c] = t1; w[2][c] = t2; w[3][c] = t3; }
        else          { w[0][c] = t3; w[1][c] = t2; w[2][c] = t1; w[3][c] = t0; }
    }
    const float4 bias = *(const float4*)(cb + dir * DI + e);

    const int base = (dir == 0) ? (l0 - 3) : l0;
    const size_t xibase = (size_t)(b * L_SEQ) * 8192 + (size_t)dir * 4096 + e;
    float4 row[7];
#pragma unroll
    for (int i = 0; i < 7; i++) {
        const int tl = base + i;
        row[i] = (tl >= 0 && tl < L_SEQ) ? *(const float4*)(g_xz + xibase + (size_t)tl * 8192)
                                         : make_float4(0.f, 0.f, 0.f, 0.f);
    }

    const size_t obase = ((size_t)dir * M_ROWS + (size_t)b * L_SEQ + l0) * DI + e;
#pragma unroll
    for (int u = 0; u < 4; u++) {
        float4 acc = bias;
#pragma unroll
        for (int j = 0; j < 4; j++) {
            const float4 xi = row[u + j];
            acc.x = fmaf(w[j][0], xi.x, acc.x);
            acc.y = fmaf(w[j][1], xi.y, acc.y);
            acc.z = fmaf(w[j][2], xi.z, acc.z);
            acc.w = fmaf(w[j][3], xi.w, acc.w);
        }
        const float xc0 = acc.x / (1.f + __expf(-acc.x));
        const float xc1 = acc.y / (1.f + __expf(-acc.y));
        const float xc2 = acc.z / (1.f + __expf(-acc.z));
        const float xc3 = acc.w / (1.f + __expf(-acc.w));
        __nv_bfloat16 h0, h1, h2, h3, lo0, lo1, lo2, lo3;
        split2(xc0, h0, lo0); split2(xc1, h1, lo1);
        split2(xc2, h2, lo2); split2(xc3, h3, lo3);
        const size_t o = obase + (size_t)u * DI;
        __nv_bfloat162 hp0(h0, h1), hp1(h2, h3), lp0(lo0, lo1), lp1(lo2, lo3);
        *(uint2*)(g_xc_hi + o) = make_uint2(*(uint32_t*)&hp0, *(uint32_t*)&hp1);
        *(uint2*)(g_xc_lo + o) = make_uint2(*(uint32_t*)&lp0, *(uint32_t*)&lp1);
    }
}

// ============================================================================
// Chunked selective scan (SCH=16, SCL=128).
// tau = scan-time index; tt = dir ? L-1-tau : tau.
// Pass 1 (chunks 0..14): P[s] = prod dA, hl[s] = local scan (h_in = 0).
// Combine: h_in[c+1] = P[c]*h_in[c] + hl[c],  h_in[0] = 0.
// Pass 2 (all 16 chunks): full scan seeded with h_in; identical fma chain.
// ============================================================================
__global__ void __launch_bounds__(128) k_scan1(const float* __restrict__ dt_b,
                                               const float* __restrict__ A_log) {
    const int tid  = threadIdx.x;
    const int lane = tid & 31;
    const int warp = tid >> 5;
    const int dir  = blockIdx.z;
    const int b    = blockIdx.y / SCM;
    const int c    = blockIdx.y % SCM;
    const int e    = blockIdx.x * 128 + tid;
    const int tau0 = c * SCL;

    __shared__ float sB[4][16];

    float a[16];
#pragma unroll
    for (int s = 0; s < 16; s++)
        a[s] = -__expf(A_log[((size_t)dir * DI + e) * 16 + s]);

    const float bias = dt_b[dir * DI + e];

    float P[16], hl[16];
#pragma unroll
    for (int s = 0; s < 16; s++) { P[s] = 1.f; hl[s] = 0.f; }

    const size_t base_de   = (size_t)dir * M_ROWS * DI;
    const size_t proj_base = (size_t)dir * M_ROWS * 96;
    const size_t brow      = (size_t)b * L_SEQ;

    float rbc[4], rdt[4], rxh[4], rxl[4];
#pragma unroll
    for (int p = 0; p < 4; p++) {
        const int tau = tau0 + p;
        const int tt = dir ? (L_SEQ - 1 - tau) : tau;
        const size_t m = brow + tt;
        rbc[p] = g_proj[proj_base + m * 96 + 64 + lane];
        rdt[p] = g_dt[base_de + m * DI + e];
        rxh[p] = __bfloat162float(g_xc_hi[base_de + m * DI + e]);
        rxl[p] = __bfloat162float(g_xc_lo[base_de + m * DI + e]);
    }

    for (int t0 = tau0; t0 < tau0 + SCL; t0 += 4) {
#pragma unroll
        for (int u = 0; u < 4; u++) {
            const int tau = t0 + u;
            const float bc = rbc[u], dtv = rdt[u], xh = rxh[u], xl = rxl[u];

            const int tp = tau + 4;
            if (tp < tau0 + SCL) {
                const int tq = dir ? (L_SEQ - 1 - tp) : tp;
                const size_t mp = brow + tq;
                rbc[u] = g_proj[proj_base + mp * 96 + 64 + lane];
                rdt[u] = g_dt[base_de + mp * DI + e];
                rxh[u] = __bfloat162float(g_xc_hi[base_de + mp * DI + e]);
                rxl[u] = __bfloat162float(g_xc_lo[base_de + mp * DI + e]);
            }

            if (lane < 16) sB[warp][lane] = bc;
            __syncwarp();

            const float v   = dtv + bias;
            const float dt  = (v > 15.f) ? v : log1pf(__expf(v));
            const float x   = xh + xl;
            const float dtx = dt * x;

#pragma unroll
            for (int s = 0; s < 16; s++) {
                float dA = __expf(dt * a[s]);
                P[s] *= dA;
                hl[s] = fmaf(hl[s], dA, dtx * sB[warp][s]);
            }
            __syncwarp();
        }
    }

    const size_t obase = ((((size_t)dir * 4 + b) * SCM + c) * 16) * 2048 + e;
#pragma unroll
    for (int s = 0; s < 16; s++) {
        g_hP[obase + (size_t)s * 2048] = P[s];
        g_hL[obase + (size_t)s * 2048] = hl[s];
    }
}

__global__ void k_scomb() {
    const uint32_t idx = blockIdx.x * blockDim.x + threadIdx.x;
    if (idx >= 2u * 4 * 16 * 2048) return;
    const int e = idx & 2047;
    const int s = (idx >> 11) & 15;
    const int b = (idx >> 15) & 3;
    const int dir = idx >> 17;
    float h = 0.f;
#pragma unroll
    for (int c = 0; c < SCM; c++) {
        const size_t base = ((((size_t)dir * 4 + b) * SCM + c) * 16 + s) * 2048 + e;
        h = fmaf(g_hP[base], h, g_hL[base]);
        g_hin[base] = h;             // h_in for chunk c+1
    }
}

__global__ void __launch_bounds__(128) k_scan2(const float* __restrict__ dt_b,
                                               const float* __restrict__ A_log,
                                               const float* __restrict__ Dp) {
    const int tid  = threadIdx.x;
    const int lane = tid & 31;
    const int warp = tid >> 5;
    const int dir  = blockIdx.z;
    const int b    = blockIdx.y >> 4;
    const int c    = blockIdx.y & 15;
    const int e    = blockIdx.x * 128 + tid;
    const int tau0 = c * SCL;

    __shared__ float sB[4][16], sC[4][16];

    float a[16];
#pragma unroll
    for (int s = 0; s < 16; s++)
        a[s] = -__expf(A_log[((size_t)dir * DI + e) * 16 + s]);

    const float bias  = dt_b[dir * DI + e];
    const float dcoef = Dp[dir * DI + e];

    float h[16];
    if (c == 0) {
#pragma unroll
        for (int s = 0; s < 16; s++) h[s] = 0.f;
    } else {
        const size_t ibase = ((((size_t)dir * 4 + b) * SCM + (c - 1)) * 16) * 2048 + e;
#pragma unroll
        for (int s = 0; s < 16; s++) h[s] = g_hin[ibase + (size_t)s * 2048];
    }

    const size_t base_de   = (size_t)dir * M_ROWS * DI;
    const size_t proj_base = (size_t)dir * M_ROWS * 96;
    const size_t brow      = (size_t)b * L_SEQ;

    float rbc[4], rdt[4], rxh[4], rxl[4], rz[4];
#pragma unroll
    for (int p = 0; p < 4; p++) {
        const int tau = tau0 + p;
        const int tt = dir ? (L_SEQ - 1 - tau) : tau;
        const size_t m = brow + tt;
        rbc[p] = g_proj[proj_base + m * 96 + 64 + lane];
        rdt[p] = g_dt[base_de + m * DI + e];
        rxh[p] = __bfloat162float(g_xc_hi[base_de + m * DI + e]);
        rxl[p] = __bfloat162float(g_xc_lo[base_de + m * DI + e]);
        rz[p]  = g_xz[m * 8192 + dir * 4096 + 2048 + e];
    }

    for (int t0 = tau0; t0 < tau0 + SCL; t0 += 4) {
#pragma unroll
        for (int u = 0; u < 4; u++) {
            const int tau = t0 + u;
            const int tt = dir ? (L_SEQ - 1 - tau) : tau;
            const size_t m = brow + tt;

            const float bc = rbc[u], dtv = rdt[u], xh = rxh[u], xl = rxl[u], zz = rz[u];

            const int tp = tau + 4;
            if (tp < tau0 + SCL) {
                const int tq = dir ? (L_SEQ - 1 - tp) : tp;
                const size_t mp = brow + tq;
                rbc[u] = g_proj[proj_base + mp * 96 + 64 + lane];
                rdt[u] = g_dt[base_de + mp * DI + e];
                rxh[u] = __bfloat162float(g_xc_hi[base_de + mp * DI + e]);
                rxl[u] = __bfloat162float(g_xc_lo[base_de + mp * DI + e]);
                rz[u]  = g_xz[mp * 8192 + dir * 4096 + 2048 + e];
            }

            if (lane < 16) sB[warp][lane] = bc; else sC[warp][lane - 16] = bc;
            __syncwarp();

            const float v   = dtv + bias;
            const float dt  = (v > 15.f) ? v : log1pf(__expf(v));
            const float x   = xh + xl;
            const float dtx = dt * x;

            float y = 0.f;
#pragma unroll
            for (int s = 0; s < 16; s++) {
                float dA = __expf(dt * a[s]);
                h[s] = fmaf(h[s], dA, dtx * sB[warp][s]);
                y    = fmaf(h[s], sC[warp][s], y);
            }
            const float yv  = fmaf(x, dcoef, y);
            const float sz  = zz / (1.f + __expf(-zz));
            const float out = yv * sz;
            __nv_bfloat16 hh, ll;
            split2(out, hh, ll);
            const size_t o = base_de + m * DI + e;
            g_y_hi[o] = hh;
            g_y_lo[o] = ll;
            __syncwarp();
        }
    }
}

// ============================================================================
extern "C" void kernel_launch(void* const* d_in, const int* in_sizes, int n_in,
                              void* d_out, int out_size) {
    const float* x      = (const float*)d_in[0];
    const float* in_w   = (const float*)d_in[1];
    const float* conv_w = (const float*)d_in[2];
    const float* conv_b = (const float*)d_in[3];
    const float* x_w    = (const float*)d_in[4];
    const float* dt_w   = (const float*)d_in[5];
    const float* dt_bv  = (const float*)d_in[6];
    const float* A_log  = (const float*)d_in[7];
    const float* Dp     = (const float*)d_in[8];
    const float* out_w  = (const float*)d_in[9];
    float* out = (float*)d_out;

    cudaFuncSetAttribute(k_gemm_z,   cudaFuncAttributeMaxDynamicSharedMemorySize, GEMM_SMEM);
    cudaFuncSetAttribute(k_gemm_cat, cudaFuncAttributeMaxDynamicSharedMemorySize, GEMM_SMEM);

    float *xz, *projpart, *dtv;
    __nv_bfloat16 *xhi, *xlo, *inwhi, *inwlo, *xwhi, *xwlo, *dtwhi, *dtwlo, *owhi, *owlo;
    __nv_bfloat16 *xchi, *xclo, *dtrhi, *dtrlo, *yhi, *ylo;
    cudaGetSymbolAddress((void**)&xz, g_xz);
    cudaGetSymbolAddress((void**)&projpart, g_proj_part);
    cudaGetSymbolAddress((void**)&dtv, g_dt);
    cudaGetSymbolAddress((void**)&xhi, g_x_hi);     cudaGetSymbolAddress((void**)&xlo, g_x_lo);
    cudaGetSymbolAddress((void**)&inwhi, g_inw_hi); cudaGetSymbolAddress((void**)&inwlo, g_inw_lo);
    cudaGetSymbolAddress((void**)&xwhi, g_xw_hi);   cudaGetSymbolAddress((void**)&xwlo, g_xw_lo);
    cudaGetSymbolAddress((void**)&dtwhi, g_dtw_hi); cudaGetSymbolAddress((void**)&dtwlo, g_dtw_lo);
    cudaGetSymbolAddress((void**)&owhi, g_ow_hi);   cudaGetSymbolAddress((void**)&owlo, g_ow_lo);
    cudaGetSymbolAddress((void**)&xchi, g_xc_hi);   cudaGetSymbolAddress((void**)&xclo, g_xc_lo);
    cudaGetSymbolAddress((void**)&dtrhi, g_dtr_hi); cudaGetSymbolAddress((void**)&dtrlo, g_dtr_lo);
    cudaGetSymbolAddress((void**)&yhi, g_y_hi);     cudaGetSymbolAddress((void**)&ylo, g_y_lo);

    // 0-1) conversions
    k_cvt_a<<<(N4_A + 255) / 256, 256>>>((const float4*)x, (const float4*)in_w);
    k_cvt_b<<<(N4_B + 255) / 256, 256>>>((const float4*)x_w, (const float4*)dt_w,
                                         (const float4*)out_w);

    // 2) in_proj: xz = x @ in_w^T  (M=8192, N=8192, K=1024)
    k_gemm_z<<<dim3(64, 64, 1), 256, GEMM_SMEM>>>(
        xhi, xlo, 0, inwhi, inwlo, 0,
        xz, 0, 0, DM, DM, 1, 8192, 8192);

    // 3) depthwise conv + silu -> xc hi/lo
    k_conv<<<(unsigned)((CONV_THREADS + 255) / 256), 256>>>(conv_w, conv_b);

    // 4) x_proj (both dirs, split-K x2)
    k_gemm_z<<<dim3(1, 64, 4), 256, GEMM_SMEM>>>(
        xchi, xclo, (size_t)M_ROWS * DI, xwhi, xwlo, (size_t)96 * DI,
        projpart, (size_t)2 * M_ROWS * 96, (size_t)M_ROWS * 96,
        DI, DI / 2, 2, 96, 96);

    // 5) reduce partials -> g_proj + dtr hi/lo
    k_reduce_proj2<<<(unsigned)(((size_t)2 * M_ROWS * 96 + 255) / 256), 256>>>();

    // 6) dt_proj (both dirs)
    k_gemm_z<<<dim3(16, 64, 2), 256, GEMM_SMEM>>>(
        dtrhi, dtrlo, (size_t)M_ROWS * DR, dtwhi, dtwlo, (size_t)DI * DR,
        dtv, (size_t)M_ROWS * DI, 0, DR, DR, 1, DI, DI);

    // 7) chunked selective scan: pass1 (chunks 0..14) -> combine -> pass2 (all 16)
    k_scan1<<<dim3(DI / 128, BSZ * SCM, 2), 128>>>(dt_bv, A_log);
    k_scomb<<<(2u * 4 * 16 * 2048 + 255) / 256, 256>>>();
    k_scan2<<<dim3(DI / 128, BSZ * SCH, 2), 128>>>(dt_bv, A_log, Dp);

    // 8) out_proj (both dirs, K-concatenated single pass)
    k_gemm_cat<<<dim3(8, 64, 1), 256, GEMM_SMEM>>>(
        yhi, ylo, yhi + (size_t)M_ROWS * DI, ylo + (size_t)M_ROWS * DI,
        owhi, owlo, owhi + (size_t)DM * DI, owlo + (size_t)DM * DI,
        out, DI, DM, DM);
}

// round 17
// speedup vs baseline: 2.8858x; 1.0476x over previous
#include <cuda_runtime.h>
#include <cuda_bf16.h>
#include <cstdint>
#include <math.h>

// Problem dims
#define L_SEQ 2048
#define BSZ   4
#define DM    1024
#define DI    2048
#define DS    16
#define DR    64
#define M_ROWS 8192   // BSZ * L_SEQ

// Scan chunking
#define SCH   16                // chunks
#define SCL   (L_SEQ / SCH)     // 128 steps per chunk
#define SCM   (SCH - 1)         // stored chunk states (0..14)

// ============================================================================
// Scratch (static device arrays)
// ============================================================================
__device__ float g_xz  [(size_t)M_ROWS * 8192];             // in_proj output (xi|z per dir)
__device__ float g_proj[2 * (size_t)M_ROWS * 96];           // x_proj output (dt_raw|B|C)
__device__ float g_proj_part[4 * (size_t)M_ROWS * 96];      // x_proj split-K partials [dir][ks]
__device__ float g_dt  [2 * (size_t)M_ROWS * DI];           // dt_proj output (POST-softplus)

// chunked-scan state buffers (chunks 0..SCM-1): [dir][b][c][s][e]
__device__ float g_hP [2 * 4 * SCM * 16 * 2048];
__device__ float g_hL [2 * 4 * SCM * 16 * 2048];
__device__ float g_hin[2 * 4 * SCM * 16 * 2048];            // h_in for chunks 1..SCH-1

// bf16 hi/lo operand planes
__device__ __nv_bfloat16 g_x_hi  [(size_t)M_ROWS * DM],  g_x_lo  [(size_t)M_ROWS * DM];
__device__ __nv_bfloat16 g_inw_hi[(size_t)8192 * DM],    g_inw_lo[(size_t)8192 * DM];
__device__ __nv_bfloat16 g_xw_hi [2 * 96 * (size_t)DI],  g_xw_lo [2 * 96 * (size_t)DI];
__device__ __nv_bfloat16 g_dtw_hi[2 * (size_t)DI * DR],  g_dtw_lo[2 * (size_t)DI * DR];
__device__ __nv_bfloat16 g_ow_hi [2 * (size_t)DM * DI],  g_ow_lo [2 * (size_t)DM * DI];
__device__ __nv_bfloat16 g_xc_hi [2 * (size_t)M_ROWS * DI], g_xc_lo[2 * (size_t)M_ROWS * DI];
__device__ __nv_bfloat16 g_dtr_hi[2 * (size_t)M_ROWS * DR], g_dtr_lo[2 * (size_t)M_ROWS * DR];
__device__ __nv_bfloat16 g_y_hi  [2 * (size_t)M_ROWS * DI], g_y_lo [2 * (size_t)M_ROWS * DI];

__device__ __forceinline__ void split2(float v, __nv_bfloat16& h, __nv_bfloat16& l) {
    h = __float2bfloat16_rn(v);
    l = __float2bfloat16_rn(v - __bfloat162float(h));
}

// ============================================================================
// PTX helpers (sm_80-class only: valid on base sm_103 target)
// ============================================================================
__device__ __forceinline__ uint32_t smem_u32(const void* p) {
    uint32_t a;
    asm("{ .reg .u64 t; cvta.to.shared.u64 t, %1; cvt.u32.u64 %0, t; }" : "=r"(a) : "l"(p));
    return a;
}
__device__ __forceinline__ void cpa16(uint32_t dst, const void* src) {
    asm volatile("cp.async.cg.shared.global [%0], [%1], 16;" :: "r"(dst), "l"(src) : "memory");
}
__device__ __forceinline__ void cpa16p(uint32_t dst, const void* src, int sz) {
    asm volatile("cp.async.cg.shared.global [%0], [%1], 16, %2;" :: "r"(dst), "l"(src), "r"(sz) : "memory");
}
__device__ __forceinline__ void cp_commit() {
    asm volatile("cp.async.commit_group;" ::: "memory");
}
template <int N>
__device__ __forceinline__ void cp_wait() {
    asm volatile("cp.async.wait_group %0;" :: "n"(N) : "memory");
}
__device__ __forceinline__ void ldsm_x4(uint32_t* r, uint32_t addr) {
    asm volatile("ldmatrix.sync.aligned.m8n8.x4.shared.b16 {%0,%1,%2,%3}, [%4];"
                 : "=r"(r[0]), "=r"(r[1]), "=r"(r[2]), "=r"(r[3]) : "r"(addr));
}
__device__ __forceinline__ void ldsm_x2(uint32_t* r, uint32_t addr) {
    asm volatile("ldmatrix.sync.aligned.m8n8.x2.shared.b16 {%0,%1}, [%2];"
                 : "=r"(r[0]), "=r"(r[1]) : "r"(addr));
}
__device__ __forceinline__ void mma_bf16(float* d, const uint32_t* a, const uint32_t* b) {
    asm volatile("mma.sync.aligned.m16n8k16.row.col.f32.bf16.bf16.f32 "
                 "{%0,%1,%2,%3}, {%4,%5,%6,%7}, {%8,%9}, {%0,%1,%2,%3};"
                 : "+f"(d[0]), "+f"(d[1]), "+f"(d[2]), "+f"(d[3])
                 : "r"(a[0]), "r"(a[1]), "r"(a[2]), "r"(a[3]), "r"(b[0]), "r"(b[1]));
}

// ============================================================================
// GEMM machinery (R11 WINNER config) — FROZEN mainloop
// ============================================================================
#define PLANE 8192
#define OFF_AH 0
#define OFF_AL (PLANE)
#define OFF_BH (2 * PLANE)
#define OFF_BL (3 * PLANE)
#define STAGE  (4 * PLANE)
#define NSTAGE 3
#define GEMM_SMEM (NSTAGE * STAGE)
#define SW64(o) ((o) ^ (((o) >> 3) & 0x30))

struct GemmCtx {
    uint32_t sb;
    int tid, lane, warp, wm, wn, bm, bn;
    uint32_t a_lane_off, b_lane_off;
};

__device__ __forceinline__ void gemm_init(GemmCtx& g, char* smem) {
    g.sb = smem_u32(smem);
    g.tid = threadIdx.x;
    g.lane = g.tid & 31;
    g.warp = g.tid >> 5;
    g.wm = g.warp >> 2;
    g.wn = g.warp & 3;
    g.bm = blockIdx.y * 128;
    g.bn = blockIdx.x * 128;
    g.a_lane_off = (uint32_t)((g.lane & 15) * 64 + (g.lane >> 4) * 16);
    g.b_lane_off = (uint32_t)((g.lane & 7) * 64 + ((g.lane >> 3) & 1) * 16);
}

__device__ __forceinline__ void gemm_load_chunk(
    const GemmCtx& g, int s, int k0, int K,
    const __nv_bfloat16* __restrict__ Ahi, const __nv_bfloat16* __restrict__ Alo,
    const __nv_bfloat16* __restrict__ Bhi, const __nv_bfloat16* __restrict__ Blo,
    int Nact)
{
    const uint32_t st = g.sb + s * STAGE;
#pragma unroll
    for (int it = 0; it < 2; ++it) {
        const int i   = g.tid + it * 256;
        const int row = i >> 2;
        const int c8  = (i & 3) * 8;
        const uint32_t so = SW64((uint32_t)(row * 64 + c8 * 2));
        const size_t ga = (size_t)(g.bm + row) * K + k0 + c8;
        cpa16(st + OFF_AH + so, Ahi + ga);
        cpa16(st + OFF_AL + so, Alo + ga);
        const size_t gb = (size_t)(g.bn + row) * K + k0 + c8;
        const int sz = (g.bn + row < Nact) ? 16 : 0;
        cpa16p(st + OFF_BH + so, Bhi + gb, sz);
        cpa16p(st + OFF_BL + so, Blo + gb, sz);
    }
}

__device__ __forceinline__ void gemm_compute_chunk(const GemmCtx& g, int s, float acc[4][4][4]) {
    const uint32_t st = g.sb + s * STAGE;
#pragma unroll
    for (int k16 = 0; k16 < 32; k16 += 16) {
        const uint32_t ak = g.a_lane_off + k16 * 2;
        const uint32_t bk = g.b_lane_off + k16 * 2;
        uint32_t bh[4][2], bl[4][2];
#pragma unroll
        for (int j = 0; j < 4; ++j) {
            const uint32_t bo = (uint32_t)((g.wn * 32 + j * 8) * 64) + bk;
            const uint32_t bos = SW64(bo);
            ldsm_x2(bh[j], st + OFF_BH + bos);
            ldsm_x2(bl[j], st + OFF_BL + bos);
        }
#pragma unroll
        for (int i = 0; i < 4; ++i) {
            const uint32_t ao = (uint32_t)((g.wm * 64 + i * 16) * 64) + ak;
            const uint32_t aos = SW64(ao);
            uint32_t ah[4], al[4];
            ldsm_x4(ah, st + OFF_AH + aos);
            ldsm_x4(al, st + OFF_AL + aos);
#pragma unroll
            for (int j = 0; j < 4; ++j) mma_bf16(acc[i][j], ah, bh[j]);
#pragma unroll
            for (int j = 0; j < 4; ++j) mma_bf16(acc[i][j], ah, bl[j]);
#pragma unroll
            for (int j = 0; j < 4; ++j) mma_bf16(acc[i][j], al, bh[j]);
        }
    }
}

__device__ __forceinline__ float softplus_f(float v) {
    return (v > 15.f) ? v : log1pf(__expf(v));
}

// spBias != nullptr => epilogue computes softplus(acc + spBias[dir*DI + col])
__global__ void __launch_bounds__(256, 2) k_gemm_z(
    const __nv_bfloat16* __restrict__ Ahi, const __nv_bfloat16* __restrict__ Alo, size_t aStride,
    const __nv_bfloat16* __restrict__ Bhi, const __nv_bfloat16* __restrict__ Blo, size_t bStride,
    float* __restrict__ C, size_t cStride, size_t partStride,
    int K_ld, int kLen, int nsplit, int Nact, int ldc,
    const float* __restrict__ spBias)
{
    extern __shared__ __align__(1024) char smem[];
    GemmCtx g;
    gemm_init(g, smem);
    const int dir = blockIdx.z / nsplit;
    const int ks  = blockIdx.z % nsplit;
    const int kStart = ks * kLen;
    Ahi += (size_t)dir * aStride; Alo += (size_t)dir * aStride;
    Bhi += (size_t)dir * bStride; Blo += (size_t)dir * bStride;
    C   += (size_t)dir * cStride + (size_t)ks * partStride;
    const int nch = kLen >> 5;

    float acc[4][4][4];
#pragma unroll
    for (int i = 0; i < 4; i++)
#pragma unroll
        for (int j = 0; j < 4; j++)
#pragma unroll
            for (int k = 0; k < 4; k++) acc[i][j][k] = 0.f;

    gemm_load_chunk(g, 0, kStart, K_ld, Ahi, Alo, Bhi, Blo, Nact);
    cp_commit();
    if (1 < nch) gemm_load_chunk(g, 1, kStart + 32, K_ld, Ahi, Alo, Bhi, Blo, Nact);
    cp_commit();

    for (int c = 0; c < nch; ++c) {
        cp_wait<1>();
        __syncthreads();
        if (c + 2 < nch)
            gemm_load_chunk(g, (c + 2) % NSTAGE, kStart + ((c + 2) << 5), K_ld, Ahi, Alo, Bhi, Blo, Nact);
        cp_commit();
        gemm_compute_chunk(g, c % NSTAGE, acc);
    }

    const int gid = g.lane >> 2;
    const int tig = g.lane & 3;
#pragma unroll
    for (int i = 0; i < 4; ++i) {
        const int row = g.bm + g.wm * 64 + i * 16 + gid;
#pragma unroll
        for (int j = 0; j < 4; ++j) {
            const int col = g.bn + g.wn * 32 + j * 8 + tig * 2;
            if (col < Nact) {
                float v0 = acc[i][j][0], v1 = acc[i][j][1];
                float v2 = acc[i][j][2], v3 = acc[i][j][3];
                if (spBias) {
                    const float b0 = spBias[dir * DI + col];
                    const float b1 = spBias[dir * DI + col + 1];
                    v0 = softplus_f(v0 + b0); v1 = softplus_f(v1 + b1);
                    v2 = softplus_f(v2 + b0); v3 = softplus_f(v3 + b1);
                }
                *(float2*)&C[(size_t)row * ldc + col]       = make_float2(v0, v1);
                *(float2*)&C[(size_t)(row + 8) * ldc + col] = make_float2(v2, v3);
            }
        }
    }
}

__global__ void __launch_bounds__(256, 2) k_gemm_cat(
    const __nv_bfloat16* __restrict__ A0hi, const __nv_bfloat16* __restrict__ A0lo,
    const __nv_bfloat16* __restrict__ A1hi, const __nv_bfloat16* __restrict__ A1lo,
    const __nv_bfloat16* __restrict__ B0hi, const __nv_bfloat16* __restrict__ B0lo,
    const __nv_bfloat16* __restrict__ B1hi, const __nv_bfloat16* __restrict__ B1lo,
    float* __restrict__ C, int Kh, int Nact, int ldc)
{
    extern __shared__ __align__(1024) char smem[];
    GemmCtx g;
    gemm_init(g, smem);
    const int nch_h = Kh >> 5;
    const int nch = nch_h * 2;

    float acc[4][4][4];
#pragma unroll
    for (int i = 0; i < 4; i++)
#pragma unroll
        for (int j = 0; j < 4; j++)
#pragma unroll
            for (int k = 0; k < 4; k++) acc[i][j][k] = 0.f;

    auto load = [&](int c, int s) {
        if (c < nch_h)
            gemm_load_chunk(g, s, c << 5, Kh, A0hi, A0lo, B0hi, B0lo, Nact);
        else
            gemm_load_chunk(g, s, (c - nch_h) << 5, Kh, A1hi, A1lo, B1hi, B1lo, Nact);
    };

    load(0, 0);
    cp_commit();
    if (1 < nch) load(1, 1);
    cp_commit();

    for (int c = 0; c < nch; ++c) {
        cp_wait<1>();
        __syncthreads();
        if (c + 2 < nch) load(c + 2, (c + 2) % NSTAGE);
        cp_commit();
        gemm_compute_chunk(g, c % NSTAGE, acc);
    }

    const int gid = g.lane >> 2;
    const int tig = g.lane & 3;
#pragma unroll
    for (int i = 0; i < 4; ++i) {
        const int row = g.bm + g.wm * 64 + i * 16 + gid;
#pragma unroll
        for (int j = 0; j < 4; ++j) {
            const int col = g.bn + g.wn * 32 + j * 8 + tig * 2;
            if (col < Nact) {
                *(float2*)&C[(size_t)row * ldc + col]       = make_float2(acc[i][j][0], acc[i][j][1]);
                *(float2*)&C[(size_t)(row + 8) * ldc + col] = make_float2(acc[i][j][2], acc[i][j][3]);
            }
        }
    }
}

// ============================================================================
// k_reduce_proj2: g_proj = sum of 2 split-K partials; cols<64 also -> dtr hi/lo
// ============================================================================
__global__ void k_reduce_proj2() {
    size_t idx = (size_t)blockIdx.x * blockDim.x + threadIdx.x;
    const size_t total = (size_t)2 * M_ROWS * 96;
    if (idx >= total) return;
    const int dir = (int)(idx / ((size_t)M_ROWS * 96));
    const size_t off = idx % ((size_t)M_ROWS * 96);
    const float* base = g_proj_part + (size_t)dir * 2 * M_ROWS * 96;
    float v = base[off] + base[off + (size_t)M_ROWS * 96];
    g_proj[idx] = v;
    const int col = (int)(off % 96);
    if (col < DR) {
        const size_t row = off / 96;
        __nv_bfloat16 h, l;
        split2(v, h, l);
        const size_t d = ((size_t)dir * M_ROWS + row) * DR + col;
        g_dtr_hi[d] = h;
        g_dtr_lo[d] = l;
    }
}

// ============================================================================
// fp32 -> bf16 hi/lo conversions (two launches)
// ============================================================================
#define N4_X   2097152u
#define N4_INW 2097152u
#define N4_A   (N4_X + N4_INW)
#define N4_XW  98304u
#define N4_DTW 65536u
#define N4_OW  1048576u
#define N4_B   (N4_XW + N4_DTW + N4_OW)

__global__ void k_cvt_a(const float4* __restrict__ x, const float4* __restrict__ inw) {
    uint32_t i = blockIdx.x * blockDim.x + threadIdx.x;
    if (i >= N4_A) return;
    const float4* src;
    __nv_bfloat16 *hi, *lo;
    uint32_t off = i;
    if (i < N4_X) { src = x;   hi = g_x_hi;   lo = g_x_lo; }
    else { off -= N4_X; src = inw; hi = g_inw_hi; lo = g_inw_lo; }
    float4 v = src[off];
    __nv_bfloat16 h0, h1, h2, h3, l0, l1, l2, l3;
    split2(v.x, h0, l0); split2(v.y, h1, l1); split2(v.z, h2, l2); split2(v.w, h3, l3);
    __nv_bfloat162* H = (__nv_bfloat162*)hi;
    __nv_bfloat162* L = (__nv_bfloat162*)lo;
    H[2 * (size_t)off]     = __nv_bfloat162(h0, h1);
    H[2 * (size_t)off + 1] = __nv_bfloat162(h2, h3);
    L[2 * (size_t)off]     = __nv_bfloat162(l0, l1);
    L[2 * (size_t)off + 1] = __nv_bfloat162(l2, l3);
}

__global__ void k_cvt_b(const float4* __restrict__ xw, const float4* __restrict__ dtw,
                        const float4* __restrict__ ow) {
    uint32_t i = blockIdx.x * blockDim.x + threadIdx.x;
    if (i >= N4_B) return;
    const float4* src;
    __nv_bfloat16 *hi, *lo;
    uint32_t off = i;
    if (i < N4_XW)                      { src = xw;  hi = g_xw_hi;  lo = g_xw_lo; }
    else if ((off -= N4_XW) < N4_DTW)   { src = dtw; hi = g_dtw_hi; lo = g_dtw_lo; }
    else { off -= N4_DTW;                 src = ow;  hi = g_ow_hi;  lo = g_ow_lo; }
    float4 v = src[off];
    __nv_bfloat16 h0, h1, h2, h3, l0, l1, l2, l3;
    split2(v.x, h0, l0); split2(v.y, h1, l1); split2(v.z, h2, l2); split2(v.w, h3, l3);
    __nv_bfloat162* H = (__nv_bfloat162*)hi;
    __nv_bfloat162* L = (__nv_bfloat162*)lo;
    H[2 * (size_t)off]     = __nv_bfloat162(h0, h1);
    H[2 * (size_t)off + 1] = __nv_bfloat162(h2, h3);
    L[2 * (size_t)off]     = __nv_bfloat162(l0, l1);
    L[2 * (size_t)off + 1] = __nv_bfloat162(l2, l3);
}

// ============================================================================
// Depthwise conv + SiLU v3 (R14 winner) — FROZEN
// ============================================================================
#define CONV_THREADS ((size_t)2 * BSZ * (L_SEQ / 4) * (DI / 4))

__global__ void __launch_bounds__(256) k_conv(const float* __restrict__ cw,
                                              const float* __restrict__ cb) {
    const size_t idx = (size_t)blockIdx.x * 256 + threadIdx.x;
    if (idx >= CONV_THREADS) return;
    const int eg  = (int)(idx & (DI / 4 - 1));
    size_t r      = idx >> 9;
    const int lb  = (int)(r & (L_SEQ / 4 - 1));
    r >>= 9;
    const int b   = (int)(r & 3);
    const int dir = (int)(r >> 2);
    const int e   = eg * 4;
    const int l0  = lb * 4;

    const float4* wv = (const float4*)(cw + ((size_t)dir * DI + e) * 4);
    float4 wc[4];
#pragma unroll
    for (int c = 0; c < 4; c++) wc[c] = wv[c];
    float w[4][4];
#pragma unroll
    for (int c = 0; c < 4; c++) {
        const float t0 = wc[c].x, t1 = wc[c].y, t2 = wc[c].z, t3 = wc[c].w;
        if (dir == 0) { w[0][c] = t0; w[1][c] = t1; w[2][c] = t2; w[3][c] = t3; }
        else          { w[0][c] = t3; w[1][c] = t2; w[2][c] = t1; w[3][c] = t0; }
    }
    const float4 bias = *(const float4*)(cb + dir * DI + e);

    const int base = (dir == 0) ? (l0 - 3) : l0;
    const size_t xibase = (size_t)(b * L_SEQ) * 8192 + (size_t)dir * 4096 + e;
    float4 row[7];
#pragma unroll
    for (int i = 0; i < 7; i++) {
        const int tl = base + i;
        row[i] = (tl >= 0 && tl < L_SEQ) ? *(const float4*)(g_xz + xibase + (size_t)tl * 8192)
                                         : make_float4(0.f, 0.f, 0.f, 0.f);
    }

    const size_t obase = ((size_t)dir * M_ROWS + (size_t)b * L_SEQ + l0) * DI + e;
#pragma unroll
    for (int u = 0; u < 4; u++) {
        float4 acc = bias;
#pragma unroll
        for (int j = 0; j < 4; j++) {
            const float4 xi = row[u + j];
            acc.x = fmaf(w[j][0], xi.x, acc.x);
            acc.y = fmaf(w[j][1], xi.y, acc.y);
            acc.z = fmaf(w[j][2], xi.z, acc.z);
            acc.w = fmaf(w[j][3], xi.w, acc.w);
        }
        const float xc0 = acc.x / (1.f + __expf(-acc.x));
        const float xc1 = acc.y / (1.f + __expf(-acc.y));
        const float xc2 = acc.z / (1.f + __expf(-acc.z));
        const float xc3 = acc.w / (1.f + __expf(-acc.w));
        __nv_bfloat16 h0, h1, h2, h3, lo0, lo1, lo2, lo3;
        split2(xc0, h0, lo0); split2(xc1, h1, lo1);
        split2(xc2, h2, lo2); split2(xc3, h3, lo3);
        const size_t o = obase + (size_t)u * DI;
        __nv_bfloat162 hp0(h0, h1), hp1(h2, h3), lp0(lo0, lo1), lp1(lo2, lo3);
        *(uint2*)(g_xc_hi + o) = make_uint2(*(uint32_t*)&hp0, *(uint32_t*)&hp1);
        *(uint2*)(g_xc_lo + o) = make_uint2(*(uint32_t*)&lp0, *(uint32_t*)&lp1);
    }
}

// ============================================================================
// Chunked selective scan (SCH=16, SCL=128). g_dt now holds POST-softplus dt.
// Pass 1 (chunks 0..14): sdt = sum dt; P[s] = exp(a[s]*sdt) (log-sum trick);
//                        hl[s] = local scan (h_in = 0).
// Combine: h_in[c+1] = P[c]*h_in[c] + hl[c],  h_in[0] = 0.
// Pass 2 (all 16 chunks): full scan seeded with h_in; identical fma chain.
// ============================================================================
__global__ void __launch_bounds__(128) k_scan1(const float* __restrict__ A_log) {
    const int tid  = threadIdx.x;
    const int lane = tid & 31;
    const int warp = tid >> 5;
    const int dir  = blockIdx.z;
    const int b    = blockIdx.y / SCM;
    const int c    = blockIdx.y % SCM;
    const int e    = blockIdx.x * 128 + tid;
    const int tau0 = c * SCL;

    __shared__ float sB[4][16];

    float a[16];
#pragma unroll
    for (int s = 0; s < 16; s++)
        a[s] = -__expf(A_log[((size_t)dir * DI + e) * 16 + s]);

    float sdt = 0.f;
    float hl[16];
#pragma unroll
    for (int s = 0; s < 16; s++) hl[s] = 0.f;

    const size_t base_de   = (size_t)dir * M_ROWS * DI;
    const size_t proj_base = (size_t)dir * M_ROWS * 96;
    const size_t brow      = (size_t)b * L_SEQ;

    float rbc[4], rdt[4], rxh[4], rxl[4];
#pragma unroll
    for (int p = 0; p < 4; p++) {
        const int tau = tau0 + p;
        const int tt = dir ? (L_SEQ - 1 - tau) : tau;
        const size_t m = brow + tt;
        rbc[p] = g_proj[proj_base + m * 96 + 64 + lane];
        rdt[p] = g_dt[base_de + m * DI + e];
        rxh[p] = __bfloat162float(g_xc_hi[base_de + m * DI + e]);
        rxl[p] = __bfloat162float(g_xc_lo[base_de + m * DI + e]);
    }

    for (int t0 = tau0; t0 < tau0 + SCL; t0 += 4) {
#pragma unroll
        for (int u = 0; u < 4; u++) {
            const int tau = t0 + u;
            const float bc = rbc[u], dt = rdt[u], xh = rxh[u], xl = rxl[u];

            const int tp = tau + 4;
            if (tp < tau0 + SCL) {
                const int tq = dir ? (L_SEQ - 1 - tp) : tp;
                const size_t mp = brow + tq;
                rbc[u] = g_proj[proj_base + mp * 96 + 64 + lane];
                rdt[u] = g_dt[base_de + mp * DI + e];
                rxh[u] = __bfloat162float(g_xc_hi[base_de + mp * DI + e]);
                rxl[u] = __bfloat162float(g_xc_lo[base_de + mp * DI + e]);
            }

            if (lane < 16) sB[warp][lane] = bc;
            __syncwarp();

            const float x   = xh + xl;
            const float dtx = dt * x;
            sdt += dt;

#pragma unroll
            for (int s = 0; s < 16; s++) {
                float dA = __expf(dt * a[s]);
                hl[s] = fmaf(hl[s], dA, dtx * sB[warp][s]);
            }
            __syncwarp();
        }
    }

    const size_t obase = ((((size_t)dir * 4 + b) * SCM + c) * 16) * 2048 + e;
#pragma unroll
    for (int s = 0; s < 16; s++) {
        g_hP[obase + (size_t)s * 2048] = __expf(a[s] * sdt);   // prod dA = exp(a*sum dt)
        g_hL[obase + (size_t)s * 2048] = hl[s];
    }
}

__global__ void k_scomb() {
    const uint32_t idx = blockIdx.x * blockDim.x + threadIdx.x;
    if (idx >= 2u * 4 * 16 * 2048) return;
    const int e = idx & 2047;
    const int s = (idx >> 11) & 15;
    const int b = (idx >> 15) & 3;
    const int dir = idx >> 17;
    float h = 0.f;
#pragma unroll
    for (int c = 0; c < SCM; c++) {
        const size_t base = ((((size_t)dir * 4 + b) * SCM + c) * 16 + s) * 2048 + e;
        h = fmaf(g_hP[base], h, g_hL[base]);
        g_hin[base] = h;             // h_in for chunk c+1
    }
}

__global__ void __launch_bounds__(128) k_scan2(const float* __restrict__ A_log,
                                               const float* __restrict__ Dp) {
    const int tid  = threadIdx.x;
    const int lane = tid & 31;
    const int warp = tid >> 5;
    const int dir  = blockIdx.z;
    const int b    = blockIdx.y >> 4;
    const int c    = blockIdx.y & 15;
    const int e    = blockIdx.x * 128 + tid;
    const int tau0 = c * SCL;

    __shared__ float sB[4][16], sC[4][16];

    float a[16];
#pragma unroll
    for (int s = 0; s < 16; s++)
        a[s] = -__expf(A_log[((size_t)dir * DI + e) * 16 + s]);

    const float dcoef = Dp[dir * DI + e];

    float h[16];
    if (c == 0) {
#pragma unroll
        for (int s = 0; s < 16; s++) h[s] = 0.f;
    } else {
        const size_t ibase = ((((size_t)dir * 4 + b) * SCM + (c - 1)) * 16) * 2048 + e;
#pragma unroll
        for (int s = 0; s < 16; s++) h[s] = g_hin[ibase + (size_t)s * 2048];
    }

    const size_t base_de   = (size_t)dir * M_ROWS * DI;
    const size_t proj_base = (size_t)dir * M_ROWS * 96;
    const size_t brow      = (size_t)b * L_SEQ;

    float rbc[4], rdt[4], rxh[4], rxl[4], rz[4];
#pragma unroll
    for (int p = 0; p < 4; p++) {
        const int tau = tau0 + p;
        const int tt = dir ? (L_SEQ - 1 - tau) : tau;
        const size_t m = brow + tt;
        rbc[p] = g_proj[proj_base + m * 96 + 64 + lane];
        rdt[p] = g_dt[base_de + m * DI + e];
        rxh[p] = __bfloat162float(g_xc_hi[base_de + m * DI + e]);
        rxl[p] = __bfloat162float(g_xc_lo[base_de + m * DI + e]);
        rz[p]  = g_xz[m * 8192 + dir * 4096 + 2048 + e];
    }

    for (int t0 = tau0; t0 < tau0 + SCL; t0 += 4) {
#pragma unroll
        for (int u = 0; u < 4; u++) {
            const int tau = t0 + u;
            const int tt = dir ? (L_SEQ - 1 - tau) : tau;
            const size_t m = brow + tt;

            const float bc = rbc[u], dt = rdt[u], xh = rxh[u], xl = rxl[u], zz = rz[u];

            const int tp = tau + 4;
            if (tp < tau0 + SCL) {
                const int tq = dir ? (L_SEQ - 1 - tp) : tp;
                const size_t mp = brow + tq;
                rbc[u] = g_proj[proj_base + mp * 96 + 64 + lane];
                rdt[u] = g_dt[base_de + mp * DI + e];
                rxh[u] = __bfloat162float(g_xc_hi[base_de + mp * DI + e]);
                rxl[u] = __bfloat162float(g_xc_lo[base_de + mp * DI + e]);
                rz[u]  = g_xz[mp * 8192 + dir * 4096 + 2048 + e];
            }

            if (lane < 16) sB[warp][lane] = bc; else sC[warp][lane - 16] = bc;
            __syncwarp();

            const float x   = xh + xl;
            const float dtx = dt * x;

            float y = 0.f;
#pragma unroll
            for (int s = 0; s < 16; s++) {
                float dA = __expf(dt * a[s]);
                h[s] = fmaf(h[s], dA, dtx * sB[warp][s]);
                y    = fmaf(h[s], sC[warp][s], y);
            }
            const float yv  = fmaf(x, dcoef, y);
            const float sz  = zz / (1.f + __expf(-zz));
            const float out = yv * sz;
            __nv_bfloat16 hh, ll;
            split2(out, hh, ll);
            const size_t o = base_de + m * DI + e;
            g_y_hi[o] = hh;
            g_y_lo[o] = ll;
            __syncwarp();
        }
    }
}

// ============================================================================
extern "C" void kernel_launch(void* const* d_in, const int* in_sizes, int n_in,
                              void* d_out, int out_size) {
    const float* x      = (const float*)d_in[0];
    const float* in_w   = (const float*)d_in[1];
    const float* conv_w = (const float*)d_in[2];
    const float* conv_b = (const float*)d_in[3];
    const float* x_w    = (const float*)d_in[4];
    const float* dt_w   = (const float*)d_in[5];
    const float* dt_bv  = (const float*)d_in[6];
    const float* A_log  = (const float*)d_in[7];
    const float* Dp     = (const float*)d_in[8];
    const float* out_w  = (const float*)d_in[9];
    float* out = (float*)d_out;

    cudaFuncSetAttribute(k_gemm_z,   cudaFuncAttributeMaxDynamicSharedMemorySize, GEMM_SMEM);
    cudaFuncSetAttribute(k_gemm_cat, cudaFuncAttributeMaxDynamicSharedMemorySize, GEMM_SMEM);

    float *xz, *projpart, *dtv;
    __nv_bfloat16 *xhi, *xlo, *inwhi, *inwlo, *xwhi, *xwlo, *dtwhi, *dtwlo, *owhi, *owlo;
    __nv_bfloat16 *xchi, *xclo, *dtrhi, *dtrlo, *yhi, *ylo;
    cudaGetSymbolAddress((void**)&xz, g_xz);
    cudaGetSymbolAddress((void**)&projpart, g_proj_part);
    cudaGetSymbolAddress((void**)&dtv, g_dt);
    cudaGetSymbolAddress((void**)&xhi, g_x_hi);     cudaGetSymbolAddress((void**)&xlo, g_x_lo);
    cudaGetSymbolAddress((void**)&inwhi, g_inw_hi); cudaGetSymbolAddress((void**)&inwlo, g_inw_lo);
    cudaGetSymbolAddress((void**)&xwhi, g_xw_hi);   cudaGetSymbolAddress((void**)&xwlo, g_xw_lo);
    cudaGetSymbolAddress((void**)&dtwhi, g_dtw_hi); cudaGetSymbolAddress((void**)&dtwlo, g_dtw_lo);
    cudaGetSymbolAddress((void**)&owhi, g_ow_hi);   cudaGetSymbolAddress((void**)&owlo, g_ow_lo);
    cudaGetSymbolAddress((void**)&xchi, g_xc_hi);   cudaGetSymbolAddress((void**)&xclo, g_xc_lo);
    cudaGetSymbolAddress((void**)&dtrhi, g_dtr_hi); cudaGetSymbolAddress((void**)&dtrlo, g_dtr_lo);
    cudaGetSymbolAddress((void**)&yhi, g_y_hi);     cudaGetSymbolAddress((void**)&ylo, g_y_lo);

    // 0-1) conversions
    k_cvt_a<<<(N4_A + 255) / 256, 256>>>((const float4*)x, (const float4*)in_w);
    k_cvt_b<<<(N4_B + 255) / 256, 256>>>((const float4*)x_w, (const float4*)dt_w,
                                         (const float4*)out_w);

    // 2) in_proj: xz = x @ in_w^T  (M=8192, N=8192, K=1024)
    k_gemm_z<<<dim3(64, 64, 1), 256, GEMM_SMEM>>>(
        xhi, xlo, 0, inwhi, inwlo, 0,
        xz, 0, 0, DM, DM, 1, 8192, 8192, nullptr);

    // 3) depthwise conv + silu -> xc hi/lo
    k_conv<<<(unsigned)((CONV_THREADS + 255) / 256), 256>>>(conv_w, conv_b);

    // 4) x_proj (both dirs, split-K x2)
    k_gemm_z<<<dim3(1, 64, 4), 256, GEMM_SMEM>>>(
        xchi, xclo, (size_t)M_ROWS * DI, xwhi, xwlo, (size_t)96 * DI,
        projpart, (size_t)2 * M_ROWS * 96, (size_t)M_ROWS * 96,
        DI, DI / 2, 2, 96, 96, nullptr);

    // 5) reduce partials -> g_proj + dtr hi/lo
    k_reduce_proj2<<<(unsigned)(((size_t)2 * M_ROWS * 96 + 255) / 256), 256>>>();

    // 6) dt_proj (both dirs) with fused bias+softplus epilogue -> g_dt (final dt)
    k_gemm_z<<<dim3(16, 64, 2), 256, GEMM_SMEM>>>(
        dtrhi, dtrlo, (size_t)M_ROWS * DR, dtwhi, dtwlo, (size_t)DI * DR,
        dtv, (size_t)M_ROWS * DI, 0, DR, DR, 1, DI, DI, dt_bv);

    // 7) chunked selective scan: pass1 (chunks 0..14) -> combine -> pass2 (all 16)
    k_scan1<<<dim3(DI / 128, BSZ * SCM, 2), 128>>>(A_log);
    k_scomb<<<(2u * 4 * 16 * 2048 + 255) / 256, 256>>>();
    k_scan2<<<dim3(DI / 128, BSZ * SCH, 2), 128>>>(A_log, Dp);

    // 8) out_proj (both dirs, K-concatenated single pass)
    k_gemm_cat<<<dim3(8, 64, 1), 256, GEMM_SMEM>>>(
        yhi, ylo, yhi + (size_t)M_ROWS * DI, ylo + (size_t)M_ROWS * DI,
        owhi, owlo, owhi + (size_t)DM * DI, owlo + (size_t)DM * DI,
        out, DI, DM, DM);
}